// round 1
// baseline (speedup 1.0000x reference)
#include <cuda_runtime.h>

// Problem constants (fixed by the dataset)
#define CC     16          // channels
#define PP     8           // patches per side
#define NN     64          // patches
#define DQK    32          // q/k dim
#define HIDN   64          // edge-MLP hidden
#define MAXE   512         // max edges (actual 224)
#define BMAX   16
#define PLANE  16384       // 128*128

// ---------------- scratch (__device__ globals: sanctioned scratch) ----------
__device__ float g_Xa [BMAX*CC*PLANE];
__device__ float g_Xb [BMAX*CC*PLANE];
__device__ float g_M  [BMAX*CC*PLANE];
__device__ float g_Ag [BMAX*CC*PLANE];
__device__ float g_Z  [BMAX*CC*PLANE];
__device__ float g_RH [BMAX*CC*PLANE];
__device__ float g_q  [BMAX*NN*DQK];
__device__ float g_k  [BMAX*NN*DQK];
__device__ float g_ev [BMAX*MAXE];
__device__ float g_T9 [CC*9];
__device__ float g_gt [BMAX*MAXE*CC*9];
__device__ int   g_off[NN+1];
__device__ int   g_le [MAXE];
__device__ int   g_lj [MAXE];

__device__ __forceinline__ float sigf(float x){ return 1.f/(1.f+__expf(-x)); }

// ---------------- shared helpers for per-patch 3x3 SAME conv ----------------
// smem input tile: [CIN][18][18] (halo of zeros), weights padded to 12 f/taps.
template<int CIN>
__device__ __forceinline__ void load_tile(float* s_in,
                                          const float* __restrict__ in0,
                                          const float* __restrict__ in1,
                                          int b, int p16, int q16)
{
    for (int i = threadIdx.x; i < CIN*324; i += 256) {
        int cin = i / 324; int r = i - cin*324;
        int yy = r / 18, xx = r - yy*18;
        int ly = yy - 1, lx = xx - 1;
        float v = 0.f;
        if ((unsigned)ly < 16u && (unsigned)lx < 16u) {
            const float* src = (CIN == 16 || cin < 16) ? in0 : in1;
            int c = (CIN == 16 || cin < 16) ? cin : (cin - 16);
            v = src[((b*CC + c)*128 + p16 + ly)*128 + (q16 + lx)];
        }
        s_in[i] = v;
    }
}

template<int CIN,int COUT>
__device__ __forceinline__ void load_w(float* s_w, float* s_b,
                                       const float* __restrict__ W,
                                       const float* __restrict__ bias)
{
    for (int i = threadIdx.x; i < COUT*CIN*9; i += 256) {
        int g = i / 9, k = i - g*9;
        s_w[g*12 + k] = W[i];
    }
    for (int i = threadIdx.x; i < COUT; i += 256) s_b[i] = bias[i];
}

template<int CIN,int COUT>
__device__ __forceinline__ void conv_core(const float* s_in, const float* s_w,
                                          const float* s_b, float* acc,
                                          int y, int x)
{
    #pragma unroll
    for (int co = 0; co < COUT; co++) acc[co] = s_b[co];
    #pragma unroll 1
    for (int cin = 0; cin < CIN; cin++) {
        const float* sp = s_in + cin*324 + y*18 + x;
        float v0=sp[0],  v1=sp[1],  v2=sp[2];
        float v3=sp[18], v4=sp[19], v5=sp[20];
        float v6=sp[36], v7=sp[37], v8=sp[38];
        #pragma unroll
        for (int co = 0; co < COUT; co++) {
            const float4* wp = reinterpret_cast<const float4*>(s_w + (co*CIN + cin)*12);
            float4 wa = wp[0], wb = wp[1], wc4 = wp[2];
            acc[co] += v0*wa.x + v1*wa.y + v2*wa.z
                     + v3*wa.w + v4*wb.x + v5*wb.y
                     + v6*wb.z + v7*wb.w + v8*wc4.x;
        }
    }
}

// smem byte sizes
#define SMEM_CONVM ((16*324 + 16*16*12 + 16)*4)
#define SMEM_GRUA  ((32*324 + 32*32*12 + 32)*4)
#define SMEM_GRUB  ((32*324 + 16*32*12 + 16)*4)

// ---------------- kernels --------------------------------------------------
// mean over patch + q/k projections
__global__ __launch_bounds__(256) void k_meanqk(const float* __restrict__ X,
    const float* __restrict__ wq, const float* __restrict__ bq,
    const float* __restrict__ wk, const float* __restrict__ bk,
    float* __restrict__ qv, float* __restrict__ kv)
{
    int bn = blockIdx.x; int b = bn >> 6, n = bn & 63;
    int p16 = (n >> 3)*16, q16 = (n & 7)*16;
    __shared__ float s_xm[CC];
    int tid = threadIdx.x, w = tid >> 5, lane = tid & 31;
    for (int c = w*2; c < w*2 + 2; c++) {
        float s = 0.f;
        for (int i = lane; i < 256; i += 32) {
            int y = i >> 4, x = i & 15;
            s += X[((b*CC + c)*128 + p16 + y)*128 + q16 + x];
        }
        #pragma unroll
        for (int o = 16; o; o >>= 1) s += __shfl_down_sync(0xffffffffu, s, o);
        if (!lane) s_xm[c] = s * (1.f/256.f);
    }
    __syncthreads();
    if (tid < 64) {
        int d = tid & 31;
        const float* wM = (tid < 32) ? wq : wk;
        const float* bM = (tid < 32) ? bq : bk;
        float a = bM[d];
        #pragma unroll
        for (int c = 0; c < CC; c++) a += s_xm[c]*wM[c*DQK + d];
        float* dst = (tid < 32) ? qv : kv;
        dst[(b*NN + n)*DQK + d] = a;
    }
}

// edge MLP: one block per edge, loops over batch; weights cached in smem
__global__ __launch_bounds__(64) void k_edgemlp(const int* __restrict__ eidx,
    const float* __restrict__ qv, const float* __restrict__ kv,
    const float* __restrict__ W1, const float* __restrict__ b1,
    const float* __restrict__ W2, const float* __restrict__ b2,
    const float* __restrict__ wo, const float* __restrict__ bo,
    float* __restrict__ ev, int E, int B)
{
    __shared__ float sW1[HIDN*HIDN], sW2[HIDN*HIDN];
    __shared__ float sb1[HIDN], sb2[HIDN], swo[HIDN];
    __shared__ float h0[HIDN], h1[HIDN], sred[2];
    int e = blockIdx.x, tid = threadIdx.x;
    int ei = eidx[2*e], ej = eidx[2*e + 1];
    for (int i = tid; i < HIDN*HIDN; i += 64) { sW1[i] = W1[i]; sW2[i] = W2[i]; }
    sb1[tid] = b1[tid]; sb2[tid] = b2[tid]; swo[tid] = wo[tid];
    float bov = bo[0];
    __syncthreads();
    for (int b = 0; b < B; b++) {
        h0[tid] = (tid < 32) ? qv[(b*NN + ei)*DQK + tid]
                             : kv[(b*NN + ej)*DQK + (tid - 32)];
        __syncthreads();
        float a = sb1[tid];
        #pragma unroll
        for (int i = 0; i < HIDN; i++) a += h0[i]*sW1[i*HIDN + tid];
        h1[tid] = fmaxf(a, 0.f);
        __syncthreads();
        float a2 = sb2[tid];
        #pragma unroll
        for (int i = 0; i < HIDN; i++) a2 += h1[i]*sW2[i*HIDN + tid];
        a2 = fmaxf(a2, 0.f);
        float part = a2*swo[tid];
        #pragma unroll
        for (int o = 16; o; o >>= 1) part += __shfl_down_sync(0xffffffffu, part, o);
        if ((tid & 31) == 0) sred[tid >> 5] = part;
        __syncthreads();
        if (tid == 0) ev[b*E + e] = sred[0] + sred[1] + bov;
        __syncthreads();
    }
}

// message conv M = conv(X, wm) + bm
__global__ __launch_bounds__(256) void k_convM(const float* __restrict__ X,
    const float* __restrict__ W, const float* __restrict__ bias,
    float* __restrict__ M)
{
    int bn = blockIdx.x; int b = bn >> 6, n = bn & 63;
    int p16 = (n >> 3)*16, q16 = (n & 7)*16;
    extern __shared__ float sm[];
    float* s_in = sm;
    float* s_w  = sm + 16*324;
    float* s_b  = s_w + 16*16*12;
    load_tile<16>(s_in, X, nullptr, b, p16, q16);
    load_w<16,16>(s_w, s_b, W, bias);
    __syncthreads();
    int y = threadIdx.x >> 4, x = threadIdx.x & 15;
    float acc[16];
    conv_core<16,16>(s_in, s_w, s_b, acc, y, x);
    int base = ((b*CC)*128 + p16 + y)*128 + q16 + x;
    #pragma unroll
    for (int co = 0; co < 16; co++) M[base + co*PLANE] = acc[co];
}

// T has only 9 distinct values per channel (corner/edge/interior classes)
__global__ void k_T9(const float* __restrict__ gw, float* __restrict__ T9)
{
    int tid = threadIdx.x; if (tid >= CC*9) return;
    int c = tid / 9, cls = tid - c*9, ry = cls/3, rx = cls - ry*3;
    float s = 0.f;
    #pragma unroll
    for (int ky = 0; ky < 3; ky++) {
        if ((ry == 0 && ky == 0) || (ry == 2 && ky == 2)) continue;
        #pragma unroll
        for (int kx = 0; kx < 3; kx++) {
            if ((rx == 0 && kx == 0) || (rx == 2 && kx == 2)) continue;
            s += gw[c*9 + ky*3 + kx];
        }
    }
    T9[tid] = s;
}

// deterministic CSR build (single thread over smem copy of edges)
__global__ void k_csr(const int* __restrict__ eidx, int E,
                      int* __restrict__ off, int* __restrict__ le, int* __restrict__ lj)
{
    __shared__ int se[MAXE*2];
    for (int i = threadIdx.x; i < 2*E; i += blockDim.x) se[i] = eidx[i];
    __syncthreads();
    if (threadIdx.x == 0) {
        int cnt[NN];
        for (int i = 0; i < NN; i++) cnt[i] = 0;
        for (int e = 0; e < E; e++) cnt[se[2*e]]++;
        int acc = 0;
        for (int i = 0; i < NN; i++) { off[i] = acc; acc += cnt[i]; cnt[i] = 0; }
        off[NN] = acc;
        for (int e = 0; e < E; e++) {
            int i = se[2*e];
            int s = off[i] + cnt[i]++;
            le[s] = e; lj[s] = se[2*e + 1];
        }
    }
}

// gate table: sigmoid over (b,edge,c,9-class) only
__global__ void k_gtab(const float* __restrict__ ev, const float* __restrict__ T9,
                       const float* __restrict__ gb, float* __restrict__ gt, int total)
{
    int idx = blockIdx.x*256 + threadIdx.x;
    if (idx >= total) return;
    int cls = idx % 9; int t = idx / 9; int c = t & 15; int be = t >> 4;
    float x = ev[be]*T9[c*9 + cls] + gb[c];
    gt[idx] = sigf(x);
}

// segment-sum of gated messages
__global__ __launch_bounds__(256) void k_agg(const float* __restrict__ M,
    const float* __restrict__ gt, const int* __restrict__ off,
    const int* __restrict__ le, const int* __restrict__ lj,
    float* __restrict__ agg, int E)
{
    int bn = blockIdx.x; int b = bn >> 6, i = bn & 63;
    int p16 = (i >> 3)*16, q16 = (i & 7)*16;
    int o0 = off[i], deg = off[i+1] - o0;
    __shared__ float sg[8*144];
    __shared__ int sbase[8];
    int tid = threadIdx.x;
    if (tid < deg) {
        int ej = lj[o0 + tid];
        sbase[tid] = ((b*CC)*128 + (ej >> 3)*16)*128 + (ej & 7)*16;
    }
    for (int t = tid; t < deg*144; t += 256) {
        int l = t / 144, r = t - l*144;
        int e = le[o0 + l];
        sg[t] = gt[((b*E + e)*CC)*9 + r];
    }
    __syncthreads();
    int y = tid >> 4, x = tid & 15;
    int cy = (y == 0) ? 0 : ((y == 15) ? 2 : 1);
    int cx = (x == 0) ? 0 : ((x == 15) ? 2 : 1);
    int cls = cy*3 + cx;
    int obase = ((b*CC)*128 + p16 + y)*128 + q16 + x;
    int pix = y*128 + x;
    #pragma unroll 1
    for (int c = 0; c < CC; c++) {
        float a = 0.f;
        for (int l = 0; l < deg; l++)
            a += sg[l*144 + c*9 + cls] * M[sbase[l] + c*PLANE + pix];
        agg[obase + c*PLANE] = a;
    }
}

// GRU gate conv: zr = sigmoid(conv([agg,h], wg)+bg); emit z and r*h
__global__ __launch_bounds__(256) void k_gruA(const float* __restrict__ agg,
    const float* __restrict__ X, const float* __restrict__ W,
    const float* __restrict__ bias, float* __restrict__ zb, float* __restrict__ rhb)
{
    int bn = blockIdx.x; int b = bn >> 6, n = bn & 63;
    int p16 = (n >> 3)*16, q16 = (n & 7)*16;
    extern __shared__ float sm[];
    float* s_in = sm;
    float* s_w  = sm + 32*324;
    float* s_b  = s_w + 32*32*12;
    load_tile<32>(s_in, agg, X, b, p16, q16);
    load_w<32,32>(s_w, s_b, W, bias);
    __syncthreads();
    int y = threadIdx.x >> 4, x = threadIdx.x & 15;
    float acc[32];
    conv_core<32,32>(s_in, s_w, s_b, acc, y, x);
    int base = ((b*CC)*128 + p16 + y)*128 + q16 + x;
    #pragma unroll
    for (int c = 0; c < 16; c++) {
        float z = sigf(acc[c]);
        float r = sigf(acc[16 + c]);
        float h = s_in[(16 + c)*324 + (y + 1)*18 + (x + 1)];
        zb [base + c*PLANE] = z;
        rhb[base + c*PLANE] = r*h;
    }
}

// GRU candidate conv + state update
__global__ __launch_bounds__(256) void k_gruB(const float* __restrict__ agg,
    const float* __restrict__ rhb, const float* __restrict__ W,
    const float* __restrict__ bias, const float* __restrict__ zb,
    const float* __restrict__ X, float* __restrict__ Xn)
{
    int bn = blockIdx.x; int b = bn >> 6, n = bn & 63;
    int p16 = (n >> 3)*16, q16 = (n & 7)*16;
    extern __shared__ float sm[];
    float* s_in = sm;
    float* s_w  = sm + 32*324;
    float* s_b  = s_w + 16*32*12;
    load_tile<32>(s_in, agg, rhb, b, p16, q16);
    load_w<32,16>(s_w, s_b, W, bias);
    __syncthreads();
    int y = threadIdx.x >> 4, x = threadIdx.x & 15;
    float acc[16];
    conv_core<32,16>(s_in, s_w, s_b, acc, y, x);
    int base = ((b*CC)*128 + p16 + y)*128 + q16 + x;
    #pragma unroll
    for (int c = 0; c < 16; c++) {
        int idx = base + c*PLANE;
        float cand = tanhf(acc[c]);
        float z = zb[idx];
        float h = X[idx];
        Xn[idx] = (1.f - z)*h + z*cand;
    }
}

// ---------------- launch ----------------------------------------------------
extern "C" void kernel_launch(void* const* d_in, const int* in_sizes, int n_in,
                              void* d_out, int out_size)
{
    const float* seed = (const float*)d_in[0];
    const int*   eidx = (const int*)  d_in[1];
    const float* wq = (const float*)d_in[2];
    const float* bq = (const float*)d_in[3];
    const float* wk = (const float*)d_in[4];
    const float* bk = (const float*)d_in[5];
    const float* wm = (const float*)d_in[6];
    const float* bm = (const float*)d_in[7];
    const float* w1 = (const float*)d_in[8];
    const float* b1 = (const float*)d_in[9];
    const float* w2 = (const float*)d_in[10];
    const float* b2 = (const float*)d_in[11];
    const float* wo = (const float*)d_in[12];
    const float* bo = (const float*)d_in[13];
    const float* gw = (const float*)d_in[14];
    const float* gb = (const float*)d_in[15];
    const float* wg = (const float*)d_in[16];
    const float* bg = (const float*)d_in[17];
    const float* wc = (const float*)d_in[18];
    const float* bc = (const float*)d_in[19];
    float* out = (float*)d_out;

    int B = in_sizes[0] / (CC*128*128);
    int E = in_sizes[1] / 2;

    void *pXa,*pXb,*pM,*pAg,*pZ,*pRH,*pq,*pk,*pev,*pT9,*pgt,*poff,*ple,*plj;
    cudaGetSymbolAddress(&pXa, g_Xa);  cudaGetSymbolAddress(&pXb, g_Xb);
    cudaGetSymbolAddress(&pM,  g_M);   cudaGetSymbolAddress(&pAg, g_Ag);
    cudaGetSymbolAddress(&pZ,  g_Z);   cudaGetSymbolAddress(&pRH, g_RH);
    cudaGetSymbolAddress(&pq,  g_q);   cudaGetSymbolAddress(&pk,  g_k);
    cudaGetSymbolAddress(&pev, g_ev);  cudaGetSymbolAddress(&pT9, g_T9);
    cudaGetSymbolAddress(&pgt, g_gt);  cudaGetSymbolAddress(&poff,g_off);
    cudaGetSymbolAddress(&ple, g_le);  cudaGetSymbolAddress(&plj, g_lj);

    cudaFuncSetAttribute(k_convM, cudaFuncAttributeMaxDynamicSharedMemorySize, SMEM_CONVM);
    cudaFuncSetAttribute(k_gruA,  cudaFuncAttributeMaxDynamicSharedMemorySize, SMEM_GRUA);
    cudaFuncSetAttribute(k_gruB,  cudaFuncAttributeMaxDynamicSharedMemorySize, SMEM_GRUB);

    k_T9 <<<1, 160>>>(gw, (float*)pT9);
    k_csr<<<1, 256>>>(eidx, E, (int*)poff, (int*)ple, (int*)plj);

    const float* Xc = seed;
    for (int it = 0; it < 4; it++) {
        float* Xn = (it == 3) ? out : ((it & 1) ? (float*)pXb : (float*)pXa);

        k_meanqk <<<B*NN, 256>>>(Xc, wq, bq, wk, bk, (float*)pq, (float*)pk);
        k_edgemlp<<<E, 64>>>(eidx, (const float*)pq, (const float*)pk,
                             w1, b1, w2, b2, wo, bo, (float*)pev, E, B);
        k_convM  <<<B*NN, 256, SMEM_CONVM>>>(Xc, wm, bm, (float*)pM);
        int tot = B*E*CC*9;
        k_gtab   <<<(tot + 255)/256, 256>>>((const float*)pev, (const float*)pT9,
                                            gb, (float*)pgt, tot);
        k_agg    <<<B*NN, 256>>>((const float*)pM, (const float*)pgt,
                                 (const int*)poff, (const int*)ple, (const int*)plj,
                                 (float*)pAg, E);
        k_gruA   <<<B*NN, 256, SMEM_GRUA>>>((const float*)pAg, Xc, wg, bg,
                                            (float*)pZ, (float*)pRH);
        k_gruB   <<<B*NN, 256, SMEM_GRUB>>>((const float*)pAg, (const float*)pRH,
                                            wc, bc, (const float*)pZ, Xc, Xn);
        Xc = Xn;
    }
}

// round 2
// speedup vs baseline: 1.3608x; 1.3608x over previous
#include <cuda_runtime.h>

typedef unsigned long long ull;

// Problem constants (fixed by the dataset)
#define CC     16
#define NN     64
#define DQK    32
#define HIDN   64
#define MAXE   512
#define BMAX   16
#define PLANE  16384

// ---------------- scratch ----------------------------------------------------
__device__ float g_Xa [BMAX*CC*PLANE];
__device__ float g_Xb [BMAX*CC*PLANE];
__device__ float g_M  [BMAX*CC*PLANE];
__device__ float g_Ag [BMAX*CC*PLANE];
__device__ float g_Z  [BMAX*CC*PLANE];
__device__ float g_RH [BMAX*CC*PLANE];
__device__ float g_AB [BMAX*NN*128];     // per-node precomputed MLP-layer1 partials
__device__ float g_ev [BMAX*MAXE];
__device__ float g_T9 [CC*9];
__device__ int   g_off[NN+1];
__device__ int   g_le [MAXE];
__device__ int   g_lj [MAXE];

__device__ __forceinline__ float sigf(float x){ return 1.f/(1.f+__expf(-x)); }

// ---------------- f32x2 packed helpers --------------------------------------
__device__ __forceinline__ ull pk(float lo, float hi){
    ull r; asm("mov.b64 %0,{%1,%2};" : "=l"(r) : "f"(lo), "f"(hi)); return r;
}
__device__ __forceinline__ float2 unpk(ull v){
    float2 r; asm("mov.b64 {%0,%1},%2;" : "=f"(r.x), "=f"(r.y) : "l"(v)); return r;
}
__device__ __forceinline__ void fma2(ull& d, ull a, ull b){
    asm("fma.rn.f32x2 %0,%1,%2,%0;" : "+l"(d) : "l"(a), "l"(b));
}
__device__ __forceinline__ ull lds64(const float* p){
    return *reinterpret_cast<const ull*>(p);
}

// ---------------- tile / weight loaders (128-thread blocks) ------------------
// input tile: [CIN][18][18] with zero halo
template<int CIN>
__device__ __forceinline__ void load_tile(float* s_in,
                                          const float* __restrict__ in0,
                                          const float* __restrict__ in1,
                                          int b, int p16, int q16)
{
    for (int i = threadIdx.x; i < CIN*324; i += 128) {
        int cin = i / 324; int r = i - cin*324;
        int yy = r / 18, xx = r - yy*18;
        int ly = yy - 1, lx = xx - 1;
        float v = 0.f;
        if ((unsigned)ly < 16u && (unsigned)lx < 16u) {
            const float* src = (CIN == 16 || cin < 16) ? in0 : in1;
            int c = (CIN == 16 || cin < 16) ? cin : (cin - 16);
            v = src[((b*CC + c)*128 + p16 + ly)*128 + (q16 + lx)];
        }
        s_in[i] = v;
    }
}

// weights padded to 12 floats per (cout,cin) group so they load as 3x LDS.128
template<int CIN,int COUT>
__device__ __forceinline__ void load_w(float* s_w, float* s_b,
                                       const float* __restrict__ W,
                                       const float* __restrict__ bias)
{
    for (int i = threadIdx.x; i < COUT*CIN*9; i += 128) {
        int g = i / 9, k = i - g*9;
        s_w[g*12 + k] = W[i];
    }
    for (int i = threadIdx.x; i < COUT; i += 128) s_b[i] = bias[i];
}

// ---------------- packed conv core ------------------------------------------
// thread computes 4 pixels (y, x0..x0+3) as two f32x2 pairs, for COH couts
// starting at coBase. s_in rows are 18 floats; 8-byte alignment holds.
template<int CIN,int COUT,int COH>
__device__ __forceinline__ void conv_packed(const float* s_in, const float* s_w,
                                            const float* s_b, ull acc[COH][2],
                                            int y, int x0, int coBase)
{
    #pragma unroll
    for (int co = 0; co < COH; co++) {
        float bb = s_b[coBase + co];
        acc[co][0] = pk(bb, bb);
        acc[co][1] = acc[co][0];
    }
    #pragma unroll 1
    for (int cin = 0; cin < CIN; cin++) {
        const float* sp = s_in + cin*324 + y*18 + x0;
        ull t0[3][3], t1[3][3];
        #pragma unroll
        for (int r = 0; r < 3; r++) {
            ull a0 = lds64(sp + r*18);
            ull a1 = lds64(sp + r*18 + 2);
            ull a2 = lds64(sp + r*18 + 4);
            float2 f0 = unpk(a0);
            float2 f1 = unpk(a1);
            float2 f2 = unpk(a2);
            t0[r][0] = a0; t0[r][1] = pk(f0.y, f1.x); t0[r][2] = a1;
            t1[r][0] = a1; t1[r][1] = pk(f1.y, f2.x); t1[r][2] = a2;
        }
        #pragma unroll
        for (int co = 0; co < COH; co++) {
            const float4* wp = reinterpret_cast<const float4*>(
                                   s_w + ((coBase + co)*CIN + cin)*12);
            float4 wa = wp[0], wb = wp[1], wc = wp[2];
            ull w0 = pk(wa.x, wa.x), w1 = pk(wa.y, wa.y), w2 = pk(wa.z, wa.z);
            ull w3 = pk(wa.w, wa.w), w4 = pk(wb.x, wb.x), w5 = pk(wb.y, wb.y);
            ull w6 = pk(wb.z, wb.z), w7 = pk(wb.w, wb.w), w8 = pk(wc.x, wc.x);
            fma2(acc[co][0], t0[0][0], w0); fma2(acc[co][1], t1[0][0], w0);
            fma2(acc[co][0], t0[0][1], w1); fma2(acc[co][1], t1[0][1], w1);
            fma2(acc[co][0], t0[0][2], w2); fma2(acc[co][1], t1[0][2], w2);
            fma2(acc[co][0], t0[1][0], w3); fma2(acc[co][1], t1[1][0], w3);
            fma2(acc[co][0], t0[1][1], w4); fma2(acc[co][1], t1[1][1], w4);
            fma2(acc[co][0], t0[1][2], w5); fma2(acc[co][1], t1[1][2], w5);
            fma2(acc[co][0], t0[2][0], w6); fma2(acc[co][1], t1[2][0], w6);
            fma2(acc[co][0], t0[2][1], w7); fma2(acc[co][1], t1[2][1], w7);
            fma2(acc[co][0], t0[2][2], w8); fma2(acc[co][1], t1[2][2], w8);
        }
    }
}

// smem byte sizes (tile + padded weights + bias)
#define SMEM_CONVM ((16*324 + 16*16*12 + 16)*4)
#define SMEM_GRUA  ((32*324 + 32*32*12 + 32)*4)
#define SMEM_GRUB  ((32*324 + 16*32*12 + 16)*4)

// ---------------- kernels ----------------------------------------------------
// mean over patch + q/k projections + MLP layer-1 per-node partials A,B
__global__ __launch_bounds__(256) void k_meanqk(const float* __restrict__ X,
    const float* __restrict__ wq, const float* __restrict__ bq,
    const float* __restrict__ wk, const float* __restrict__ bk,
    const float* __restrict__ W1, float* __restrict__ AB)
{
    int bn = blockIdx.x; int b = bn >> 6, n = bn & 63;
    int p16 = (n >> 3)*16, q16 = (n & 7)*16;
    __shared__ float s_xm[CC];
    __shared__ float s_qk[64];
    int tid = threadIdx.x, w = tid >> 5, lane = tid & 31;
    for (int c = w*2; c < w*2 + 2; c++) {
        float s = 0.f;
        for (int i = lane; i < 256; i += 32) {
            int y = i >> 4, x = i & 15;
            s += X[((b*CC + c)*128 + p16 + y)*128 + q16 + x];
        }
        #pragma unroll
        for (int o = 16; o; o >>= 1) s += __shfl_down_sync(0xffffffffu, s, o);
        if (!lane) s_xm[c] = s * (1.f/256.f);
    }
    __syncthreads();
    if (tid < 64) {
        int d = tid & 31;
        const float* wM = (tid < 32) ? wq : wk;
        const float* bM = (tid < 32) ? bq : bk;
        float a = bM[d];
        #pragma unroll
        for (int c = 0; c < CC; c++) a += s_xm[c]*wM[c*DQK + d];
        s_qk[tid] = a;
    }
    __syncthreads();
    if (tid < 128) {
        int t = tid & 63;
        int off = (tid < 64) ? 0 : 32;       // A uses q (rows 0..31), B uses k (rows 32..63)
        float a = 0.f;
        #pragma unroll
        for (int d = 0; d < 32; d++) a += s_qk[off + d]*W1[(off + d)*HIDN + t];
        AB[(b*NN + n)*128 + (tid < 64 ? 0 : 64) + t] = a;
    }
}

// edge MLP (layer1 precomputed): one block per edge, 4 batches in parallel
__global__ __launch_bounds__(256) void k_edgemlp(const int* __restrict__ eidx,
    const float* __restrict__ AB,
    const float* __restrict__ b1,
    const float* __restrict__ W2, const float* __restrict__ b2,
    const float* __restrict__ wo, const float* __restrict__ bo,
    float* __restrict__ ev, int E, int B)
{
    __shared__ float sW2[HIDN*HIDN];
    __shared__ float sb1[HIDN], sb2[HIDN], swo[HIDN];
    __shared__ float h1s[4][HIDN], sred[4][2];
    int e = blockIdx.x, tid = threadIdx.x;
    int bg = tid >> 6, t = tid & 63;
    int ei = eidx[2*e], ej = eidx[2*e + 1];
    for (int i = tid; i < HIDN*HIDN; i += 256) sW2[i] = W2[i];
    if (tid < HIDN) { sb1[tid] = b1[tid]; sb2[tid] = b2[tid]; swo[tid] = wo[tid]; }
    float bov = bo[0];
    __syncthreads();
    for (int b = bg; b < B; b += 4) {
        float h1 = AB[(b*NN + ei)*128 + t] + AB[(b*NN + ej)*128 + 64 + t] + sb1[t];
        h1s[bg][t] = fmaxf(h1, 0.f);
        __syncthreads();
        float a2 = sb2[t];
        #pragma unroll
        for (int i = 0; i < HIDN; i++) a2 += h1s[bg][i]*sW2[i*HIDN + t];
        a2 = fmaxf(a2, 0.f);
        float part = a2*swo[t];
        #pragma unroll
        for (int o = 16; o; o >>= 1) part += __shfl_down_sync(0xffffffffu, part, o);
        if ((t & 31) == 0) sred[bg][t >> 5] = part;
        __syncthreads();
        if (t == 0) ev[b*E + e] = sred[bg][0] + sred[bg][1] + bov;
    }
}

// message conv M = conv(X, wm) + bm  (packed f32x2)
__global__ __launch_bounds__(128) void k_convM(const float* __restrict__ X,
    const float* __restrict__ W, const float* __restrict__ bias,
    float* __restrict__ M)
{
    int bn = blockIdx.x; int b = bn >> 6, n = bn & 63;
    int p16 = (n >> 3)*16, q16 = (n & 7)*16;
    extern __shared__ float sm[];
    float* s_in = sm;
    float* s_w  = sm + 16*324;
    float* s_b  = s_w + 16*16*12;
    load_tile<16>(s_in, X, nullptr, b, p16, q16);
    load_w<16,16>(s_w, s_b, W, bias);
    __syncthreads();
    int ch = threadIdx.x >> 6, pg = threadIdx.x & 63;
    int y = pg >> 2, x0 = (pg & 3)*4;
    ull acc[8][2];
    conv_packed<16,16,8>(s_in, s_w, s_b, acc, y, x0, ch*8);
    int base = ((b*CC + ch*8)*128 + p16 + y)*128 + q16 + x0;
    #pragma unroll
    for (int co = 0; co < 8; co++) {
        float2 a = unpk(acc[co][0]), c = unpk(acc[co][1]);
        *reinterpret_cast<float4*>(&M[base + co*PLANE]) = make_float4(a.x, a.y, c.x, c.y);
    }
}

// T has only 9 distinct values per channel
__global__ void k_T9(const float* __restrict__ gw, float* __restrict__ T9)
{
    int tid = threadIdx.x; if (tid >= CC*9) return;
    int c = tid / 9, cls = tid - c*9, ry = cls/3, rx = cls - ry*3;
    float s = 0.f;
    #pragma unroll
    for (int ky = 0; ky < 3; ky++) {
        if ((ry == 0 && ky == 0) || (ry == 2 && ky == 2)) continue;
        #pragma unroll
        for (int kx = 0; kx < 3; kx++) {
            if ((rx == 0 && kx == 0) || (rx == 2 && kx == 2)) continue;
            s += gw[c*9 + ky*3 + kx];
        }
    }
    T9[tid] = s;
}

// deterministic CSR build
__global__ void k_csr(const int* __restrict__ eidx, int E,
                      int* __restrict__ off, int* __restrict__ le, int* __restrict__ lj)
{
    __shared__ int se[MAXE*2];
    for (int i = threadIdx.x; i < 2*E; i += blockDim.x) se[i] = eidx[i];
    __syncthreads();
    if (threadIdx.x == 0) {
        int cnt[NN];
        for (int i = 0; i < NN; i++) cnt[i] = 0;
        for (int e = 0; e < E; e++) cnt[se[2*e]]++;
        int acc = 0;
        for (int i = 0; i < NN; i++) { off[i] = acc; acc += cnt[i]; cnt[i] = 0; }
        off[NN] = acc;
        for (int e = 0; e < E; e++) {
            int i = se[2*e];
            int s = off[i] + cnt[i]++;
            le[s] = e; lj[s] = se[2*e + 1];
        }
    }
}

// segment-sum of gated messages; gate table computed in-block (fused k_gtab)
__global__ __launch_bounds__(256) void k_agg(const float* __restrict__ M,
    const float* __restrict__ ev, const float* __restrict__ T9,
    const float* __restrict__ gb,
    const int* __restrict__ off, const int* __restrict__ le,
    const int* __restrict__ lj,
    float* __restrict__ agg, int E)
{
    int bn = blockIdx.x; int b = bn >> 6, i = bn & 63;
    int p16 = (i >> 3)*16, q16 = (i & 7)*16;
    int o0 = off[i], deg = off[i+1] - o0;
    __shared__ float sg[8*144];
    __shared__ float sT9[144], sgb[CC], sev[8];
    __shared__ int sbase[8];
    int tid = threadIdx.x;
    if (tid < 144) sT9[tid] = T9[tid];
    if (tid < CC)  sgb[tid] = gb[tid];
    if (tid < deg) {
        int e = le[o0 + tid];
        sev[tid] = ev[b*E + e];
        int ej = lj[o0 + tid];
        sbase[tid] = ((b*CC)*128 + (ej >> 3)*16)*128 + (ej & 7)*16;
    }
    __syncthreads();
    for (int t = tid; t < deg*144; t += 256) {
        int l = t / 144, r = t - l*144;
        int c = r / 9, cls = r - c*9;
        sg[t] = sigf(sev[l]*sT9[c*9 + cls] + sgb[c]);
    }
    __syncthreads();
    // thread: 4 channels (cg) x 4 pixels (y, x0..x0+3)
    int cg = tid >> 6, pg = tid & 63;
    int y = pg >> 2, x0 = (pg & 3)*4;
    int cy = (y == 0) ? 0 : ((y == 15) ? 2 : 1);
    int cix[4];
    #pragma unroll
    for (int k = 0; k < 4; k++) {
        int x = x0 + k;
        cix[k] = cy*3 + ((x == 0) ? 0 : ((x == 15) ? 2 : 1));
    }
    int pix = y*128 + x0;
    #pragma unroll
    for (int cc = 0; cc < 4; cc++) {
        int c = cg*4 + cc;
        float4 a = make_float4(0.f, 0.f, 0.f, 0.f);
        for (int l = 0; l < deg; l++) {
            const float* gl = &sg[l*144 + c*9];
            float4 m = *reinterpret_cast<const float4*>(&M[sbase[l] + c*PLANE + pix]);
            a.x += gl[cix[0]]*m.x;
            a.y += gl[cix[1]]*m.y;
            a.z += gl[cix[2]]*m.z;
            a.w += gl[cix[3]]*m.w;
        }
        int obase = ((b*CC + c)*128 + p16 + y)*128 + q16 + x0;
        *reinterpret_cast<float4*>(&agg[obase]) = a;
    }
}

// GRU gate conv (packed): z (half 0) and r*h (half 1)
__global__ __launch_bounds__(128) void k_gruA(const float* __restrict__ agg,
    const float* __restrict__ X, const float* __restrict__ W,
    const float* __restrict__ bias, float* __restrict__ zb, float* __restrict__ rhb)
{
    int bn = blockIdx.x; int b = bn >> 6, n = bn & 63;
    int p16 = (n >> 3)*16, q16 = (n & 7)*16;
    extern __shared__ float sm[];
    float* s_in = sm;
    float* s_w  = sm + 32*324;
    float* s_b  = s_w + 32*32*12;
    load_tile<32>(s_in, agg, X, b, p16, q16);
    load_w<32,32>(s_w, s_b, W, bias);
    __syncthreads();
    int ch = threadIdx.x >> 6, pg = threadIdx.x & 63;
    int y = pg >> 2, x0 = (pg & 3)*4;
    ull acc[16][2];
    conv_packed<32,32,16>(s_in, s_w, s_b, acc, y, x0, ch*16);
    if (ch == 0) {
        // z gates: couts 0..15
        #pragma unroll
        for (int co = 0; co < 16; co++) {
            float2 a = unpk(acc[co][0]), c = unpk(acc[co][1]);
            int base = ((b*CC + co)*128 + p16 + y)*128 + q16 + x0;
            *reinterpret_cast<float4*>(&zb[base]) =
                make_float4(sigf(a.x), sigf(a.y), sigf(c.x), sigf(c.y));
        }
    } else {
        // r gates: couts 16..31 -> rh for channel co
        #pragma unroll
        for (int co = 0; co < 16; co++) {
            float2 a = unpk(acc[co][0]), c = unpk(acc[co][1]);
            const float* hp = s_in + (16 + co)*324 + (y + 1)*18 + (x0 + 1);
            float4 rh = make_float4(sigf(a.x)*hp[0], sigf(a.y)*hp[1],
                                    sigf(c.x)*hp[2], sigf(c.y)*hp[3]);
            int base = ((b*CC + co)*128 + p16 + y)*128 + q16 + x0;
            *reinterpret_cast<float4*>(&rhb[base]) = rh;
        }
    }
}

// GRU candidate conv (packed) + state update
__global__ __launch_bounds__(128) void k_gruB(const float* __restrict__ agg,
    const float* __restrict__ rhb, const float* __restrict__ W,
    const float* __restrict__ bias, const float* __restrict__ zb,
    const float* __restrict__ X, float* __restrict__ Xn)
{
    int bn = blockIdx.x; int b = bn >> 6, n = bn & 63;
    int p16 = (n >> 3)*16, q16 = (n & 7)*16;
    extern __shared__ float sm[];
    float* s_in = sm;
    float* s_w  = sm + 32*324;
    float* s_b  = s_w + 16*32*12;
    load_tile<32>(s_in, agg, rhb, b, p16, q16);
    load_w<32,16>(s_w, s_b, W, bias);
    __syncthreads();
    int ch = threadIdx.x >> 6, pg = threadIdx.x & 63;
    int y = pg >> 2, x0 = (pg & 3)*4;
    ull acc[8][2];
    conv_packed<32,16,8>(s_in, s_w, s_b, acc, y, x0, ch*8);
    #pragma unroll
    for (int co = 0; co < 8; co++) {
        int c = ch*8 + co;
        int idx = ((b*CC + c)*128 + p16 + y)*128 + q16 + x0;
        float2 a = unpk(acc[co][0]), cc = unpk(acc[co][1]);
        float4 z = *reinterpret_cast<const float4*>(&zb[idx]);
        float4 h = *reinterpret_cast<const float4*>(&X[idx]);
        float4 o;
        o.x = (1.f - z.x)*h.x + z.x*tanhf(a.x);
        o.y = (1.f - z.y)*h.y + z.y*tanhf(a.y);
        o.z = (1.f - z.z)*h.z + z.z*tanhf(cc.x);
        o.w = (1.f - z.w)*h.w + z.w*tanhf(cc.y);
        *reinterpret_cast<float4*>(&Xn[idx]) = o;
    }
}

// ---------------- launch ------------------------------------------------------
extern "C" void kernel_launch(void* const* d_in, const int* in_sizes, int n_in,
                              void* d_out, int out_size)
{
    const float* seed = (const float*)d_in[0];
    const int*   eidx = (const int*)  d_in[1];
    const float* wq = (const float*)d_in[2];
    const float* bq = (const float*)d_in[3];
    const float* wk = (const float*)d_in[4];
    const float* bk = (const float*)d_in[5];
    const float* wm = (const float*)d_in[6];
    const float* bm = (const float*)d_in[7];
    const float* w1 = (const float*)d_in[8];
    const float* b1 = (const float*)d_in[9];
    const float* w2 = (const float*)d_in[10];
    const float* b2 = (const float*)d_in[11];
    const float* wo = (const float*)d_in[12];
    const float* bo = (const float*)d_in[13];
    const float* gw = (const float*)d_in[14];
    const float* gb = (const float*)d_in[15];
    const float* wg = (const float*)d_in[16];
    const float* bg = (const float*)d_in[17];
    const float* wc = (const float*)d_in[18];
    const float* bc = (const float*)d_in[19];
    float* out = (float*)d_out;

    int B = in_sizes[0] / (CC*128*128);
    int E = in_sizes[1] / 2;

    void *pXa,*pXb,*pM,*pAg,*pZ,*pRH,*pAB,*pev,*pT9,*poff,*ple,*plj;
    cudaGetSymbolAddress(&pXa, g_Xa);  cudaGetSymbolAddress(&pXb, g_Xb);
    cudaGetSymbolAddress(&pM,  g_M);   cudaGetSymbolAddress(&pAg, g_Ag);
    cudaGetSymbolAddress(&pZ,  g_Z);   cudaGetSymbolAddress(&pRH, g_RH);
    cudaGetSymbolAddress(&pAB, g_AB);  cudaGetSymbolAddress(&pev, g_ev);
    cudaGetSymbolAddress(&pT9, g_T9);  cudaGetSymbolAddress(&poff,g_off);
    cudaGetSymbolAddress(&ple, g_le);  cudaGetSymbolAddress(&plj, g_lj);

    cudaFuncSetAttribute(k_convM, cudaFuncAttributeMaxDynamicSharedMemorySize, SMEM_CONVM);
    cudaFuncSetAttribute(k_gruA,  cudaFuncAttributeMaxDynamicSharedMemorySize, SMEM_GRUA);
    cudaFuncSetAttribute(k_gruB,  cudaFuncAttributeMaxDynamicSharedMemorySize, SMEM_GRUB);

    k_T9 <<<1, 160>>>(gw, (float*)pT9);
    k_csr<<<1, 256>>>(eidx, E, (int*)poff, (int*)ple, (int*)plj);

    const float* Xc = seed;
    for (int it = 0; it < 4; it++) {
        float* Xn = (it == 3) ? out : ((it & 1) ? (float*)pXb : (float*)pXa);

        k_meanqk <<<B*NN, 256>>>(Xc, wq, bq, wk, bk, w1, (float*)pAB);
        k_edgemlp<<<E, 256>>>(eidx, (const float*)pAB, b1, w2, b2, wo, bo,
                              (float*)pev, E, B);
        k_convM  <<<B*NN, 128, SMEM_CONVM>>>(Xc, wm, bm, (float*)pM);
        k_agg    <<<B*NN, 256>>>((const float*)pM, (const float*)pev,
                                 (const float*)pT9, gb,
                                 (const int*)poff, (const int*)ple, (const int*)plj,
                                 (float*)pAg, E);
        k_gruA   <<<B*NN, 128, SMEM_GRUA>>>((const float*)pAg, Xc, wg, bg,
                                            (float*)pZ, (float*)pRH);
        k_gruB   <<<B*NN, 128, SMEM_GRUB>>>((const float*)pAg, (const float*)pRH,
                                            wc, bc, (const float*)pZ, Xc, Xn);
        Xc = Xn;
    }
}

// round 3
// speedup vs baseline: 1.4439x; 1.0610x over previous
#include <cuda_runtime.h>

typedef unsigned int uint;

// Problem constants (fixed by the dataset)
#define CC     16
#define NN     64
#define DQK    32
#define HIDN   64
#define MAXE   512
#define BMAX   16
#define PLANE  16384

// ---------------- scratch ----------------------------------------------------
__device__ float g_Xa [BMAX*CC*PLANE];
__device__ float g_Xb [BMAX*CC*PLANE];
__device__ float g_M  [BMAX*CC*PLANE];
__device__ float g_Ag [BMAX*CC*PLANE];
__device__ float g_AB [BMAX*NN*128];
__device__ float g_ev [BMAX*MAXE];
__device__ float g_T9 [CC*9];
__device__ int   g_off[NN+1];
__device__ int   g_le [MAXE];
__device__ int   g_lj [MAXE];

__device__ __forceinline__ float sigf(float x){ return 1.f/(1.f+__expf(-x)); }

// ---------------- tf32 helpers -----------------------------------------------
__device__ __forceinline__ void tf32split(float x, uint& hi, uint& lo){
    asm("cvt.rna.tf32.f32 %0,%1;" : "=r"(hi) : "f"(x));
    float l = x - __uint_as_float(hi);
    asm("cvt.rna.tf32.f32 %0,%1;" : "=r"(lo) : "f"(l));
}

__device__ __forceinline__ void mma8(float c[4], const uint a[4], uint b0, uint b1){
    asm volatile("mma.sync.aligned.m16n8k8.row.col.f32.tf32.tf32.f32 "
        "{%0,%1,%2,%3},{%4,%5,%6,%7},{%8,%9},{%0,%1,%2,%3};"
        : "+f"(c[0]),"+f"(c[1]),"+f"(c[2]),"+f"(c[3])
        : "r"(a[0]),"r"(a[1]),"r"(a[2]),"r"(a[3]),"r"(b0),"r"(b1));
}

// ---------------- tile loader (256-thread blocks) -----------------------------
// input tile: [CIN][18][18] with zero halo
template<int CIN>
__device__ __forceinline__ void load_tile(float* s_in,
                                          const float* __restrict__ in0,
                                          const float* __restrict__ in1,
                                          int b, int p16, int q16)
{
    for (int i = threadIdx.x; i < CIN*324; i += 256) {
        int cin = i / 324; int r = i - cin*324;
        int yy = r / 18, xx = r - yy*18;
        int ly = yy - 1, lx = xx - 1;
        float v = 0.f;
        if ((unsigned)ly < 16u && (unsigned)lx < 16u) {
            const float* src = (CIN == 16 || cin < 16) ? in0 : in1;
            int c = (CIN == 16 || cin < 16) ? cin : (cin - 16);
            v = src[((b*CC + c)*128 + p16 + ly)*128 + (q16 + lx)];
        }
        s_in[i] = v;
    }
}

// split weights into hi/lo tf32 smem arrays, tap-major K: k = tap*CIN + cin
// W gmem layout [n][cin][tap]; B[k][n] with row stride N
template<int CIN,int N>
__device__ __forceinline__ void prep_B(const float* __restrict__ W,
                                       float* sBh, float* sBl)
{
    constexpr int TOT = CIN*9*N;
    for (int i = threadIdx.x; i < TOT; i += 256) {
        int n = i % N, k = i / N;
        int cin = k % CIN, tap = k / CIN;
        uint hi, lo;
        tf32split(W[(n*CIN + cin)*9 + tap], hi, lo);
        sBh[i] = __uint_as_float(hi);
        sBl[i] = __uint_as_float(lo);
    }
}

// ---------------- 3xTF32 conv GEMM core --------------------------------------
// M=256 (pixels, mtile m = image row y), K = CIN*9 tap-major, N = NT*8.
// warp handles mtiles {2*wid, 2*wid+1}, all NT n-tiles.
template<int CIN,int NT>
__device__ __forceinline__ void mma_conv(const float* s_tile,
                                         const float* sBh, const float* sBl,
                                         const float* s_bias,
                                         float acc[2][NT][4])
{
    constexpr int N = NT*8;
    constexpr int KSTEPS = CIN*9/8;
    constexpr int KPT = CIN/8;           // ksteps per tap
    int lane = threadIdx.x & 31;
    int wid  = threadIdx.x >> 5;
    int g = lane >> 2, q = lane & 3;
    int m0 = wid*2;

    #pragma unroll
    for (int mm = 0; mm < 2; mm++)
        #pragma unroll
        for (int nt = 0; nt < NT; nt++) {
            float b0 = s_bias[nt*8 + q*2], b1 = s_bias[nt*8 + q*2 + 1];
            acc[mm][nt][0] = b0; acc[mm][nt][1] = b1;
            acc[mm][nt][2] = b0; acc[mm][nt][3] = b1;
        }

    #pragma unroll 1
    for (int ks = 0; ks < KSTEPS; ks++) {
        int tap = ks / KPT;
        int cb  = (ks - tap*KPT)*8 + q;       // cin for a0/a1 (a2/a3: +4)
        int ty = tap/3, tx = tap - ty*3;
        uint ah[2][4], al[2][4];
        #pragma unroll
        for (int mm = 0; mm < 2; mm++) {
            int m = m0 + mm;
            int base = cb*324 + (m + ty)*18 + (g + tx);
            tf32split(s_tile[base],            ah[mm][0], al[mm][0]);
            tf32split(s_tile[base + 8],        ah[mm][1], al[mm][1]);
            tf32split(s_tile[base + 1296],     ah[mm][2], al[mm][2]);
            tf32split(s_tile[base + 1296 + 8], ah[mm][3], al[mm][3]);
        }
        #pragma unroll
        for (int nt = 0; nt < NT; nt++) {
            int n  = nt*8 + g;
            int k0 = ks*8 + q;
            uint b0h = __float_as_uint(sBh[k0*N + n]);
            uint b1h = __float_as_uint(sBh[(k0+4)*N + n]);
            uint b0l = __float_as_uint(sBl[k0*N + n]);
            uint b1l = __float_as_uint(sBl[(k0+4)*N + n]);
            #pragma unroll
            for (int mm = 0; mm < 2; mm++) {
                mma8(acc[mm][nt], ah[mm], b0h, b1h);
                mma8(acc[mm][nt], ah[mm], b0l, b1l);
                mma8(acc[mm][nt], al[mm], b0h, b1h);
            }
        }
    }
}

// ---------------- kernels ----------------------------------------------------
// mean + q/k projections + MLP layer-1 per-node partials
__global__ __launch_bounds__(256) void k_meanqk(const float* __restrict__ X,
    const float* __restrict__ wq, const float* __restrict__ bq,
    const float* __restrict__ wk, const float* __restrict__ bk,
    const float* __restrict__ W1, float* __restrict__ AB)
{
    int bn = blockIdx.x; int b = bn >> 6, n = bn & 63;
    int p16 = (n >> 3)*16, q16 = (n & 7)*16;
    __shared__ float s_xm[CC];
    __shared__ float s_qk[64];
    int tid = threadIdx.x, w = tid >> 5, lane = tid & 31;
    for (int c = w*2; c < w*2 + 2; c++) {
        float s = 0.f;
        for (int i = lane; i < 256; i += 32) {
            int y = i >> 4, x = i & 15;
            s += X[((b*CC + c)*128 + p16 + y)*128 + q16 + x];
        }
        #pragma unroll
        for (int o = 16; o; o >>= 1) s += __shfl_down_sync(0xffffffffu, s, o);
        if (!lane) s_xm[c] = s * (1.f/256.f);
    }
    __syncthreads();
    if (tid < 64) {
        int d = tid & 31;
        const float* wM = (tid < 32) ? wq : wk;
        const float* bM = (tid < 32) ? bq : bk;
        float a = bM[d];
        #pragma unroll
        for (int c = 0; c < CC; c++) a += s_xm[c]*wM[c*DQK + d];
        s_qk[tid] = a;
    }
    __syncthreads();
    if (tid < 128) {
        int t = tid & 63;
        int off = (tid < 64) ? 0 : 32;
        float a = 0.f;
        #pragma unroll
        for (int d = 0; d < 32; d++) a += s_qk[off + d]*W1[(off + d)*HIDN + t];
        AB[(b*NN + n)*128 + (tid < 64 ? 0 : 64) + t] = a;
    }
}

// edge MLP: one block per edge, 4 batches in parallel
__global__ __launch_bounds__(256) void k_edgemlp(const int* __restrict__ eidx,
    const float* __restrict__ AB, const float* __restrict__ b1,
    const float* __restrict__ W2, const float* __restrict__ b2,
    const float* __restrict__ wo, const float* __restrict__ bo,
    float* __restrict__ ev, int E, int B)
{
    __shared__ float sW2[HIDN*HIDN];
    __shared__ float sb1[HIDN], sb2[HIDN], swo[HIDN];
    __shared__ float h1s[4][HIDN], sred[4][2];
    int e = blockIdx.x, tid = threadIdx.x;
    int bg = tid >> 6, t = tid & 63;
    int ei = eidx[2*e], ej = eidx[2*e + 1];
    for (int i = tid; i < HIDN*HIDN; i += 256) sW2[i] = W2[i];
    if (tid < HIDN) { sb1[tid] = b1[tid]; sb2[tid] = b2[tid]; swo[tid] = wo[tid]; }
    float bov = bo[0];
    __syncthreads();
    for (int b = bg; b < B; b += 4) {
        float h1 = AB[(b*NN + ei)*128 + t] + AB[(b*NN + ej)*128 + 64 + t] + sb1[t];
        h1s[bg][t] = fmaxf(h1, 0.f);
        __syncthreads();
        float a2 = sb2[t];
        #pragma unroll
        for (int i = 0; i < HIDN; i++) a2 += h1s[bg][i]*sW2[i*HIDN + t];
        a2 = fmaxf(a2, 0.f);
        float part = a2*swo[t];
        #pragma unroll
        for (int o = 16; o; o >>= 1) part += __shfl_down_sync(0xffffffffu, part, o);
        if ((t & 31) == 0) sred[bg][t >> 5] = part;
        __syncthreads();
        if (t == 0) ev[b*E + e] = sred[bg][0] + sred[bg][1] + bov;
    }
}

// message conv M = conv(X, wm) + bm via 3xTF32 MMA
__global__ __launch_bounds__(256) void k_convM(const float* __restrict__ X,
    const float* __restrict__ W, const float* __restrict__ bias,
    float* __restrict__ M)
{
    int bn = blockIdx.x; int b = bn >> 6, n = bn & 63;
    int p16 = (n >> 3)*16, q16 = (n & 7)*16;
    __shared__ float s_tile[16*324];
    __shared__ float sBh[144*16], sBl[144*16];
    __shared__ float s_bias[16];
    load_tile<16>(s_tile, X, nullptr, b, p16, q16);
    prep_B<16,16>(W, sBh, sBl);
    if (threadIdx.x < 16) s_bias[threadIdx.x] = bias[threadIdx.x];
    __syncthreads();

    float acc[2][2][4];
    mma_conv<16,2>(s_tile, sBh, sBl, s_bias, acc);

    int lane = threadIdx.x & 31, wid = threadIdx.x >> 5;
    int g = lane >> 2, q = lane & 3, m0 = wid*2;
    #pragma unroll
    for (int mm = 0; mm < 2; mm++) {
        int y = m0 + mm;
        #pragma unroll
        for (int nt = 0; nt < 2; nt++) {
            int co = nt*8 + q*2;
            int r0 = ((b*CC + co)*128 + p16 + y)*128 + q16;
            int r1 = r0 + PLANE;
            M[r0 + g]     = acc[mm][nt][0];
            M[r1 + g]     = acc[mm][nt][1];
            M[r0 + g + 8] = acc[mm][nt][2];
            M[r1 + g + 8] = acc[mm][nt][3];
        }
    }
}

// T 9-class table
__global__ void k_T9(const float* __restrict__ gw, float* __restrict__ T9)
{
    int tid = threadIdx.x; if (tid >= CC*9) return;
    int c = tid / 9, cls = tid - c*9, ry = cls/3, rx = cls - ry*3;
    float s = 0.f;
    #pragma unroll
    for (int ky = 0; ky < 3; ky++) {
        if ((ry == 0 && ky == 0) || (ry == 2 && ky == 2)) continue;
        #pragma unroll
        for (int kx = 0; kx < 3; kx++) {
            if ((rx == 0 && kx == 0) || (rx == 2 && kx == 2)) continue;
            s += gw[c*9 + ky*3 + kx];
        }
    }
    T9[tid] = s;
}

// deterministic CSR build
__global__ void k_csr(const int* __restrict__ eidx, int E,
                      int* __restrict__ off, int* __restrict__ le, int* __restrict__ lj)
{
    __shared__ int se[MAXE*2];
    for (int i = threadIdx.x; i < 2*E; i += blockDim.x) se[i] = eidx[i];
    __syncthreads();
    if (threadIdx.x == 0) {
        int cnt[NN];
        for (int i = 0; i < NN; i++) cnt[i] = 0;
        for (int e = 0; e < E; e++) cnt[se[2*e]]++;
        int acc = 0;
        for (int i = 0; i < NN; i++) { off[i] = acc; acc += cnt[i]; cnt[i] = 0; }
        off[NN] = acc;
        for (int e = 0; e < E; e++) {
            int i = se[2*e];
            int s = off[i] + cnt[i]++;
            le[s] = e; lj[s] = se[2*e + 1];
        }
    }
}

// segment-sum of gated messages (gate table fused, float4)
__global__ __launch_bounds__(256) void k_agg(const float* __restrict__ M,
    const float* __restrict__ ev, const float* __restrict__ T9,
    const float* __restrict__ gb,
    const int* __restrict__ off, const int* __restrict__ le,
    const int* __restrict__ lj,
    float* __restrict__ agg, int E)
{
    int bn = blockIdx.x; int b = bn >> 6, i = bn & 63;
    int p16 = (i >> 3)*16, q16 = (i & 7)*16;
    int o0 = off[i], deg = off[i+1] - o0;
    __shared__ float sg[8*144];
    __shared__ float sT9[144], sgb[CC], sev[8];
    __shared__ int sbase[8];
    int tid = threadIdx.x;
    if (tid < 144) sT9[tid] = T9[tid];
    if (tid < CC)  sgb[tid] = gb[tid];
    if (tid < deg) {
        int e = le[o0 + tid];
        sev[tid] = ev[b*E + e];
        int ej = lj[o0 + tid];
        sbase[tid] = ((b*CC)*128 + (ej >> 3)*16)*128 + (ej & 7)*16;
    }
    __syncthreads();
    for (int t = tid; t < deg*144; t += 256) {
        int l = t / 144, r = t - l*144;
        int c = r / 9, cls = r - c*9;
        sg[t] = sigf(sev[l]*sT9[c*9 + cls] + sgb[c]);
    }
    __syncthreads();
    int cg = tid >> 6, pg = tid & 63;
    int y = pg >> 2, x0 = (pg & 3)*4;
    int cy = (y == 0) ? 0 : ((y == 15) ? 2 : 1);
    int cix[4];
    #pragma unroll
    for (int k = 0; k < 4; k++) {
        int x = x0 + k;
        cix[k] = cy*3 + ((x == 0) ? 0 : ((x == 15) ? 2 : 1));
    }
    int pix = y*128 + x0;
    #pragma unroll
    for (int cc = 0; cc < 4; cc++) {
        int c = cg*4 + cc;
        float4 a = make_float4(0.f, 0.f, 0.f, 0.f);
        for (int l = 0; l < deg; l++) {
            const float* gl = &sg[l*144 + c*9];
            float4 m = *reinterpret_cast<const float4*>(&M[sbase[l] + c*PLANE + pix]);
            a.x += gl[cix[0]]*m.x;
            a.y += gl[cix[1]]*m.y;
            a.z += gl[cix[2]]*m.z;
            a.w += gl[cix[3]]*m.w;
        }
        int obase = ((b*CC + c)*128 + p16 + y)*128 + q16 + x0;
        *reinterpret_cast<float4*>(&agg[obase]) = a;
    }
}

// fused GRU: gate conv -> z, rh; candidate conv -> update, all in one block
__global__ __launch_bounds__(256) void k_gru(const float* __restrict__ agg,
    const float* __restrict__ X,
    const float* __restrict__ Wg, const float* __restrict__ bg,
    const float* __restrict__ Wc, const float* __restrict__ bc,
    float* __restrict__ Xn)
{
    int bn = blockIdx.x; int b = bn >> 6, n = bn & 63;
    int p16 = (n >> 3)*16, q16 = (n & 7)*16;
    extern __shared__ float sm[];
    float* s_tile = sm;                       // 32*324 = 10368
    float* sBgh   = s_tile + 10368;           // 288*32 = 9216
    float* sBgl   = sBgh + 9216;
    float* sBch   = sBgl + 9216;              // 288*16 = 4608
    float* sBcl   = sBch + 4608;
    float* s_z    = sBcl + 4608;              // 16*256 = 4096
    float* s_bg   = s_z + 4096;               // 32
    float* s_bc   = s_bg + 32;                // 16

    load_tile<32>(s_tile, agg, X, b, p16, q16);
    prep_B<32,32>(Wg, sBgh, sBgl);
    prep_B<32,16>(Wc, sBch, sBcl);
    if (threadIdx.x < 32) s_bg[threadIdx.x] = bg[threadIdx.x];
    if (threadIdx.x < 16) s_bc[threadIdx.x] = bc[threadIdx.x];
    __syncthreads();

    int lane = threadIdx.x & 31, wid = threadIdx.x >> 5;
    int g = lane >> 2, q = lane & 3, m0 = wid*2;

    // ---- gate conv ----
    {
        float acc[2][4][4];
        mma_conv<32,4>(s_tile, sBgh, sBgl, s_bg, acc);
        __syncthreads();   // all tile reads done before rh overwrite
        #pragma unroll
        for (int mm = 0; mm < 2; mm++) {
            int y = m0 + mm;
            #pragma unroll
            for (int nt = 0; nt < 4; nt++) {
                int co = nt*8 + q*2;
                #pragma unroll
                for (int rr = 0; rr < 4; rr++) {
                    int c  = co + (rr & 1);
                    int x  = g + (rr >= 2 ? 8 : 0);
                    float v = sigf(acc[mm][nt][rr]);
                    if (c < 16) {
                        s_z[c*256 + y*16 + x] = v;
                    } else {
                        float* hp = &s_tile[c*324 + (y + 1)*18 + (x + 1)];
                        *hp = v * (*hp);      // rh overwrites X in tile
                    }
                }
            }
        }
    }
    __syncthreads();

    // ---- candidate conv + update ----
    {
        float acc[2][2][4];
        mma_conv<32,2>(s_tile, sBch, sBcl, s_bc, acc);
        #pragma unroll
        for (int mm = 0; mm < 2; mm++) {
            int y = m0 + mm;
            #pragma unroll
            for (int nt = 0; nt < 2; nt++) {
                int co = nt*8 + q*2;
                #pragma unroll
                for (int rr = 0; rr < 4; rr++) {
                    int c = co + (rr & 1);
                    int x = g + (rr >= 2 ? 8 : 0);
                    float cand = tanhf(acc[mm][nt][rr]);
                    float z = s_z[c*256 + y*16 + x];
                    int idx = ((b*CC + c)*128 + p16 + y)*128 + q16 + x;
                    float h = X[idx];
                    Xn[idx] = (1.f - z)*h + z*cand;
                }
            }
        }
    }
}

#define SMEM_GRU ((10368 + 9216*2 + 4608*2 + 4096 + 32 + 16)*4)

// ---------------- launch ------------------------------------------------------
extern "C" void kernel_launch(void* const* d_in, const int* in_sizes, int n_in,
                              void* d_out, int out_size)
{
    const float* seed = (const float*)d_in[0];
    const int*   eidx = (const int*)  d_in[1];
    const float* wq = (const float*)d_in[2];
    const float* bq = (const float*)d_in[3];
    const float* wk = (const float*)d_in[4];
    const float* bk = (const float*)d_in[5];
    const float* wm = (const float*)d_in[6];
    const float* bm = (const float*)d_in[7];
    const float* w1 = (const float*)d_in[8];
    const float* b1 = (const float*)d_in[9];
    const float* w2 = (const float*)d_in[10];
    const float* b2 = (const float*)d_in[11];
    const float* wo = (const float*)d_in[12];
    const float* bo = (const float*)d_in[13];
    const float* gw = (const float*)d_in[14];
    const float* gb = (const float*)d_in[15];
    const float* wg = (const float*)d_in[16];
    const float* bg = (const float*)d_in[17];
    const float* wc = (const float*)d_in[18];
    const float* bc = (const float*)d_in[19];
    float* out = (float*)d_out;

    int B = in_sizes[0] / (CC*128*128);
    int E = in_sizes[1] / 2;

    void *pXa,*pXb,*pM,*pAg,*pAB,*pev,*pT9,*poff,*ple,*plj;
    cudaGetSymbolAddress(&pXa, g_Xa);  cudaGetSymbolAddress(&pXb, g_Xb);
    cudaGetSymbolAddress(&pM,  g_M);   cudaGetSymbolAddress(&pAg, g_Ag);
    cudaGetSymbolAddress(&pAB, g_AB);  cudaGetSymbolAddress(&pev, g_ev);
    cudaGetSymbolAddress(&pT9, g_T9);  cudaGetSymbolAddress(&poff,g_off);
    cudaGetSymbolAddress(&ple, g_le);  cudaGetSymbolAddress(&plj, g_lj);

    cudaFuncSetAttribute(k_gru, cudaFuncAttributeMaxDynamicSharedMemorySize, SMEM_GRU);

    k_T9 <<<1, 160>>>(gw, (float*)pT9);
    k_csr<<<1, 256>>>(eidx, E, (int*)poff, (int*)ple, (int*)plj);

    const float* Xc = seed;
    for (int it = 0; it < 4; it++) {
        float* Xn = (it == 3) ? out : ((it & 1) ? (float*)pXb : (float*)pXa);

        k_meanqk <<<B*NN, 256>>>(Xc, wq, bq, wk, bk, w1, (float*)pAB);
        k_edgemlp<<<E, 256>>>(eidx, (const float*)pAB, b1, w2, b2, wo, bo,
                              (float*)pev, E, B);
        k_convM  <<<B*NN, 256>>>(Xc, wm, bm, (float*)pM);
        k_agg    <<<B*NN, 256>>>((const float*)pM, (const float*)pev,
                                 (const float*)pT9, gb,
                                 (const int*)poff, (const int*)ple, (const int*)plj,
                                 (float*)pAg, E);
        k_gru    <<<B*NN, 256, SMEM_GRU>>>((const float*)pAg, Xc, wg, bg, wc, bc, Xn);
        Xc = Xn;
    }
}

// round 4
// speedup vs baseline: 2.0245x; 1.4021x over previous
#include <cuda_runtime.h>

typedef unsigned int uint;

// Problem constants (fixed by the dataset)
#define CC     16
#define NN     64
#define DQK    32
#define HIDN   64
#define MAXE   512
#define BMAX   16
#define PLANE  16384

// ---------------- scratch ----------------------------------------------------
__device__ float g_Xa [BMAX*CC*PLANE];
__device__ float g_Xb [BMAX*CC*PLANE];
__device__ float g_M  [BMAX*CC*PLANE];
__device__ float g_Ag [BMAX*CC*PLANE];
__device__ float g_AB [BMAX*NN*128];
__device__ float g_ev [BMAX*MAXE];
__device__ float g_T9 [CC*9];
__device__ int   g_off[NN+1];
__device__ int   g_le [MAXE];
__device__ int   g_lj [MAXE];
// pre-split tf32 weight fragment tables: [(ks*N + n)*4 + q] -> (b0h,b1h,b0l,b1l)
__device__ float4 g_pBM[18*16*4];
__device__ float4 g_pBg[36*32*4];
__device__ float4 g_pBc[36*16*4];

__device__ __forceinline__ float sigf(float x){ return 1.f/(1.f+__expf(-x)); }

// ---------------- tf32 helpers -----------------------------------------------
__device__ __forceinline__ void tf32split(float x, uint& hi, uint& lo){
    asm("cvt.rna.tf32.f32 %0,%1;" : "=r"(hi) : "f"(x));
    float l = x - __uint_as_float(hi);
    asm("cvt.rna.tf32.f32 %0,%1;" : "=r"(lo) : "f"(l));
}

__device__ __forceinline__ void mma8(float c[4], const uint a[4], uint b0, uint b1){
    asm volatile("mma.sync.aligned.m16n8k8.row.col.f32.tf32.tf32.f32 "
        "{%0,%1,%2,%3},{%4,%5,%6,%7},{%8,%9},{%0,%1,%2,%3};"
        : "+f"(c[0]),"+f"(c[1]),"+f"(c[2]),"+f"(c[3])
        : "r"(a[0]),"r"(a[1]),"r"(a[2]),"r"(a[3]),"r"(b0),"r"(b1));
}

// ---------------- weight prepack (runs once) ----------------------------------
// W layout [n][cin][tap]; K tap-major: k = tap*CIN + cin.
// frag at (ks,n,q): b0 = B[ks*8+q][n], b1 = B[ks*8+q+4][n], each split hi/lo.
__global__ void k_prepB(const float* __restrict__ W, float4* __restrict__ out,
                        int CIN, int N)
{
    int KSTEPS = CIN*9/8;
    int tot = KSTEPS*N*4;
    int i = blockIdx.x*256 + threadIdx.x;
    if (i >= tot) return;
    int q = i & 3; int t = i >> 2; int n = t % N; int ks = t / N;
    int kA = ks*8 + q, kB = kA + 4;
    float wA = W[n*CIN*9 + (kA % CIN)*9 + (kA / CIN)];
    float wB = W[n*CIN*9 + (kB % CIN)*9 + (kB / CIN)];
    uint hA, lA, hB, lB;
    tf32split(wA, hA, lA);
    tf32split(wB, hB, lB);
    out[(ks*N + n)*4 + q] = make_float4(__uint_as_float(hA), __uint_as_float(hB),
                                        __uint_as_float(lA), __uint_as_float(lB));
}

// ---------------- tile loader: split into float2(hi,lo) -----------------------
template<int CIN>
__device__ __forceinline__ void load_tile2(float2* sT,
                                           const float* __restrict__ in0,
                                           const float* __restrict__ in1,
                                           int b, int p16, int q16)
{
    for (int i = threadIdx.x; i < CIN*324; i += 256) {
        int cin = i / 324; int r = i - cin*324;
        int yy = r / 18, xx = r - yy*18;
        int ly = yy - 1, lx = xx - 1;
        float v = 0.f;
        if ((unsigned)ly < 16u && (unsigned)lx < 16u) {
            const float* src = (CIN == 16 || cin < 16) ? in0 : in1;
            int c = (CIN == 16 || cin < 16) ? cin : (cin - 16);
            v = src[((b*CC + c)*128 + p16 + ly)*128 + (q16 + lx)];
        }
        uint hi, lo; tf32split(v, hi, lo);
        sT[i] = make_float2(__uint_as_float(hi), __uint_as_float(lo));
    }
}

// ---------------- 3xTF32 conv GEMM core (pre-split operands) ------------------
// M=256 pixels (mtile m = image row y, row-in-tile = x), K=CIN*9 tap-major.
template<int CIN,int NT>
__device__ __forceinline__ void mma_conv2(const float2* sT,
                                          const float4* __restrict__ pB,
                                          const float* s_bias,
                                          float acc[2][NT][4])
{
    constexpr int N = NT*8;
    constexpr int KSTEPS = CIN*9/8;
    constexpr int KPT = CIN/8;
    int lane = threadIdx.x & 31;
    int wid  = threadIdx.x >> 5;
    int g = lane >> 2, q = lane & 3;
    int m0 = wid*2;

    #pragma unroll
    for (int mm = 0; mm < 2; mm++)
        #pragma unroll
        for (int nt = 0; nt < NT; nt++) {
            float b0 = s_bias[nt*8 + q*2], b1 = s_bias[nt*8 + q*2 + 1];
            acc[mm][nt][0] = b0; acc[mm][nt][1] = b1;
            acc[mm][nt][2] = b0; acc[mm][nt][3] = b1;
        }

    #pragma unroll 1
    for (int ks = 0; ks < KSTEPS; ks++) {
        int tap = ks / KPT;
        int cb  = (ks - tap*KPT)*8 + q;
        int ty = tap/3, tx = tap - ty*3;
        uint ah[2][4], al[2][4];
        #pragma unroll
        for (int mm = 0; mm < 2; mm++) {
            int base = cb*324 + (m0 + mm + ty)*18 + (g + tx);
            float2 e0 = sT[base];
            float2 e1 = sT[base + 8];
            float2 e2 = sT[base + 1296];
            float2 e3 = sT[base + 1304];
            ah[mm][0] = __float_as_uint(e0.x); al[mm][0] = __float_as_uint(e0.y);
            ah[mm][1] = __float_as_uint(e1.x); al[mm][1] = __float_as_uint(e1.y);
            ah[mm][2] = __float_as_uint(e2.x); al[mm][2] = __float_as_uint(e2.y);
            ah[mm][3] = __float_as_uint(e3.x); al[mm][3] = __float_as_uint(e3.y);
        }
        #pragma unroll
        for (int nt = 0; nt < NT; nt++) {
            float4 bv = pB[(ks*N + nt*8 + g)*4 + q];
            uint b0h = __float_as_uint(bv.x), b1h = __float_as_uint(bv.y);
            uint b0l = __float_as_uint(bv.z), b1l = __float_as_uint(bv.w);
            #pragma unroll
            for (int mm = 0; mm < 2; mm++) {
                mma8(acc[mm][nt], ah[mm], b0h, b1h);
                mma8(acc[mm][nt], ah[mm], b0l, b1l);
                mma8(acc[mm][nt], al[mm], b0h, b1h);
            }
        }
    }
}

// ---------------- kernels ----------------------------------------------------
// mean + q/k projections + MLP layer-1 per-node partials
__global__ __launch_bounds__(256) void k_meanqk(const float* __restrict__ X,
    const float* __restrict__ wq, const float* __restrict__ bq,
    const float* __restrict__ wk, const float* __restrict__ bk,
    const float* __restrict__ W1, float* __restrict__ AB)
{
    int bn = blockIdx.x; int b = bn >> 6, n = bn & 63;
    int p16 = (n >> 3)*16, q16 = (n & 7)*16;
    __shared__ float s_xm[CC];
    __shared__ float s_qk[64];
    int tid = threadIdx.x, w = tid >> 5, lane = tid & 31;
    for (int c = w*2; c < w*2 + 2; c++) {
        float s = 0.f;
        for (int i = lane; i < 256; i += 32) {
            int y = i >> 4, x = i & 15;
            s += X[((b*CC + c)*128 + p16 + y)*128 + q16 + x];
        }
        #pragma unroll
        for (int o = 16; o; o >>= 1) s += __shfl_down_sync(0xffffffffu, s, o);
        if (!lane) s_xm[c] = s * (1.f/256.f);
    }
    __syncthreads();
    if (tid < 64) {
        int d = tid & 31;
        const float* wM = (tid < 32) ? wq : wk;
        const float* bM = (tid < 32) ? bq : bk;
        float a = bM[d];
        #pragma unroll
        for (int c = 0; c < CC; c++) a += s_xm[c]*wM[c*DQK + d];
        s_qk[tid] = a;
    }
    __syncthreads();
    if (tid < 128) {
        int t = tid & 63;
        int off = (tid < 64) ? 0 : 32;
        float a = 0.f;
        #pragma unroll
        for (int d = 0; d < 32; d++) a += s_qk[off + d]*W1[(off + d)*HIDN + t];
        AB[(b*NN + n)*128 + (tid < 64 ? 0 : 64) + t] = a;
    }
}

// edge MLP: one block per edge, 4 batches in parallel
__global__ __launch_bounds__(256) void k_edgemlp(const int* __restrict__ eidx,
    const float* __restrict__ AB, const float* __restrict__ b1,
    const float* __restrict__ W2, const float* __restrict__ b2,
    const float* __restrict__ wo, const float* __restrict__ bo,
    float* __restrict__ ev, int E, int B)
{
    __shared__ float sW2[HIDN*HIDN];
    __shared__ float sb1[HIDN], sb2[HIDN], swo[HIDN];
    __shared__ float h1s[4][HIDN], sred[4][2];
    int e = blockIdx.x, tid = threadIdx.x;
    int bg = tid >> 6, t = tid & 63;
    int ei = eidx[2*e], ej = eidx[2*e + 1];
    for (int i = tid; i < HIDN*HIDN; i += 256) sW2[i] = W2[i];
    if (tid < HIDN) { sb1[tid] = b1[tid]; sb2[tid] = b2[tid]; swo[tid] = wo[tid]; }
    float bov = bo[0];
    __syncthreads();
    for (int b = bg; b < B; b += 4) {
        float h1 = AB[(b*NN + ei)*128 + t] + AB[(b*NN + ej)*128 + 64 + t] + sb1[t];
        h1s[bg][t] = fmaxf(h1, 0.f);
        __syncthreads();
        float a2 = sb2[t];
        #pragma unroll
        for (int i = 0; i < HIDN; i++) a2 += h1s[bg][i]*sW2[i*HIDN + t];
        a2 = fmaxf(a2, 0.f);
        float part = a2*swo[t];
        #pragma unroll
        for (int o = 16; o; o >>= 1) part += __shfl_down_sync(0xffffffffu, part, o);
        if ((t & 31) == 0) sred[bg][t >> 5] = part;
        __syncthreads();
        if (t == 0) ev[b*E + e] = sred[bg][0] + sred[bg][1] + bov;
    }
}

// message conv M = conv(X, wm) + bm via 3xTF32 MMA (pre-split operands)
__global__ __launch_bounds__(256) void k_convM(const float* __restrict__ X,
    const float4* __restrict__ pB, const float* __restrict__ bias,
    float* __restrict__ M)
{
    int bn = blockIdx.x; int b = bn >> 6, n = bn & 63;
    int p16 = (n >> 3)*16, q16 = (n & 7)*16;
    __shared__ float2 sT[16*324];
    __shared__ float s_bias[16];
    load_tile2<16>(sT, X, nullptr, b, p16, q16);
    if (threadIdx.x < 16) s_bias[threadIdx.x] = bias[threadIdx.x];
    __syncthreads();

    float acc[2][2][4];
    mma_conv2<16,2>(sT, pB, s_bias, acc);

    int lane = threadIdx.x & 31, wid = threadIdx.x >> 5;
    int g = lane >> 2, q = lane & 3, m0 = wid*2;
    #pragma unroll
    for (int mm = 0; mm < 2; mm++) {
        int y = m0 + mm;
        #pragma unroll
        for (int nt = 0; nt < 2; nt++) {
            int co = nt*8 + q*2;
            int r0 = ((b*CC + co)*128 + p16 + y)*128 + q16;
            int r1 = r0 + PLANE;
            M[r0 + g]     = acc[mm][nt][0];
            M[r1 + g]     = acc[mm][nt][1];
            M[r0 + g + 8] = acc[mm][nt][2];
            M[r1 + g + 8] = acc[mm][nt][3];
        }
    }
}

// T 9-class table
__global__ void k_T9(const float* __restrict__ gw, float* __restrict__ T9)
{
    int tid = threadIdx.x; if (tid >= CC*9) return;
    int c = tid / 9, cls = tid - c*9, ry = cls/3, rx = cls - ry*3;
    float s = 0.f;
    #pragma unroll
    for (int ky = 0; ky < 3; ky++) {
        if ((ry == 0 && ky == 0) || (ry == 2 && ky == 2)) continue;
        #pragma unroll
        for (int kx = 0; kx < 3; kx++) {
            if ((rx == 0 && kx == 0) || (rx == 2 && kx == 2)) continue;
            s += gw[c*9 + ky*3 + kx];
        }
    }
    T9[tid] = s;
}

// deterministic CSR build
__global__ void k_csr(const int* __restrict__ eidx, int E,
                      int* __restrict__ off, int* __restrict__ le, int* __restrict__ lj)
{
    __shared__ int se[MAXE*2];
    for (int i = threadIdx.x; i < 2*E; i += blockDim.x) se[i] = eidx[i];
    __syncthreads();
    if (threadIdx.x == 0) {
        int cnt[NN];
        for (int i = 0; i < NN; i++) cnt[i] = 0;
        for (int e = 0; e < E; e++) cnt[se[2*e]]++;
        int acc = 0;
        for (int i = 0; i < NN; i++) { off[i] = acc; acc += cnt[i]; cnt[i] = 0; }
        off[NN] = acc;
        for (int e = 0; e < E; e++) {
            int i = se[2*e];
            int s = off[i] + cnt[i]++;
            le[s] = e; lj[s] = se[2*e + 1];
        }
    }
}

// segment-sum of gated messages (gate table fused, float4)
__global__ __launch_bounds__(256) void k_agg(const float* __restrict__ M,
    const float* __restrict__ ev, const float* __restrict__ T9,
    const float* __restrict__ gb,
    const int* __restrict__ off, const int* __restrict__ le,
    const int* __restrict__ lj,
    float* __restrict__ agg, int E)
{
    int bn = blockIdx.x; int b = bn >> 6, i = bn & 63;
    int p16 = (i >> 3)*16, q16 = (i & 7)*16;
    int o0 = off[i], deg = off[i+1] - o0;
    __shared__ float sg[8*144];
    __shared__ float sT9[144], sgb[CC], sev[8];
    __shared__ int sbase[8];
    int tid = threadIdx.x;
    if (tid < 144) sT9[tid] = T9[tid];
    if (tid < CC)  sgb[tid] = gb[tid];
    if (tid < deg) {
        int e = le[o0 + tid];
        sev[tid] = ev[b*E + e];
        int ej = lj[o0 + tid];
        sbase[tid] = ((b*CC)*128 + (ej >> 3)*16)*128 + (ej & 7)*16;
    }
    __syncthreads();
    for (int t = tid; t < deg*144; t += 256) {
        int l = t / 144, r = t - l*144;
        int c = r / 9, cls = r - c*9;
        sg[t] = sigf(sev[l]*sT9[c*9 + cls] + sgb[c]);
    }
    __syncthreads();
    int cg = tid >> 6, pg = tid & 63;
    int y = pg >> 2, x0 = (pg & 3)*4;
    int cy = (y == 0) ? 0 : ((y == 15) ? 2 : 1);
    int cix[4];
    #pragma unroll
    for (int k = 0; k < 4; k++) {
        int x = x0 + k;
        cix[k] = cy*3 + ((x == 0) ? 0 : ((x == 15) ? 2 : 1));
    }
    int pix = y*128 + x0;
    #pragma unroll
    for (int cc = 0; cc < 4; cc++) {
        int c = cg*4 + cc;
        float4 a = make_float4(0.f, 0.f, 0.f, 0.f);
        for (int l = 0; l < deg; l++) {
            const float* gl = &sg[l*144 + c*9];
            float4 m = *reinterpret_cast<const float4*>(&M[sbase[l] + c*PLANE + pix]);
            a.x += gl[cix[0]]*m.x;
            a.y += gl[cix[1]]*m.y;
            a.z += gl[cix[2]]*m.z;
            a.w += gl[cix[3]]*m.w;
        }
        int obase = ((b*CC + c)*128 + p16 + y)*128 + q16 + x0;
        *reinterpret_cast<float4*>(&agg[obase]) = a;
    }
}

// fused GRU: gate conv -> z (regs), rh (smem tile); candidate conv -> update
__global__ __launch_bounds__(256,2) void k_gru(const float* __restrict__ agg,
    const float* __restrict__ X,
    const float4* __restrict__ pBg, const float* __restrict__ bgv,
    const float4* __restrict__ pBc, const float* __restrict__ bcv,
    float* __restrict__ Xn)
{
    int bn = blockIdx.x; int b = bn >> 6, n = bn & 63;
    int p16 = (n >> 3)*16, q16 = (n & 7)*16;
    extern __shared__ float2 sT[];          // 32*324 float2 = 82,944 B
    __shared__ float s_bg[32], s_bc[16];

    load_tile2<32>(sT, agg, X, b, p16, q16);
    if (threadIdx.x < 32) s_bg[threadIdx.x] = bgv[threadIdx.x];
    if (threadIdx.x < 16) s_bc[threadIdx.x] = bcv[threadIdx.x];
    __syncthreads();

    int lane = threadIdx.x & 31, wid = threadIdx.x >> 5;
    int g = lane >> 2, q = lane & 3, m0 = wid*2;

    float zreg[2][2][4];
    float hreg[2][2][4];

    // ---- gate conv ----
    {
        float acc[2][4][4];
        mma_conv2<32,4>(sT, pBg, s_bg, acc);
        __syncthreads();   // all tile reads complete before rh overwrite
        #pragma unroll
        for (int mm = 0; mm < 2; mm++) {
            int y = m0 + mm;
            #pragma unroll
            for (int nt = 0; nt < 4; nt++) {
                int co = nt*8 + q*2;
                #pragma unroll
                for (int rr = 0; rr < 4; rr++) {
                    int c = co + (rr & 1);
                    int x = g + (rr >= 2 ? 8 : 0);
                    float v = sigf(acc[mm][nt][rr]);
                    if (nt < 2) {
                        zreg[mm][nt][rr] = v;
                    } else {
                        // c in 16..31: read h, save it, write rh (hi/lo) in place
                        int ti = c*324 + (y + 1)*18 + (x + 1);
                        float2 e = sT[ti];
                        float h = e.x + e.y;
                        hreg[mm][nt - 2][rr] = h;
                        float rh = v*h;
                        uint hi, lo; tf32split(rh, hi, lo);
                        sT[ti] = make_float2(__uint_as_float(hi), __uint_as_float(lo));
                    }
                }
            }
        }
    }
    __syncthreads();

    // ---- candidate conv + update ----
    {
        float acc[2][2][4];
        mma_conv2<32,2>(sT, pBc, s_bc, acc);
        #pragma unroll
        for (int mm = 0; mm < 2; mm++) {
            int y = m0 + mm;
            #pragma unroll
            for (int nt = 0; nt < 2; nt++) {
                int co = nt*8 + q*2;
                #pragma unroll
                for (int rr = 0; rr < 4; rr++) {
                    int c = co + (rr & 1);
                    int x = g + (rr >= 2 ? 8 : 0);
                    float cand = tanhf(acc[mm][nt][rr]);
                    float z = zreg[mm][nt][rr];
                    float h = hreg[mm][nt][rr];
                    int idx = ((b*CC + c)*128 + p16 + y)*128 + q16 + x;
                    Xn[idx] = (1.f - z)*h + z*cand;
                }
            }
        }
    }
}

#define SMEM_GRU (32*324*8)

// ---------------- launch ------------------------------------------------------
extern "C" void kernel_launch(void* const* d_in, const int* in_sizes, int n_in,
                              void* d_out, int out_size)
{
    const float* seed = (const float*)d_in[0];
    const int*   eidx = (const int*)  d_in[1];
    const float* wq = (const float*)d_in[2];
    const float* bq = (const float*)d_in[3];
    const float* wk = (const float*)d_in[4];
    const float* bk = (const float*)d_in[5];
    const float* wm = (const float*)d_in[6];
    const float* bm = (const float*)d_in[7];
    const float* w1 = (const float*)d_in[8];
    const float* b1 = (const float*)d_in[9];
    const float* w2 = (const float*)d_in[10];
    const float* b2 = (const float*)d_in[11];
    const float* wo = (const float*)d_in[12];
    const float* bo = (const float*)d_in[13];
    const float* gw = (const float*)d_in[14];
    const float* gb = (const float*)d_in[15];
    const float* wg = (const float*)d_in[16];
    const float* bg = (const float*)d_in[17];
    const float* wc = (const float*)d_in[18];
    const float* bc = (const float*)d_in[19];
    float* out = (float*)d_out;

    int B = in_sizes[0] / (CC*128*128);
    int E = in_sizes[1] / 2;

    void *pXa,*pXb,*pM,*pAg,*pAB,*pev,*pT9,*poff,*ple,*plj,*pBM,*pBg,*pBc;
    cudaGetSymbolAddress(&pXa, g_Xa);  cudaGetSymbolAddress(&pXb, g_Xb);
    cudaGetSymbolAddress(&pM,  g_M);   cudaGetSymbolAddress(&pAg, g_Ag);
    cudaGetSymbolAddress(&pAB, g_AB);  cudaGetSymbolAddress(&pev, g_ev);
    cudaGetSymbolAddress(&pT9, g_T9);  cudaGetSymbolAddress(&poff,g_off);
    cudaGetSymbolAddress(&ple, g_le);  cudaGetSymbolAddress(&plj, g_lj);
    cudaGetSymbolAddress(&pBM, g_pBM); cudaGetSymbolAddress(&pBg, g_pBg);
    cudaGetSymbolAddress(&pBc, g_pBc);

    cudaFuncSetAttribute(k_gru, cudaFuncAttributeMaxDynamicSharedMemorySize, SMEM_GRU);

    k_T9  <<<1, 160>>>(gw, (float*)pT9);
    k_csr <<<1, 256>>>(eidx, E, (int*)poff, (int*)ple, (int*)plj);
    k_prepB<<<(18*16*4 + 255)/256, 256>>>(wm, (float4*)pBM, 16, 16);
    k_prepB<<<(36*32*4 + 255)/256, 256>>>(wg, (float4*)pBg, 32, 32);
    k_prepB<<<(36*16*4 + 255)/256, 256>>>(wc, (float4*)pBc, 32, 16);

    const float* Xc = seed;
    for (int it = 0; it < 4; it++) {
        float* Xn = (it == 3) ? out : ((it & 1) ? (float*)pXb : (float*)pXa);

        k_meanqk <<<B*NN, 256>>>(Xc, wq, bq, wk, bk, w1, (float*)pAB);
        k_edgemlp<<<E, 256>>>(eidx, (const float*)pAB, b1, w2, b2, wo, bo,
                              (float*)pev, E, B);
        k_convM  <<<B*NN, 256>>>(Xc, (const float4*)pBM, bm, (float*)pM);
        k_agg    <<<B*NN, 256>>>((const float*)pM, (const float*)pev,
                                 (const float*)pT9, gb,
                                 (const int*)poff, (const int*)ple, (const int*)plj,
                                 (float*)pAg, E);
        k_gru    <<<B*NN, 256, SMEM_GRU>>>((const float*)pAg, Xc,
                                           (const float4*)pBg, bg,
                                           (const float4*)pBc, bc, Xn);
        Xc = Xn;
    }
}

// round 5
// speedup vs baseline: 2.0776x; 1.0262x over previous
#include <cuda_runtime.h>

typedef unsigned int uint;

// Problem constants (fixed by the dataset)
#define CC     16
#define NN     64
#define DQK    32
#define HIDN   64
#define MAXE   512
#define BMAX   16
#define PLANE  16384

// ---------------- scratch ----------------------------------------------------
__device__ float g_Xa [BMAX*CC*PLANE];
__device__ float g_Xb [BMAX*CC*PLANE];
__device__ float g_M  [BMAX*CC*PLANE];
__device__ float g_AB [BMAX*NN*128];
__device__ float g_T9 [CC*9];
__device__ int   g_off[NN+1];
__device__ int   g_lj [MAXE];
// pre-split tf32 weight fragment tables: [(ks*N + n)*4 + q] -> (b0h,b1h,b0l,b1l)
__device__ float4 g_pBM[18*16*4];
__device__ float4 g_pBg[36*32*4];
__device__ float4 g_pBc[36*16*4];

__device__ __forceinline__ float sigf(float x){ return 1.f/(1.f+__expf(-x)); }

// ---------------- tf32 helpers -----------------------------------------------
__device__ __forceinline__ void tf32split(float x, uint& hi, uint& lo){
    asm("cvt.rna.tf32.f32 %0,%1;" : "=r"(hi) : "f"(x));
    float l = x - __uint_as_float(hi);
    asm("cvt.rna.tf32.f32 %0,%1;" : "=r"(lo) : "f"(l));
}

__device__ __forceinline__ void mma8(float c[4], const uint a[4], uint b0, uint b1){
    asm volatile("mma.sync.aligned.m16n8k8.row.col.f32.tf32.tf32.f32 "
        "{%0,%1,%2,%3},{%4,%5,%6,%7},{%8,%9},{%0,%1,%2,%3};"
        : "+f"(c[0]),"+f"(c[1]),"+f"(c[2]),"+f"(c[3])
        : "r"(a[0]),"r"(a[1]),"r"(a[2]),"r"(a[3]),"r"(b0),"r"(b1));
}

// ---------------- weight prepack (runs once) ----------------------------------
__global__ void k_prepB(const float* __restrict__ W, float4* __restrict__ out,
                        int CIN, int N)
{
    int KSTEPS = CIN*9/8;
    int tot = KSTEPS*N*4;
    int i = blockIdx.x*256 + threadIdx.x;
    if (i >= tot) return;
    int q = i & 3; int t = i >> 2; int n = t % N; int ks = t / N;
    int kA = ks*8 + q, kB = kA + 4;
    float wA = W[n*CIN*9 + (kA % CIN)*9 + (kA / CIN)];
    float wB = W[n*CIN*9 + (kB % CIN)*9 + (kB / CIN)];
    uint hA, lA, hB, lB;
    tf32split(wA, hA, lA);
    tf32split(wB, hB, lB);
    out[(ks*N + n)*4 + q] = make_float4(__uint_as_float(hA), __uint_as_float(hB),
                                        __uint_as_float(lA), __uint_as_float(lB));
}

// ---------------- tile loader: channels [c0,c1) of src into split tile --------
__device__ __forceinline__ void load_tile_rng(float2* sT,
                                              const float* __restrict__ src,
                                              int c0, int c1,
                                              int b, int p16, int q16)
{
    int nel = (c1 - c0)*324;
    for (int i = threadIdx.x; i < nel; i += 256) {
        int cin = i / 324; int r = i - cin*324;
        int yy = r / 18, xx = r - yy*18;
        int ly = yy - 1, lx = xx - 1;
        float v = 0.f;
        if ((unsigned)ly < 16u && (unsigned)lx < 16u)
            v = src[((b*CC + cin)*128 + p16 + ly)*128 + (q16 + lx)];
        uint hi, lo; tf32split(v, hi, lo);
        sT[(c0 + cin)*324 + r] = make_float2(__uint_as_float(hi), __uint_as_float(lo));
    }
}

// ---------------- 3xTF32 conv GEMM core (pre-split operands) ------------------
template<int CIN,int NT>
__device__ __forceinline__ void mma_conv2(const float2* sT,
                                          const float4* __restrict__ pB,
                                          const float* s_bias,
                                          float acc[2][NT][4])
{
    constexpr int N = NT*8;
    constexpr int KSTEPS = CIN*9/8;
    constexpr int KPT = CIN/8;
    int lane = threadIdx.x & 31;
    int wid  = threadIdx.x >> 5;
    int g = lane >> 2, q = lane & 3;
    int m0 = wid*2;

    #pragma unroll
    for (int mm = 0; mm < 2; mm++)
        #pragma unroll
        for (int nt = 0; nt < NT; nt++) {
            float b0 = s_bias[nt*8 + q*2], b1 = s_bias[nt*8 + q*2 + 1];
            acc[mm][nt][0] = b0; acc[mm][nt][1] = b1;
            acc[mm][nt][2] = b0; acc[mm][nt][3] = b1;
        }

    #pragma unroll 1
    for (int ks = 0; ks < KSTEPS; ks++) {
        int tap = ks / KPT;
        int cb  = (ks - tap*KPT)*8 + q;
        int ty = tap/3, tx = tap - ty*3;
        uint ah[2][4], al[2][4];
        #pragma unroll
        for (int mm = 0; mm < 2; mm++) {
            int base = cb*324 + (m0 + mm + ty)*18 + (g + tx);
            float2 e0 = sT[base];
            float2 e1 = sT[base + 8];
            float2 e2 = sT[base + 1296];
            float2 e3 = sT[base + 1304];
            ah[mm][0] = __float_as_uint(e0.x); al[mm][0] = __float_as_uint(e0.y);
            ah[mm][1] = __float_as_uint(e1.x); al[mm][1] = __float_as_uint(e1.y);
            ah[mm][2] = __float_as_uint(e2.x); al[mm][2] = __float_as_uint(e2.y);
            ah[mm][3] = __float_as_uint(e3.x); al[mm][3] = __float_as_uint(e3.y);
        }
        #pragma unroll
        for (int nt = 0; nt < NT; nt++) {
            float4 bv = pB[(ks*N + nt*8 + g)*4 + q];
            uint b0h = __float_as_uint(bv.x), b1h = __float_as_uint(bv.y);
            uint b0l = __float_as_uint(bv.z), b1l = __float_as_uint(bv.w);
            #pragma unroll
            for (int mm = 0; mm < 2; mm++) {
                mma8(acc[mm][nt], ah[mm], b0h, b1h);
                mma8(acc[mm][nt], ah[mm], b0l, b1l);
                mma8(acc[mm][nt], al[mm], b0h, b1h);
            }
        }
    }
}

// ---------------- setup kernels ----------------------------------------------
__global__ void k_T9(const float* __restrict__ gw, float* __restrict__ T9)
{
    int tid = threadIdx.x; if (tid >= CC*9) return;
    int c = tid / 9, cls = tid - c*9, ry = cls/3, rx = cls - ry*3;
    float s = 0.f;
    #pragma unroll
    for (int ky = 0; ky < 3; ky++) {
        if ((ry == 0 && ky == 0) || (ry == 2 && ky == 2)) continue;
        #pragma unroll
        for (int kx = 0; kx < 3; kx++) {
            if ((rx == 0 && kx == 0) || (rx == 2 && kx == 2)) continue;
            s += gw[c*9 + ky*3 + kx];
        }
    }
    T9[tid] = s;
}

__global__ void k_csr(const int* __restrict__ eidx, int E,
                      int* __restrict__ off, int* __restrict__ lj)
{
    __shared__ int se[MAXE*2];
    for (int i = threadIdx.x; i < 2*E; i += blockDim.x) se[i] = eidx[i];
    __syncthreads();
    if (threadIdx.x == 0) {
        int cnt[NN];
        for (int i = 0; i < NN; i++) cnt[i] = 0;
        for (int e = 0; e < E; e++) cnt[se[2*e]]++;
        int acc = 0;
        for (int i = 0; i < NN; i++) { off[i] = acc; acc += cnt[i]; cnt[i] = 0; }
        off[NN] = acc;
        for (int e = 0; e < E; e++) {
            int i = se[2*e];
            int s = off[i] + cnt[i]++;
            lj[s] = se[2*e + 1];
        }
    }
}

// ---------------- fused conv + mean/qk/AB kernel -------------------------------
__global__ __launch_bounds__(256) void k_convQ(const float* __restrict__ X,
    const float4* __restrict__ pBM, const float* __restrict__ bm,
    const float* __restrict__ wq, const float* __restrict__ bq,
    const float* __restrict__ wk, const float* __restrict__ bk,
    const float* __restrict__ W1,
    float* __restrict__ M, float* __restrict__ AB)
{
    int bn = blockIdx.x; int b = bn >> 6, n = bn & 63;
    int p16 = (n >> 3)*16, q16 = (n & 7)*16;
    __shared__ float2 sT[16*324];
    __shared__ float s_bias[16];
    __shared__ float s_red[16][8];
    __shared__ float s_xm[16];
    __shared__ float s_qk[64];
    load_tile_rng(sT, X, 0, 16, b, p16, q16);
    if (threadIdx.x < 16) s_bias[threadIdx.x] = bm[threadIdx.x];
    __syncthreads();

    int tid = threadIdx.x;
    // per-channel patch mean (hi+lo reconstruction; error ~2^-22)
    {
        int y = tid >> 4, x = tid & 15;
        int w = tid >> 5;
        #pragma unroll 1
        for (int c = 0; c < 16; c++) {
            float2 e = sT[c*324 + (y + 1)*18 + (x + 1)];
            float v = e.x + e.y;
            #pragma unroll
            for (int o = 16; o; o >>= 1) v += __shfl_down_sync(0xffffffffu, v, o);
            if ((tid & 31) == 0) s_red[c][w] = v;
        }
    }

    // conv via MMA (no sync needed yet; uses sT only)
    float acc[2][2][4];
    mma_conv2<16,2>(sT, pBM, s_bias, acc);

    int lane = tid & 31, wid = tid >> 5;
    int g = lane >> 2, q = lane & 3, m0 = wid*2;
    #pragma unroll
    for (int mm = 0; mm < 2; mm++) {
        int y = m0 + mm;
        #pragma unroll
        for (int nt = 0; nt < 2; nt++) {
            int co = nt*8 + q*2;
            int r0 = ((b*CC + co)*128 + p16 + y)*128 + q16;
            int r1 = r0 + PLANE;
            M[r0 + g]     = acc[mm][nt][0];
            M[r1 + g]     = acc[mm][nt][1];
            M[r0 + g + 8] = acc[mm][nt][2];
            M[r1 + g + 8] = acc[mm][nt][3];
        }
    }
    __syncthreads();
    if (tid < 16) {
        float s = 0.f;
        #pragma unroll
        for (int w = 0; w < 8; w++) s += s_red[tid][w];
        s_xm[tid] = s * (1.f/256.f);
    }
    __syncthreads();
    if (tid < 64) {
        int d = tid & 31;
        const float* wM = (tid < 32) ? wq : wk;
        const float* bM = (tid < 32) ? bq : bk;
        float a = bM[d];
        #pragma unroll
        for (int c = 0; c < CC; c++) a += s_xm[c]*wM[c*DQK + d];
        s_qk[tid] = a;
    }
    __syncthreads();
    if (tid < 128) {
        int t = tid & 63;
        int off = (tid < 64) ? 0 : 32;
        float a = 0.f;
        #pragma unroll
        for (int d = 0; d < 32; d++) a += s_qk[off + d]*W1[(off + d)*HIDN + t];
        AB[(b*NN + n)*128 + (tid < 64 ? 0 : 64) + t] = a;
    }
}

// ---------------- fused edgeMLP + gate + agg + GRU kernel ----------------------
__global__ __launch_bounds__(256,2) void k_aggGru(const float* __restrict__ M,
    const float* __restrict__ X, const float* __restrict__ AB,
    const float* __restrict__ T9, const float* __restrict__ gbv,
    const float* __restrict__ b1, const float* __restrict__ W2,
    const float* __restrict__ b2, const float* __restrict__ wo,
    const float* __restrict__ bo,
    const float4* __restrict__ pBg, const float* __restrict__ bgv,
    const float4* __restrict__ pBc, const float* __restrict__ bcv,
    const int* __restrict__ off, const int* __restrict__ lj,
    float* __restrict__ Xn)
{
    int bn = blockIdx.x; int b = bn >> 6, i = bn & 63;
    int p16 = (i >> 3)*16, q16 = (i & 7)*16;
    extern __shared__ float2 sT[];              // 32*324 float2 = 82,944 B
    __shared__ float sW2[HIDN*HIDN];            // 16 KB
    __shared__ float sg[4*144];
    __shared__ float sT9[144];
    __shared__ float sgb[16], s_bg[32], s_bc[16];
    __shared__ float sb1[64], sb2[64], swo[64];
    __shared__ float h1s[4][64], sred[4][2], sev[4];
    __shared__ int sbase[4];

    int tid = threadIdx.x;
    int o0 = off[i], deg = off[i+1] - o0;

    // zero agg channels (incl. halo); load X into channels 16..31
    for (int t = tid; t < 16*324; t += 256) sT[t] = make_float2(0.f, 0.f);
    load_tile_rng(sT, X, 16, 32, b, p16, q16);

    for (int t = tid; t < HIDN*HIDN; t += 256) sW2[t] = W2[t];
    if (tid < 144) sT9[tid] = T9[tid];
    if (tid < 16)  sgb[tid] = gbv[tid];
    if (tid < 32)  s_bg[tid] = bgv[tid];
    if (tid < 16)  s_bc[tid] = bcv[tid];
    if (tid < 64)  { sb1[tid] = b1[tid]; sb2[tid] = b2[tid]; swo[tid] = wo[tid]; }
    if (tid < deg) {
        int ej = lj[o0 + tid];
        sbase[tid] = ((b*CC)*128 + (ej >> 3)*16)*128 + (ej & 7)*16;
    }
    float bov = bo[0];
    __syncthreads();

    // ---- edge MLP for this node's incident edges (<=4) ----
    int l = tid >> 6, t = tid & 63;
    if (l < deg) {
        int ej = lj[o0 + l];
        float a = AB[(b*NN + i)*128 + t] + AB[(b*NN + ej)*128 + 64 + t] + sb1[t];
        h1s[l][t] = fmaxf(a, 0.f);
    }
    __syncthreads();
    if (l < deg) {
        float a2 = sb2[t];
        #pragma unroll
        for (int k = 0; k < HIDN; k++) a2 += h1s[l][k]*sW2[k*HIDN + t];
        a2 = fmaxf(a2, 0.f);
        float part = a2*swo[t];
        #pragma unroll
        for (int o = 16; o; o >>= 1) part += __shfl_down_sync(0xffffffffu, part, o);
        if ((t & 31) == 0) sred[l][t >> 5] = part;
    }
    __syncthreads();
    if (tid < deg) sev[tid] = sred[tid][0] + sred[tid][1] + bov;
    __syncthreads();

    // ---- gate table ----
    for (int t2 = tid; t2 < deg*144; t2 += 256) {
        int le = t2 / 144, r = t2 - le*144;
        int c = r / 9;
        sg[t2] = sigf(sev[le]*sT9[r] + sgb[c]);
    }
    __syncthreads();

    // ---- segment-sum of gated messages, write split into sT ch 0..15 ----
    {
        int cg = tid >> 6, pg = tid & 63;
        int y = pg >> 2, x0 = (pg & 3)*4;
        int cy = (y == 0) ? 0 : ((y == 15) ? 2 : 1);
        int cix[4];
        #pragma unroll
        for (int k = 0; k < 4; k++) {
            int x = x0 + k;
            cix[k] = cy*3 + ((x == 0) ? 0 : ((x == 15) ? 2 : 1));
        }
        int pix = y*128 + x0;
        #pragma unroll
        for (int cc = 0; cc < 4; cc++) {
            int c = cg*4 + cc;
            float av[4] = {0.f, 0.f, 0.f, 0.f};
            for (int le = 0; le < deg; le++) {
                const float* gl = &sg[le*144 + c*9];
                float4 m = *reinterpret_cast<const float4*>(&M[sbase[le] + c*PLANE + pix]);
                av[0] += gl[cix[0]]*m.x;
                av[1] += gl[cix[1]]*m.y;
                av[2] += gl[cix[2]]*m.z;
                av[3] += gl[cix[3]]*m.w;
            }
            #pragma unroll
            for (int k = 0; k < 4; k++) {
                uint hi, lo; tf32split(av[k], hi, lo);
                sT[c*324 + (y + 1)*18 + (x0 + 1 + k)] =
                    make_float2(__uint_as_float(hi), __uint_as_float(lo));
            }
        }
    }
    __syncthreads();

    // ---- GRU ----
    int lane = tid & 31, wid = tid >> 5;
    int g = lane >> 2, q = lane & 3, m0 = wid*2;

    float zreg[2][2][4];
    float hreg[2][2][4];

    {   // gate conv
        float acc[2][4][4];
        mma_conv2<32,4>(sT, pBg, s_bg, acc);
        __syncthreads();   // all tile reads complete before rh overwrite
        #pragma unroll
        for (int mm = 0; mm < 2; mm++) {
            int y = m0 + mm;
            #pragma unroll
            for (int nt = 0; nt < 4; nt++) {
                int co = nt*8 + q*2;
                #pragma unroll
                for (int rr = 0; rr < 4; rr++) {
                    int c = co + (rr & 1);
                    int x = g + (rr >= 2 ? 8 : 0);
                    float v = sigf(acc[mm][nt][rr]);
                    if (nt < 2) {
                        zreg[mm][nt][rr] = v;
                    } else {
                        int ti = c*324 + (y + 1)*18 + (x + 1);
                        float2 e = sT[ti];
                        float h = e.x + e.y;
                        hreg[mm][nt - 2][rr] = h;
                        float rh = v*h;
                        uint hi, lo; tf32split(rh, hi, lo);
                        sT[ti] = make_float2(__uint_as_float(hi), __uint_as_float(lo));
                    }
                }
            }
        }
    }
    __syncthreads();

    {   // candidate conv + update
        float acc[2][2][4];
        mma_conv2<32,2>(sT, pBc, s_bc, acc);
        #pragma unroll
        for (int mm = 0; mm < 2; mm++) {
            int y = m0 + mm;
            #pragma unroll
            for (int nt = 0; nt < 2; nt++) {
                int co = nt*8 + q*2;
                #pragma unroll
                for (int rr = 0; rr < 4; rr++) {
                    int c = co + (rr & 1);
                    int x = g + (rr >= 2 ? 8 : 0);
                    float cand = tanhf(acc[mm][nt][rr]);
                    float z = zreg[mm][nt][rr];
                    float h = hreg[mm][nt][rr];
                    int idx = ((b*CC + c)*128 + p16 + y)*128 + q16 + x;
                    Xn[idx] = (1.f - z)*h + z*cand;
                }
            }
        }
    }
}

#define SMEM_AGGGRU (32*324*8)

// ---------------- launch ------------------------------------------------------
extern "C" void kernel_launch(void* const* d_in, const int* in_sizes, int n_in,
                              void* d_out, int out_size)
{
    const float* seed = (const float*)d_in[0];
    const int*   eidx = (const int*)  d_in[1];
    const float* wq = (const float*)d_in[2];
    const float* bq = (const float*)d_in[3];
    const float* wk = (const float*)d_in[4];
    const float* bk = (const float*)d_in[5];
    const float* wm = (const float*)d_in[6];
    const float* bm = (const float*)d_in[7];
    const float* w1 = (const float*)d_in[8];
    const float* b1 = (const float*)d_in[9];
    const float* w2 = (const float*)d_in[10];
    const float* b2 = (const float*)d_in[11];
    const float* wo = (const float*)d_in[12];
    const float* bo = (const float*)d_in[13];
    const float* gw = (const float*)d_in[14];
    const float* gb = (const float*)d_in[15];
    const float* wg = (const float*)d_in[16];
    const float* bg = (const float*)d_in[17];
    const float* wc = (const float*)d_in[18];
    const float* bc = (const float*)d_in[19];
    float* out = (float*)d_out;

    int B = in_sizes[0] / (CC*128*128);
    int E = in_sizes[1] / 2;

    void *pXa,*pXb,*pM,*pAB,*pT9,*poff,*plj,*pBM,*pBg,*pBc;
    cudaGetSymbolAddress(&pXa, g_Xa);  cudaGetSymbolAddress(&pXb, g_Xb);
    cudaGetSymbolAddress(&pM,  g_M);   cudaGetSymbolAddress(&pAB, g_AB);
    cudaGetSymbolAddress(&pT9, g_T9);  cudaGetSymbolAddress(&poff,g_off);
    cudaGetSymbolAddress(&plj, g_lj);
    cudaGetSymbolAddress(&pBM, g_pBM); cudaGetSymbolAddress(&pBg, g_pBg);
    cudaGetSymbolAddress(&pBc, g_pBc);

    cudaFuncSetAttribute(k_aggGru, cudaFuncAttributeMaxDynamicSharedMemorySize,
                         SMEM_AGGGRU);

    k_T9  <<<1, 160>>>(gw, (float*)pT9);
    k_csr <<<1, 256>>>(eidx, E, (int*)poff, (int*)plj);
    k_prepB<<<(18*16*4 + 255)/256, 256>>>(wm, (float4*)pBM, 16, 16);
    k_prepB<<<(36*32*4 + 255)/256, 256>>>(wg, (float4*)pBg, 32, 32);
    k_prepB<<<(36*16*4 + 255)/256, 256>>>(wc, (float4*)pBc, 32, 16);

    const float* Xc = seed;
    for (int it = 0; it < 4; it++) {
        float* Xn = (it == 3) ? out : ((it & 1) ? (float*)pXb : (float*)pXa);

        k_convQ <<<B*NN, 256>>>(Xc, (const float4*)pBM, bm,
                                wq, bq, wk, bk, w1,
                                (float*)pM, (float*)pAB);
        k_aggGru<<<B*NN, 256, SMEM_AGGGRU>>>((const float*)pM, Xc,
                                (const float*)pAB, (const float*)pT9, gb,
                                b1, w2, b2, wo, bo,
                                (const float4*)pBg, bg,
                                (const float4*)pBc, bc,
                                (const int*)poff, (const int*)plj, Xn);
        Xc = Xn;
    }
}

// round 7
// speedup vs baseline: 3.5502x; 1.7088x over previous
#include <cuda_runtime.h>
#include <cuda_fp16.h>

typedef unsigned int uint;

// Problem constants (fixed by the dataset)
#define CC     16
#define NN     64
#define DQK    32
#define HIDN   64
#define MAXE   512
#define BMAX   16
#define PLANE  16384

// ---------------- scratch ----------------------------------------------------
__device__ float g_Xa [BMAX*CC*PLANE];
__device__ float g_Xb [BMAX*CC*PLANE];
__device__ float g_M  [BMAX*CC*PLANE];
__device__ float g_AB [BMAX*NN*128];
__device__ float g_T9 [CC*9];
__device__ int   g_off[NN+1];
__device__ int   g_lj [MAXE];
// fp16-split weight fragment tables: [(ks*N + n)*4 + q] -> (b0h,b1h,b0l,b1l)
__device__ uint4 g_pBM[9*16*4];
__device__ uint4 g_pBg[18*32*4];
__device__ uint4 g_pBc[18*16*4];

__device__ __forceinline__ float sigf(float x){ return 1.f/(1.f+__expf(-x)); }

// ---------------- fp16 split helpers -----------------------------------------
__device__ __forceinline__ uint packh2(__half a, __half b){
    __half2 h = __halves2half2(a, b);
    return *reinterpret_cast<uint*>(&h);
}
// split two floats into (hi half2, lo half2)
__device__ __forceinline__ uint2 h2pair(float v0, float v1){
    __half h0 = __float2half_rn(v0);
    __half h1 = __float2half_rn(v1);
    __half l0 = __float2half_rn(v0 - __half2float(h0));
    __half l1 = __float2half_rn(v1 - __half2float(h1));
    uint2 r; r.x = packh2(h0, h1); r.y = packh2(l0, l1); return r;
}
// reconstruct two floats
__device__ __forceinline__ float2 h2rec(uint2 e){
    __half2 hh = *reinterpret_cast<__half2*>(&e.x);
    __half2 ll = *reinterpret_cast<__half2*>(&e.y);
    float2 fh = __half22float2(hh), fl = __half22float2(ll);
    return make_float2(fh.x + fl.x, fh.y + fl.y);
}

__device__ __forceinline__ void mmah(float c[4], const uint a[4], uint b0, uint b1){
    asm volatile("mma.sync.aligned.m16n8k16.row.col.f32.f16.f16.f32 "
        "{%0,%1,%2,%3},{%4,%5,%6,%7},{%8,%9},{%0,%1,%2,%3};"
        : "+f"(c[0]),"+f"(c[1]),"+f"(c[2]),"+f"(c[3])
        : "r"(a[0]),"r"(a[1]),"r"(a[2]),"r"(a[3]),"r"(b0),"r"(b1));
}

// ---------------- weight prepack (runs once) ----------------------------------
// W layout [n][cin][tap]; K tap-major: k = tap*CIN + cin; kstep covers 16 k's.
__global__ void k_prepB(const float* __restrict__ W, uint4* __restrict__ out,
                        int CIN, int N)
{
    int KSTEPS = CIN*9/16;
    int tot = KSTEPS*N*4;
    int i = blockIdx.x*256 + threadIdx.x;
    if (i >= tot) return;
    int q = i & 3; int t = i >> 2; int n = t % N; int ks = t / N;
    float w[4]; __half h[4], l[4];
    int kk[4] = { ks*16 + 2*q, ks*16 + 2*q + 1, ks*16 + 2*q + 8, ks*16 + 2*q + 9 };
    #pragma unroll
    for (int j = 0; j < 4; j++) {
        int k = kk[j];
        w[j] = W[n*CIN*9 + (k % CIN)*9 + (k / CIN)];
        h[j] = __float2half_rn(w[j]);
        l[j] = __float2half_rn(w[j] - __half2float(h[j]));
    }
    uint4 o;
    o.x = packh2(h[0], h[1]);   // b0 hi
    o.y = packh2(h[2], h[3]);   // b1 hi
    o.z = packh2(l[0], l[1]);   // b0 lo
    o.w = packh2(l[2], l[3]);   // b1 lo
    out[(ks*N + n)*4 + q] = o;
}

// ---------------- tile loader ------------------------------------------------
// tile: [cpair][18][18] of uint2 (hi half2, lo half2).
// source channel pairs are LOCAL (0-based): src channels (2cp, 2cp+1) go to
// tile pair (cp0 + cp). zero halo.
__device__ __forceinline__ void load_tileh(uint2* sT,
                                           const float* __restrict__ src,
                                           int cp0, int cp1,
                                           int b, int p16, int q16)
{
    int nel = (cp1 - cp0)*324;
    for (int i = threadIdx.x; i < nel; i += 256) {
        int cp = i / 324; int r = i - cp*324;
        int yy = r / 18, xx = r - yy*18;
        int ly = yy - 1, lx = xx - 1;
        float v0 = 0.f, v1 = 0.f;
        if ((unsigned)ly < 16u && (unsigned)lx < 16u) {
            int c = cp*2;   // LOCAL source channel
            const float* p = &src[((b*CC + c)*128 + p16 + ly)*128 + (q16 + lx)];
            v0 = p[0]; v1 = p[PLANE];
        }
        sT[(cp0 + cp)*324 + r] = h2pair(v0, v1);
    }
}

// ---------------- fp16 3-term conv GEMM core ----------------------------------
// M=256 pixels (mtile = image row y, A-row = x), K = CIN*9 tap-major, kstep=16.
template<int CIN,int NT>
__device__ __forceinline__ void mma_convh(const uint2* sT,
                                          const uint4* __restrict__ pB,
                                          const float* s_bias,
                                          float acc[2][NT][4])
{
    constexpr int N = NT*8;
    constexpr int KSTEPS = CIN*9/16;
    constexpr int KPT = CIN/16;        // ksteps per tap (1 for CIN16, 2 for CIN32)
    int lane = threadIdx.x & 31;
    int wid  = threadIdx.x >> 5;
    int g = lane >> 2, q = lane & 3;
    int m0 = wid*2;

    #pragma unroll
    for (int mm = 0; mm < 2; mm++)
        #pragma unroll
        for (int nt = 0; nt < NT; nt++) {
            float b0 = s_bias[nt*8 + q*2], b1 = s_bias[nt*8 + q*2 + 1];
            acc[mm][nt][0] = b0; acc[mm][nt][1] = b1;
            acc[mm][nt][2] = b0; acc[mm][nt][3] = b1;
        }

    #pragma unroll 1
    for (int ks = 0; ks < KSTEPS; ks++) {
        int tap = (KPT == 1) ? ks : (ks >> 1);
        int sub = (KPT == 1) ? 0  : (ks & 1);
        int cpA = sub*8 + q;               // a0/a1 channel pair
        int ty = tap/3, tx = tap - ty*3;
        uint ah[2][4], al[2][4];
        #pragma unroll
        for (int mm = 0; mm < 2; mm++) {
            int row = (m0 + mm + ty)*18 + tx;
            uint2 e00 = sT[cpA*324       + row + g];
            uint2 e01 = sT[cpA*324       + row + g + 8];
            uint2 e10 = sT[(cpA + 4)*324 + row + g];
            uint2 e11 = sT[(cpA + 4)*324 + row + g + 8];
            ah[mm][0] = e00.x; al[mm][0] = e00.y;
            ah[mm][1] = e01.x; al[mm][1] = e01.y;
            ah[mm][2] = e10.x; al[mm][2] = e10.y;
            ah[mm][3] = e11.x; al[mm][3] = e11.y;
        }
        #pragma unroll
        for (int nt = 0; nt < NT; nt++) {
            uint4 bv = pB[(ks*N + nt*8 + g)*4 + q];
            #pragma unroll
            for (int mm = 0; mm < 2; mm++) {
                mmah(acc[mm][nt], ah[mm], bv.x, bv.y);   // hi*hi
                mmah(acc[mm][nt], ah[mm], bv.z, bv.w);   // hi*lo
                mmah(acc[mm][nt], al[mm], bv.x, bv.y);   // lo*hi
            }
        }
    }
}

// ---------------- setup kernels ----------------------------------------------
__global__ void k_T9(const float* __restrict__ gw, float* __restrict__ T9)
{
    int tid = threadIdx.x; if (tid >= CC*9) return;
    int c = tid / 9, cls = tid - c*9, ry = cls/3, rx = cls - ry*3;
    float s = 0.f;
    #pragma unroll
    for (int ky = 0; ky < 3; ky++) {
        if ((ry == 0 && ky == 0) || (ry == 2 && ky == 2)) continue;
        #pragma unroll
        for (int kx = 0; kx < 3; kx++) {
            if ((rx == 0 && kx == 0) || (rx == 2 && kx == 2)) continue;
            s += gw[c*9 + ky*3 + kx];
        }
    }
    T9[tid] = s;
}

__global__ void k_csr(const int* __restrict__ eidx, int E,
                      int* __restrict__ off, int* __restrict__ lj)
{
    __shared__ int se[MAXE*2];
    for (int i = threadIdx.x; i < 2*E; i += blockDim.x) se[i] = eidx[i];
    __syncthreads();
    if (threadIdx.x == 0) {
        int cnt[NN];
        for (int i = 0; i < NN; i++) cnt[i] = 0;
        for (int e = 0; e < E; e++) cnt[se[2*e]]++;
        int acc = 0;
        for (int i = 0; i < NN; i++) { off[i] = acc; acc += cnt[i]; cnt[i] = 0; }
        off[NN] = acc;
        for (int e = 0; e < E; e++) {
            int i = se[2*e];
            int s = off[i] + cnt[i]++;
            lj[s] = se[2*e + 1];
        }
    }
}

// ---------------- fused conv + mean/qk/AB kernel -------------------------------
__global__ __launch_bounds__(256) void k_convQ(const float* __restrict__ X,
    const uint4* __restrict__ pBM, const float* __restrict__ bm,
    const float* __restrict__ wq, const float* __restrict__ bq,
    const float* __restrict__ wk, const float* __restrict__ bk,
    const float* __restrict__ W1,
    float* __restrict__ M, float* __restrict__ AB)
{
    int bn = blockIdx.x; int b = bn >> 6, n = bn & 63;
    int p16 = (n >> 3)*16, q16 = (n & 7)*16;
    __shared__ uint2 sT[8*324];
    __shared__ float s_bias[16];
    __shared__ float s_red[16][8];
    __shared__ float s_xm[16];
    __shared__ float s_qk[64];
    load_tileh(sT, X, 0, 8, b, p16, q16);
    if (threadIdx.x < 16) s_bias[threadIdx.x] = bm[threadIdx.x];
    __syncthreads();

    int tid = threadIdx.x;
    // per-channel patch mean (hi+lo reconstruction; error ~2^-22)
    {
        int y = tid >> 4, x = tid & 15;
        int w = tid >> 5;
        #pragma unroll 1
        for (int cp = 0; cp < 8; cp++) {
            float2 v = h2rec(sT[cp*324 + (y + 1)*18 + (x + 1)]);
            #pragma unroll
            for (int o = 16; o; o >>= 1) {
                v.x += __shfl_down_sync(0xffffffffu, v.x, o);
                v.y += __shfl_down_sync(0xffffffffu, v.y, o);
            }
            if ((tid & 31) == 0) { s_red[2*cp][w] = v.x; s_red[2*cp + 1][w] = v.y; }
        }
    }

    float acc[2][2][4];
    mma_convh<16,2>(sT, pBM, s_bias, acc);

    int lane = tid & 31, wid = tid >> 5;
    int g = lane >> 2, q = lane & 3, m0 = wid*2;
    #pragma unroll
    for (int mm = 0; mm < 2; mm++) {
        int y = m0 + mm;
        #pragma unroll
        for (int nt = 0; nt < 2; nt++) {
            int co = nt*8 + q*2;
            int r0 = ((b*CC + co)*128 + p16 + y)*128 + q16;
            int r1 = r0 + PLANE;
            M[r0 + g]     = acc[mm][nt][0];
            M[r1 + g]     = acc[mm][nt][1];
            M[r0 + g + 8] = acc[mm][nt][2];
            M[r1 + g + 8] = acc[mm][nt][3];
        }
    }
    __syncthreads();
    if (tid < 16) {
        float s = 0.f;
        #pragma unroll
        for (int w = 0; w < 8; w++) s += s_red[tid][w];
        s_xm[tid] = s * (1.f/256.f);
    }
    __syncthreads();
    if (tid < 64) {
        int d = tid & 31;
        const float* wM = (tid < 32) ? wq : wk;
        const float* bM = (tid < 32) ? bq : bk;
        float a = bM[d];
        #pragma unroll
        for (int c = 0; c < CC; c++) a += s_xm[c]*wM[c*DQK + d];
        s_qk[tid] = a;
    }
    __syncthreads();
    if (tid < 128) {
        int t = tid & 63;
        int off = (tid < 64) ? 0 : 32;
        float a = 0.f;
        #pragma unroll
        for (int d = 0; d < 32; d++) a += s_qk[off + d]*W1[(off + d)*HIDN + t];
        AB[(b*NN + n)*128 + (tid < 64 ? 0 : 64) + t] = a;
    }
}

// ---------------- fused edgeMLP + gate + agg + GRU kernel ----------------------
__global__ __launch_bounds__(256,3) void k_aggGru(const float* __restrict__ M,
    const float* __restrict__ X, const float* __restrict__ AB,
    const float* __restrict__ T9, const float* __restrict__ gbv,
    const float* __restrict__ b1, const float* __restrict__ W2,
    const float* __restrict__ b2, const float* __restrict__ wo,
    const float* __restrict__ bo,
    const uint4* __restrict__ pBg, const float* __restrict__ bgv,
    const uint4* __restrict__ pBc, const float* __restrict__ bcv,
    const int* __restrict__ off, const int* __restrict__ lj,
    float* __restrict__ Xn)
{
    int bn = blockIdx.x; int b = bn >> 6, i = bn & 63;
    int p16 = (i >> 3)*16, q16 = (i & 7)*16;
    extern __shared__ uint2 sT[];               // 16*324 uint2 = 41,472 B
    __shared__ float sW2[HIDN*HIDN];            // 16 KB
    __shared__ float sg[4*144];
    __shared__ float sT9[144];
    __shared__ float sgb[16], s_bg[32], s_bc[16];
    __shared__ float sb1[64], sb2[64], swo[64];
    __shared__ float h1s[4][64], sred[4][2], sev[4];
    __shared__ int sbase[4];

    int tid = threadIdx.x;
    int o0 = off[i], deg = off[i+1] - o0;

    // zero agg channel-pairs 0..7 (incl. halo); load X into pairs 8..15
    for (int t = tid; t < 8*324; t += 256) sT[t] = make_uint2(0u, 0u);
    load_tileh(sT, X, 8, 16, b, p16, q16);

    for (int t = tid; t < HIDN*HIDN; t += 256) sW2[t] = W2[t];
    if (tid < 144) sT9[tid] = T9[tid];
    if (tid < 16)  sgb[tid] = gbv[tid];
    if (tid < 32)  s_bg[tid] = bgv[tid];
    if (tid < 16)  s_bc[tid] = bcv[tid];
    if (tid < 64)  { sb1[tid] = b1[tid]; sb2[tid] = b2[tid]; swo[tid] = wo[tid]; }
    if (tid < deg) {
        int ej = lj[o0 + tid];
        sbase[tid] = ((b*CC)*128 + (ej >> 3)*16)*128 + (ej & 7)*16;
    }
    float bov = bo[0];
    __syncthreads();

    // ---- edge MLP for this node's incident edges (<=4) ----
    int l = tid >> 6, t = tid & 63;
    if (l < deg) {
        int ej = lj[o0 + l];
        float a = AB[(b*NN + i)*128 + t] + AB[(b*NN + ej)*128 + 64 + t] + sb1[t];
        h1s[l][t] = fmaxf(a, 0.f);
    }
    __syncthreads();
    if (l < deg) {
        float a2 = sb2[t];
        #pragma unroll
        for (int k = 0; k < HIDN; k++) a2 += h1s[l][k]*sW2[k*HIDN + t];
        a2 = fmaxf(a2, 0.f);
        float part = a2*swo[t];
        #pragma unroll
        for (int o = 16; o; o >>= 1) part += __shfl_down_sync(0xffffffffu, part, o);
        if ((t & 31) == 0) sred[l][t >> 5] = part;
    }
    __syncthreads();
    if (tid < deg) sev[tid] = sred[tid][0] + sred[tid][1] + bov;
    __syncthreads();

    // ---- gate table ----
    for (int t2 = tid; t2 < deg*144; t2 += 256) {
        int le = t2 / 144, r = t2 - le*144;
        int c = r / 9;
        sg[t2] = sigf(sev[le]*sT9[r] + sgb[c]);
    }
    __syncthreads();

    // ---- segment-sum of gated messages, write split pairs into sT cp 0..7 ----
    {
        int cg = tid >> 6, pg = tid & 63;
        int y = pg >> 2, x0 = (pg & 3)*4;
        int cy = (y == 0) ? 0 : ((y == 15) ? 2 : 1);
        int cix[4];
        #pragma unroll
        for (int k = 0; k < 4; k++) {
            int x = x0 + k;
            cix[k] = cy*3 + ((x == 0) ? 0 : ((x == 15) ? 2 : 1));
        }
        int pix = y*128 + x0;
        float av[4][4];
        #pragma unroll
        for (int cc = 0; cc < 4; cc++) {
            int c = cg*4 + cc;
            float a0=0.f,a1=0.f,a2=0.f,a3=0.f;
            for (int le = 0; le < deg; le++) {
                const float* gl = &sg[le*144 + c*9];
                float4 m = *reinterpret_cast<const float4*>(&M[sbase[le] + c*PLANE + pix]);
                a0 += gl[cix[0]]*m.x;
                a1 += gl[cix[1]]*m.y;
                a2 += gl[cix[2]]*m.z;
                a3 += gl[cix[3]]*m.w;
            }
            av[cc][0]=a0; av[cc][1]=a1; av[cc][2]=a2; av[cc][3]=a3;
        }
        #pragma unroll
        for (int p = 0; p < 2; p++) {
            int cp = cg*2 + p;
            #pragma unroll
            for (int k = 0; k < 4; k++) {
                sT[cp*324 + (y + 1)*18 + (x0 + 1 + k)] =
                    h2pair(av[2*p][k], av[2*p + 1][k]);
            }
        }
    }
    __syncthreads();

    // ---- GRU ----
    int lane = tid & 31, wid = tid >> 5;
    int g = lane >> 2, q = lane & 3, m0 = wid*2;

    float zreg[2][2][4];
    float hreg[2][2][4];

    {   // gate conv
        float acc[2][4][4];
        mma_convh<32,4>(sT, pBg, s_bg, acc);
        __syncthreads();   // all tile reads complete before rh overwrite
        #pragma unroll
        for (int mm = 0; mm < 2; mm++) {
            int y = m0 + mm;
            #pragma unroll
            for (int nt = 0; nt < 4; nt++) {
                int co = nt*8 + q*2;
                if (nt < 2) {
                    #pragma unroll
                    for (int rr = 0; rr < 4; rr++)
                        zreg[mm][nt][rr] = sigf(acc[mm][nt][rr]);
                } else {
                    int cp = co >> 1;   // channel pair (co, co+1), co >= 16
                    #pragma unroll
                    for (int half = 0; half < 2; half++) {
                        int x = g + half*8;
                        int ti = cp*324 + (y + 1)*18 + (x + 1);
                        float2 h = h2rec(sT[ti]);
                        float r0 = sigf(acc[mm][nt][half*2]);
                        float r1 = sigf(acc[mm][nt][half*2 + 1]);
                        hreg[mm][nt - 2][half*2]     = h.x;
                        hreg[mm][nt - 2][half*2 + 1] = h.y;
                        sT[ti] = h2pair(r0*h.x, r1*h.y);
                    }
                }
            }
        }
    }
    __syncthreads();

    {   // candidate conv + update
        float acc[2][2][4];
        mma_convh<32,2>(sT, pBc, s_bc, acc);
        #pragma unroll
        for (int mm = 0; mm < 2; mm++) {
            int y = m0 + mm;
            #pragma unroll
            for (int nt = 0; nt < 2; nt++) {
                int co = nt*8 + q*2;
                #pragma unroll
                for (int rr = 0; rr < 4; rr++) {
                    int c = co + (rr & 1);
                    int x = g + (rr >= 2 ? 8 : 0);
                    float cand = tanhf(acc[mm][nt][rr]);
                    float z = zreg[mm][nt][rr];
                    float h = hreg[mm][nt][rr];
                    int idx = ((b*CC + c)*128 + p16 + y)*128 + q16 + x;
                    Xn[idx] = (1.f - z)*h + z*cand;
                }
            }
        }
    }
}

#define SMEM_AGGGRU (16*324*8)

// ---------------- launch ------------------------------------------------------
extern "C" void kernel_launch(void* const* d_in, const int* in_sizes, int n_in,
                              void* d_out, int out_size)
{
    const float* seed = (const float*)d_in[0];
    const int*   eidx = (const int*)  d_in[1];
    const float* wq = (const float*)d_in[2];
    const float* bq = (const float*)d_in[3];
    const float* wk = (const float*)d_in[4];
    const float* bk = (const float*)d_in[5];
    const float* wm = (const float*)d_in[6];
    const float* bm = (const float*)d_in[7];
    const float* w1 = (const float*)d_in[8];
    const float* b1 = (const float*)d_in[9];
    const float* w2 = (const float*)d_in[10];
    const float* b2 = (const float*)d_in[11];
    const float* wo = (const float*)d_in[12];
    const float* bo = (const float*)d_in[13];
    const float* gw = (const float*)d_in[14];
    const float* gb = (const float*)d_in[15];
    const float* wg = (const float*)d_in[16];
    const float* bg = (const float*)d_in[17];
    const float* wc = (const float*)d_in[18];
    const float* bc = (const float*)d_in[19];
    float* out = (float*)d_out;

    int B = in_sizes[0] / (CC*128*128);
    int E = in_sizes[1] / 2;

    void *pXa,*pXb,*pM,*pAB,*pT9,*poff,*plj,*pBM,*pBg,*pBc;
    cudaGetSymbolAddress(&pXa, g_Xa);  cudaGetSymbolAddress(&pXb, g_Xb);
    cudaGetSymbolAddress(&pM,  g_M);   cudaGetSymbolAddress(&pAB, g_AB);
    cudaGetSymbolAddress(&pT9, g_T9);  cudaGetSymbolAddress(&poff,g_off);
    cudaGetSymbolAddress(&plj, g_lj);
    cudaGetSymbolAddress(&pBM, g_pBM); cudaGetSymbolAddress(&pBg, g_pBg);
    cudaGetSymbolAddress(&pBc, g_pBc);

    cudaFuncSetAttribute(k_aggGru, cudaFuncAttributeMaxDynamicSharedMemorySize,
                         SMEM_AGGGRU);

    k_T9  <<<1, 160>>>(gw, (float*)pT9);
    k_csr <<<1, 256>>>(eidx, E, (int*)poff, (int*)plj);
    k_prepB<<<(9*16*4  + 255)/256, 256>>>(wm, (uint4*)pBM, 16, 16);
    k_prepB<<<(18*32*4 + 255)/256, 256>>>(wg, (uint4*)pBg, 32, 32);
    k_prepB<<<(18*16*4 + 255)/256, 256>>>(wc, (uint4*)pBc, 32, 16);

    const float* Xc = seed;
    for (int it = 0; it < 4; it++) {
        float* Xn = (it == 3) ? out : ((it & 1) ? (float*)pXb : (float*)pXa);

        k_convQ <<<B*NN, 256>>>(Xc, (const uint4*)pBM, bm,
                                wq, bq, wk, bk, w1,
                                (float*)pM, (float*)pAB);
        k_aggGru<<<B*NN, 256, SMEM_AGGGRU>>>((const float*)pM, Xc,
                                (const float*)pAB, (const float*)pT9, gb,
                                b1, w2, b2, wo, bo,
                                (const uint4*)pBg, bg,
                                (const uint4*)pBc, bc,
                                (const int*)poff, (const int*)plj, Xn);
        Xc = Xn;
    }
}

// round 8
// speedup vs baseline: 3.6752x; 1.0352x over previous
#include <cuda_runtime.h>
#include <cuda_fp16.h>

typedef unsigned int uint;

// Problem constants (fixed by the dataset)
#define CC     16
#define NN     64
#define DQK    32
#define HIDN   64
#define MAXE   512
#define BMAX   16
#define PLANE  16384

// ---------------- scratch ----------------------------------------------------
__device__ float g_Xa [BMAX*CC*PLANE];
__device__ float g_Xb [BMAX*CC*PLANE];
__device__ float g_M0 [BMAX*CC*PLANE];
__device__ float g_M1 [BMAX*CC*PLANE];
__device__ float g_AB0[BMAX*NN*128];
__device__ float g_AB1[BMAX*NN*128];
__device__ float g_T9 [CC*9];
__device__ int   g_off[NN+1];
__device__ int   g_lj [MAXE];
// fp16-split weight fragment tables: [(ks*N + n)*4 + q] -> (b0h,b1h,b0l,b1l)
__device__ uint4 g_pBM[9*16*4];
__device__ uint4 g_pBg[18*32*4];
__device__ uint4 g_pBc[18*16*4];

__device__ __forceinline__ float sigf(float x){ return 1.f/(1.f+__expf(-x)); }

// ---------------- fp16 split helpers -----------------------------------------
__device__ __forceinline__ uint packh2(__half a, __half b){
    __half2 h = __halves2half2(a, b);
    return *reinterpret_cast<uint*>(&h);
}
__device__ __forceinline__ uint2 h2pair(float v0, float v1){
    __half h0 = __float2half_rn(v0);
    __half h1 = __float2half_rn(v1);
    __half l0 = __float2half_rn(v0 - __half2float(h0));
    __half l1 = __float2half_rn(v1 - __half2float(h1));
    uint2 r; r.x = packh2(h0, h1); r.y = packh2(l0, l1); return r;
}
__device__ __forceinline__ float2 h2rec(uint2 e){
    __half2 hh = *reinterpret_cast<__half2*>(&e.x);
    __half2 ll = *reinterpret_cast<__half2*>(&e.y);
    float2 fh = __half22float2(hh), fl = __half22float2(ll);
    return make_float2(fh.x + fl.x, fh.y + fl.y);
}

__device__ __forceinline__ void mmah(float c[4], const uint a[4], uint b0, uint b1){
    asm volatile("mma.sync.aligned.m16n8k16.row.col.f32.f16.f16.f32 "
        "{%0,%1,%2,%3},{%4,%5,%6,%7},{%8,%9},{%0,%1,%2,%3};"
        : "+f"(c[0]),"+f"(c[1]),"+f"(c[2]),"+f"(c[3])
        : "r"(a[0]),"r"(a[1]),"r"(a[2]),"r"(a[3]),"r"(b0),"r"(b1));
}

// ---------------- weight prepack (runs once) ----------------------------------
__global__ void k_prepB(const float* __restrict__ W, uint4* __restrict__ out,
                        int CIN, int N)
{
    int KSTEPS = CIN*9/16;
    int tot = KSTEPS*N*4;
    int i = blockIdx.x*256 + threadIdx.x;
    if (i >= tot) return;
    int q = i & 3; int t = i >> 2; int n = t % N; int ks = t / N;
    float w[4]; __half h[4], l[4];
    int kk[4] = { ks*16 + 2*q, ks*16 + 2*q + 1, ks*16 + 2*q + 8, ks*16 + 2*q + 9 };
    #pragma unroll
    for (int j = 0; j < 4; j++) {
        int k = kk[j];
        w[j] = W[n*CIN*9 + (k % CIN)*9 + (k / CIN)];
        h[j] = __float2half_rn(w[j]);
        l[j] = __float2half_rn(w[j] - __half2float(h[j]));
    }
    uint4 o;
    o.x = packh2(h[0], h[1]);
    o.y = packh2(h[2], h[3]);
    o.z = packh2(l[0], l[1]);
    o.w = packh2(l[2], l[3]);
    out[(ks*N + n)*4 + q] = o;
}

// ---------------- tile loader ------------------------------------------------
// tile: [cpair][18][18] of uint2 (hi half2, lo half2). Source pairs LOCAL.
__device__ __forceinline__ void load_tileh(uint2* sT,
                                           const float* __restrict__ src,
                                           int cp0, int cp1,
                                           int b, int p16, int q16)
{
    int nel = (cp1 - cp0)*324;
    for (int i = threadIdx.x; i < nel; i += 256) {
        int cp = i / 324; int r = i - cp*324;
        int yy = r / 18, xx = r - yy*18;
        int ly = yy - 1, lx = xx - 1;
        float v0 = 0.f, v1 = 0.f;
        if ((unsigned)ly < 16u && (unsigned)lx < 16u) {
            int c = cp*2;
            const float* p = &src[((b*CC + c)*128 + p16 + ly)*128 + (q16 + lx)];
            v0 = p[0]; v1 = p[PLANE];
        }
        sT[(cp0 + cp)*324 + r] = h2pair(v0, v1);
    }
}

// ---------------- fp16 3-term conv GEMM core ----------------------------------
template<int CIN,int NT>
__device__ __forceinline__ void mma_convh(const uint2* sT,
                                          const uint4* __restrict__ pB,
                                          const float* s_bias,
                                          float acc[2][NT][4])
{
    constexpr int N = NT*8;
    constexpr int KSTEPS = CIN*9/16;
    constexpr int KPT = CIN/16;
    int lane = threadIdx.x & 31;
    int wid  = threadIdx.x >> 5;
    int g = lane >> 2, q = lane & 3;
    int m0 = wid*2;

    #pragma unroll
    for (int mm = 0; mm < 2; mm++)
        #pragma unroll
        for (int nt = 0; nt < NT; nt++) {
            float b0 = s_bias[nt*8 + q*2], b1 = s_bias[nt*8 + q*2 + 1];
            acc[mm][nt][0] = b0; acc[mm][nt][1] = b1;
            acc[mm][nt][2] = b0; acc[mm][nt][3] = b1;
        }

    #pragma unroll 1
    for (int ks = 0; ks < KSTEPS; ks++) {
        int tap = (KPT == 1) ? ks : (ks >> 1);
        int sub = (KPT == 1) ? 0  : (ks & 1);
        int cpA = sub*8 + q;
        int ty = tap/3, tx = tap - ty*3;
        uint ah[2][4], al[2][4];
        #pragma unroll
        for (int mm = 0; mm < 2; mm++) {
            int row = (m0 + mm + ty)*18 + tx;
            uint2 e00 = sT[cpA*324       + row + g];
            uint2 e01 = sT[cpA*324       + row + g + 8];
            uint2 e10 = sT[(cpA + 4)*324 + row + g];
            uint2 e11 = sT[(cpA + 4)*324 + row + g + 8];
            ah[mm][0] = e00.x; al[mm][0] = e00.y;
            ah[mm][1] = e01.x; al[mm][1] = e01.y;
            ah[mm][2] = e10.x; al[mm][2] = e10.y;
            ah[mm][3] = e11.x; al[mm][3] = e11.y;
        }
        #pragma unroll
        for (int nt = 0; nt < NT; nt++) {
            uint4 bv = pB[(ks*N + nt*8 + g)*4 + q];
            #pragma unroll
            for (int mm = 0; mm < 2; mm++) {
                mmah(acc[mm][nt], ah[mm], bv.x, bv.y);
                mmah(acc[mm][nt], ah[mm], bv.z, bv.w);
                mmah(acc[mm][nt], al[mm], bv.x, bv.y);
            }
        }
    }
}

// ---------------- setup kernels ----------------------------------------------
__global__ void k_T9(const float* __restrict__ gw, float* __restrict__ T9)
{
    int tid = threadIdx.x; if (tid >= CC*9) return;
    int c = tid / 9, cls = tid - c*9, ry = cls/3, rx = cls - ry*3;
    float s = 0.f;
    #pragma unroll
    for (int ky = 0; ky < 3; ky++) {
        if ((ry == 0 && ky == 0) || (ry == 2 && ky == 2)) continue;
        #pragma unroll
        for (int kx = 0; kx < 3; kx++) {
            if ((rx == 0 && kx == 0) || (rx == 2 && kx == 2)) continue;
            s += gw[c*9 + ky*3 + kx];
        }
    }
    T9[tid] = s;
}

__global__ void k_csr(const int* __restrict__ eidx, int E,
                      int* __restrict__ off, int* __restrict__ lj)
{
    __shared__ int se[MAXE*2];
    for (int i = threadIdx.x; i < 2*E; i += blockDim.x) se[i] = eidx[i];
    __syncthreads();
    if (threadIdx.x == 0) {
        int cnt[NN];
        for (int i = 0; i < NN; i++) cnt[i] = 0;
        for (int e = 0; e < E; e++) cnt[se[2*e]]++;
        int acc = 0;
        for (int i = 0; i < NN; i++) { off[i] = acc; acc += cnt[i]; cnt[i] = 0; }
        off[NN] = acc;
        for (int e = 0; e < E; e++) {
            int i = se[2*e];
            int s = off[i] + cnt[i]++;
            lj[s] = se[2*e + 1];
        }
    }
}

// ---------------- initial conv + mean/qk/AB kernel (seed only) ----------------
__global__ __launch_bounds__(256) void k_convQ(const float* __restrict__ X,
    const uint4* __restrict__ pBM, const float* __restrict__ bm,
    const float* __restrict__ wq, const float* __restrict__ bq,
    const float* __restrict__ wk, const float* __restrict__ bk,
    const float* __restrict__ W1,
    float* __restrict__ M, float* __restrict__ AB)
{
    int bn = blockIdx.x; int b = bn >> 6, n = bn & 63;
    int p16 = (n >> 3)*16, q16 = (n & 7)*16;
    __shared__ uint2 sT[8*324];
    __shared__ float s_bias[16];
    __shared__ float s_red[16][8];
    __shared__ float s_xm[16];
    __shared__ float s_qk[64];
    load_tileh(sT, X, 0, 8, b, p16, q16);
    if (threadIdx.x < 16) s_bias[threadIdx.x] = bm[threadIdx.x];
    __syncthreads();

    int tid = threadIdx.x;
    {
        int y = tid >> 4, x = tid & 15;
        int w = tid >> 5;
        #pragma unroll 1
        for (int cp = 0; cp < 8; cp++) {
            float2 v = h2rec(sT[cp*324 + (y + 1)*18 + (x + 1)]);
            #pragma unroll
            for (int o = 16; o; o >>= 1) {
                v.x += __shfl_down_sync(0xffffffffu, v.x, o);
                v.y += __shfl_down_sync(0xffffffffu, v.y, o);
            }
            if ((tid & 31) == 0) { s_red[2*cp][w] = v.x; s_red[2*cp + 1][w] = v.y; }
        }
    }

    float acc[2][2][4];
    mma_convh<16,2>(sT, pBM, s_bias, acc);

    int lane = tid & 31, wid = tid >> 5;
    int g = lane >> 2, q = lane & 3, m0 = wid*2;
    #pragma unroll
    for (int mm = 0; mm < 2; mm++) {
        int y = m0 + mm;
        #pragma unroll
        for (int nt = 0; nt < 2; nt++) {
            int co = nt*8 + q*2;
            int r0 = ((b*CC + co)*128 + p16 + y)*128 + q16;
            int r1 = r0 + PLANE;
            M[r0 + g]     = acc[mm][nt][0];
            M[r1 + g]     = acc[mm][nt][1];
            M[r0 + g + 8] = acc[mm][nt][2];
            M[r1 + g + 8] = acc[mm][nt][3];
        }
    }
    __syncthreads();
    if (tid < 16) {
        float s = 0.f;
        #pragma unroll
        for (int w = 0; w < 8; w++) s += s_red[tid][w];
        s_xm[tid] = s * (1.f/256.f);
    }
    __syncthreads();
    if (tid < 64) {
        int d = tid & 31;
        const float* wM = (tid < 32) ? wq : wk;
        const float* bM = (tid < 32) ? bq : bk;
        float a = bM[d];
        #pragma unroll
        for (int c = 0; c < CC; c++) a += s_xm[c]*wM[c*DQK + d];
        s_qk[tid] = a;
    }
    __syncthreads();
    if (tid < 128) {
        int t = tid & 63;
        int off = (tid < 64) ? 0 : 32;
        float a = 0.f;
        #pragma unroll
        for (int d = 0; d < 32; d++) a += s_qk[off + d]*W1[(off + d)*HIDN + t];
        AB[(b*NN + n)*128 + (tid < 64 ? 0 : 64) + t] = a;
    }
}

// ---------------- fused iteration kernel ---------------------------------------
// edgeMLP + gate + agg + GRU + (optionally) next-iter convM + mean/qk/AB tail
__global__ __launch_bounds__(256,3) void k_iter(const float* __restrict__ M,
    const float* __restrict__ X, const float* __restrict__ AB,
    const float* __restrict__ T9, const float* __restrict__ gbv,
    const float* __restrict__ b1, const float* __restrict__ W2,
    const float* __restrict__ b2, const float* __restrict__ wo,
    const float* __restrict__ bo,
    const uint4* __restrict__ pBg, const float* __restrict__ bgv,
    const uint4* __restrict__ pBc, const float* __restrict__ bcv,
    const uint4* __restrict__ pBM, const float* __restrict__ bm,
    const float* __restrict__ wq, const float* __restrict__ bq,
    const float* __restrict__ wk, const float* __restrict__ bk,
    const float* __restrict__ W1,
    const int* __restrict__ off, const int* __restrict__ lj,
    float* __restrict__ Xn, float* __restrict__ Mout,
    float* __restrict__ ABout, int doTail)
{
    int bn = blockIdx.x; int b = bn >> 6, i = bn & 63;
    int p16 = (i >> 3)*16, q16 = (i & 7)*16;
    extern __shared__ uint2 sT[];               // 16*324 uint2 = 41,472 B
    __shared__ float sW2[HIDN*HIDN];            // 16 KB
    __shared__ float sg[4*144];
    __shared__ float sT9[144];
    __shared__ float sgb[16], s_bg[32], s_bc[16], s_bm[16];
    __shared__ float sb1[64], sb2[64], swo[64];
    __shared__ float h1s[4][64], sred[4][2], sev[4];
    __shared__ float s_red[16][8], s_xm[16], s_qk[64];
    __shared__ int sbase[4];

    int tid = threadIdx.x;
    int o0 = off[i], deg = off[i+1] - o0;

    // zero agg channel-pairs 0..7 (incl. halo); load X into pairs 8..15
    for (int t = tid; t < 8*324; t += 256) sT[t] = make_uint2(0u, 0u);
    load_tileh(sT, X, 8, 16, b, p16, q16);

    for (int t = tid; t < HIDN*HIDN; t += 256) sW2[t] = W2[t];
    if (tid < 144) sT9[tid] = T9[tid];
    if (tid < 16)  sgb[tid] = gbv[tid];
    if (tid < 32)  s_bg[tid] = bgv[tid];
    if (tid < 16)  s_bc[tid] = bcv[tid];
    if (tid < 16)  s_bm[tid] = bm[tid];
    if (tid < 64)  { sb1[tid] = b1[tid]; sb2[tid] = b2[tid]; swo[tid] = wo[tid]; }
    if (tid < deg) {
        int ej = lj[o0 + tid];
        sbase[tid] = ((b*CC)*128 + (ej >> 3)*16)*128 + (ej & 7)*16;
    }
    float bov = bo[0];
    __syncthreads();

    // ---- edge MLP for this node's incident edges (<=4) ----
    int l = tid >> 6, t = tid & 63;
    if (l < deg) {
        int ej = lj[o0 + l];
        float a = AB[(b*NN + i)*128 + t] + AB[(b*NN + ej)*128 + 64 + t] + sb1[t];
        h1s[l][t] = fmaxf(a, 0.f);
    }
    __syncthreads();
    if (l < deg) {
        float a2 = sb2[t];
        #pragma unroll
        for (int k = 0; k < HIDN; k++) a2 += h1s[l][k]*sW2[k*HIDN + t];
        a2 = fmaxf(a2, 0.f);
        float part = a2*swo[t];
        #pragma unroll
        for (int o = 16; o; o >>= 1) part += __shfl_down_sync(0xffffffffu, part, o);
        if ((t & 31) == 0) sred[l][t >> 5] = part;
    }
    __syncthreads();
    if (tid < deg) sev[tid] = sred[tid][0] + sred[tid][1] + bov;
    __syncthreads();

    // ---- gate table ----
    for (int t2 = tid; t2 < deg*144; t2 += 256) {
        int le = t2 / 144, r = t2 - le*144;
        int c = r / 9;
        sg[t2] = sigf(sev[le]*sT9[r] + sgb[c]);
    }
    __syncthreads();

    // ---- segment-sum of gated messages, write split pairs into sT cp 0..7 ----
    {
        int cg = tid >> 6, pg = tid & 63;
        int y = pg >> 2, x0 = (pg & 3)*4;
        int cy = (y == 0) ? 0 : ((y == 15) ? 2 : 1);
        int cix[4];
        #pragma unroll
        for (int k = 0; k < 4; k++) {
            int x = x0 + k;
            cix[k] = cy*3 + ((x == 0) ? 0 : ((x == 15) ? 2 : 1));
        }
        int pix = y*128 + x0;
        float av[4][4];
        #pragma unroll
        for (int cc = 0; cc < 4; cc++) {
            int c = cg*4 + cc;
            float a0=0.f,a1=0.f,a2=0.f,a3=0.f;
            for (int le = 0; le < deg; le++) {
                const float* gl = &sg[le*144 + c*9];
                float4 m = *reinterpret_cast<const float4*>(&M[sbase[le] + c*PLANE + pix]);
                a0 += gl[cix[0]]*m.x;
                a1 += gl[cix[1]]*m.y;
                a2 += gl[cix[2]]*m.z;
                a3 += gl[cix[3]]*m.w;
            }
            av[cc][0]=a0; av[cc][1]=a1; av[cc][2]=a2; av[cc][3]=a3;
        }
        #pragma unroll
        for (int p = 0; p < 2; p++) {
            int cp = cg*2 + p;
            #pragma unroll
            for (int k = 0; k < 4; k++) {
                sT[cp*324 + (y + 1)*18 + (x0 + 1 + k)] =
                    h2pair(av[2*p][k], av[2*p + 1][k]);
            }
        }
    }
    __syncthreads();

    // ---- GRU ----
    int lane = tid & 31, wid = tid >> 5;
    int g = lane >> 2, q = lane & 3, m0 = wid*2;

    float zreg[2][2][4];
    float hreg[2][2][4];

    {   // gate conv
        float acc[2][4][4];
        mma_convh<32,4>(sT, pBg, s_bg, acc);
        __syncthreads();
        #pragma unroll
        for (int mm = 0; mm < 2; mm++) {
            int y = m0 + mm;
            #pragma unroll
            for (int nt = 0; nt < 4; nt++) {
                int co = nt*8 + q*2;
                if (nt < 2) {
                    #pragma unroll
                    for (int rr = 0; rr < 4; rr++)
                        zreg[mm][nt][rr] = sigf(acc[mm][nt][rr]);
                } else {
                    int cp = co >> 1;
                    #pragma unroll
                    for (int half = 0; half < 2; half++) {
                        int x = g + half*8;
                        int ti = cp*324 + (y + 1)*18 + (x + 1);
                        float2 h = h2rec(sT[ti]);
                        float r0 = sigf(acc[mm][nt][half*2]);
                        float r1 = sigf(acc[mm][nt][half*2 + 1]);
                        hreg[mm][nt - 2][half*2]     = h.x;
                        hreg[mm][nt - 2][half*2 + 1] = h.y;
                        sT[ti] = h2pair(r0*h.x, r1*h.y);
                    }
                }
            }
        }
    }
    __syncthreads();

    float xn[2][2][4];
    {   // candidate conv + update
        float acc[2][2][4];
        mma_convh<32,2>(sT, pBc, s_bc, acc);
        #pragma unroll
        for (int mm = 0; mm < 2; mm++) {
            int y = m0 + mm;
            #pragma unroll
            for (int nt = 0; nt < 2; nt++) {
                int co = nt*8 + q*2;
                #pragma unroll
                for (int rr = 0; rr < 4; rr++) {
                    int c = co + (rr & 1);
                    int x = g + (rr >= 2 ? 8 : 0);
                    float cand = tanhf(acc[mm][nt][rr]);
                    float z = zreg[mm][nt][rr];
                    float h = hreg[mm][nt][rr];
                    float v = (1.f - z)*h + z*cand;
                    xn[mm][nt][rr] = v;
                    int idx = ((b*CC + c)*128 + p16 + y)*128 + q16 + x;
                    Xn[idx] = v;
                }
            }
        }
    }

    if (!doTail) return;

    // ---- tail: next-iteration convM + mean/qk/AB from Xn (patch-local) ----
    __syncthreads();    // all cand-conv tile reads done before overwrite
    #pragma unroll
    for (int mm = 0; mm < 2; mm++) {
        int y = m0 + mm;
        #pragma unroll
        for (int nt = 0; nt < 2; nt++) {
            int cp = (nt*8 + q*2) >> 1;
            #pragma unroll
            for (int half = 0; half < 2; half++) {
                int x = g + half*8;
                sT[cp*324 + (y + 1)*18 + (x + 1)] =
                    h2pair(xn[mm][nt][half*2], xn[mm][nt][half*2 + 1]);
            }
        }
    }
    __syncthreads();

    {   // patch mean from split tile
        int y = tid >> 4, x = tid & 15;
        int w = tid >> 5;
        #pragma unroll 1
        for (int cp = 0; cp < 8; cp++) {
            float2 v = h2rec(sT[cp*324 + (y + 1)*18 + (x + 1)]);
            #pragma unroll
            for (int o = 16; o; o >>= 1) {
                v.x += __shfl_down_sync(0xffffffffu, v.x, o);
                v.y += __shfl_down_sync(0xffffffffu, v.y, o);
            }
            if ((tid & 31) == 0) { s_red[2*cp][w] = v.x; s_red[2*cp + 1][w] = v.y; }
        }
    }

    {   // M conv for next iteration
        float acc[2][2][4];
        mma_convh<16,2>(sT, pBM, s_bm, acc);
        #pragma unroll
        for (int mm = 0; mm < 2; mm++) {
            int y = m0 + mm;
            #pragma unroll
            for (int nt = 0; nt < 2; nt++) {
                int co = nt*8 + q*2;
                int r0 = ((b*CC + co)*128 + p16 + y)*128 + q16;
                int r1 = r0 + PLANE;
                Mout[r0 + g]     = acc[mm][nt][0];
                Mout[r1 + g]     = acc[mm][nt][1];
                Mout[r0 + g + 8] = acc[mm][nt][2];
                Mout[r1 + g + 8] = acc[mm][nt][3];
            }
        }
    }
    __syncthreads();
    if (tid < 16) {
        float s = 0.f;
        #pragma unroll
        for (int w = 0; w < 8; w++) s += s_red[tid][w];
        s_xm[tid] = s * (1.f/256.f);
    }
    __syncthreads();
    if (tid < 64) {
        int d = tid & 31;
        const float* wM = (tid < 32) ? wq : wk;
        const float* bM = (tid < 32) ? bq : bk;
        float a = bM[d];
        #pragma unroll
        for (int c = 0; c < CC; c++) a += s_xm[c]*wM[c*DQK + d];
        s_qk[tid] = a;
    }
    __syncthreads();
    if (tid < 128) {
        int t2 = tid & 63;
        int offp = (tid < 64) ? 0 : 32;
        float a = 0.f;
        #pragma unroll
        for (int d = 0; d < 32; d++) a += s_qk[offp + d]*W1[(offp + d)*HIDN + t2];
        ABout[(b*NN + i)*128 + (tid < 64 ? 0 : 64) + t2] = a;
    }
}

#define SMEM_ITER (16*324*8)

// ---------------- launch ------------------------------------------------------
extern "C" void kernel_launch(void* const* d_in, const int* in_sizes, int n_in,
                              void* d_out, int out_size)
{
    const float* seed = (const float*)d_in[0];
    const int*   eidx = (const int*)  d_in[1];
    const float* wq = (const float*)d_in[2];
    const float* bq = (const float*)d_in[3];
    const float* wk = (const float*)d_in[4];
    const float* bk = (const float*)d_in[5];
    const float* wm = (const float*)d_in[6];
    const float* bm = (const float*)d_in[7];
    const float* w1 = (const float*)d_in[8];
    const float* b1 = (const float*)d_in[9];
    const float* w2 = (const float*)d_in[10];
    const float* b2 = (const float*)d_in[11];
    const float* wo = (const float*)d_in[12];
    const float* bo = (const float*)d_in[13];
    const float* gw = (const float*)d_in[14];
    const float* gb = (const float*)d_in[15];
    const float* wg = (const float*)d_in[16];
    const float* bg = (const float*)d_in[17];
    const float* wc = (const float*)d_in[18];
    const float* bc = (const float*)d_in[19];
    float* out = (float*)d_out;

    int B = in_sizes[0] / (CC*128*128);
    int E = in_sizes[1] / 2;

    void *pXa,*pXb,*pM0,*pM1,*pAB0,*pAB1,*pT9,*poff,*plj,*pBM,*pBg,*pBc;
    cudaGetSymbolAddress(&pXa, g_Xa);   cudaGetSymbolAddress(&pXb, g_Xb);
    cudaGetSymbolAddress(&pM0, g_M0);   cudaGetSymbolAddress(&pM1, g_M1);
    cudaGetSymbolAddress(&pAB0,g_AB0);  cudaGetSymbolAddress(&pAB1,g_AB1);
    cudaGetSymbolAddress(&pT9, g_T9);   cudaGetSymbolAddress(&poff,g_off);
    cudaGetSymbolAddress(&plj, g_lj);
    cudaGetSymbolAddress(&pBM, g_pBM);  cudaGetSymbolAddress(&pBg, g_pBg);
    cudaGetSymbolAddress(&pBc, g_pBc);

    cudaFuncSetAttribute(k_iter, cudaFuncAttributeMaxDynamicSharedMemorySize,
                         SMEM_ITER);

    k_T9  <<<1, 160>>>(gw, (float*)pT9);
    k_csr <<<1, 256>>>(eidx, E, (int*)poff, (int*)plj);
    k_prepB<<<(9*16*4  + 255)/256, 256>>>(wm, (uint4*)pBM, 16, 16);
    k_prepB<<<(18*32*4 + 255)/256, 256>>>(wg, (uint4*)pBg, 32, 32);
    k_prepB<<<(18*16*4 + 255)/256, 256>>>(wc, (uint4*)pBc, 32, 16);

    k_convQ<<<B*NN, 256>>>(seed, (const uint4*)pBM, bm,
                           wq, bq, wk, bk, w1, (float*)pM0, (float*)pAB0);

    const float* Xc = seed;
    for (int it = 0; it < 4; it++) {
        float* Xn = (it == 3) ? out : ((it & 1) ? (float*)pXb : (float*)pXa);
        float* Mi  = (it & 1) ? (float*)pM1  : (float*)pM0;
        float* Mo  = (it & 1) ? (float*)pM0  : (float*)pM1;
        float* ABi = (it & 1) ? (float*)pAB1 : (float*)pAB0;
        float* ABo = (it & 1) ? (float*)pAB0 : (float*)pAB1;

        k_iter<<<B*NN, 256, SMEM_ITER>>>(Mi, Xc, ABi,
                        (const float*)pT9, gb, b1, w2, b2, wo, bo,
                        (const uint4*)pBg, bg,
                        (const uint4*)pBc, bc,
                        (const uint4*)pBM, bm,
                        wq, bq, wk, bk, w1,
                        (const int*)poff, (const int*)plj,
                        Xn, Mo, ABo, (it < 3) ? 1 : 0);
        Xc = Xn;
    }
}

// round 9
// speedup vs baseline: 4.0852x; 1.1115x over previous
#include <cuda_runtime.h>
#include <cuda_fp16.h>

typedef unsigned int uint;

// Problem constants (fixed by the dataset)
#define CC     16
#define NN     64
#define DQK    32
#define HIDN   64
#define MAXE   512
#define BMAX   16
#define PLANE  16384

// pixel-major split tile: [324 pixels][40 halves pitch] hi plane, then lo plane
#define TPITCH_U 20              // uints per pixel row (40 halves = 80 bytes)
#define LOU      (324*TPITCH_U)  // uint offset of lo plane
#define TILE_U   (324*TPITCH_U*2)
#define TILE_BYTES (TILE_U*4)    // 51840
#define LO_BYTES (324*80)        // byte offset of lo plane

// ---------------- scratch ----------------------------------------------------
__device__ float g_Xa [BMAX*CC*PLANE];
__device__ float g_Xb [BMAX*CC*PLANE];
__device__ float g_M0 [BMAX*CC*PLANE];
__device__ float g_M1 [BMAX*CC*PLANE];
__device__ float g_AB0[BMAX*NN*128];
__device__ float g_AB1[BMAX*NN*128];
__device__ float g_T9 [CC*9];
__device__ int   g_off[NN+1];
__device__ int   g_lj [MAXE];
// fp16-split weight fragment tables: [(ks*N + n)*4 + q] -> (b0h,b1h,b0l,b1l)
__device__ uint4 g_pBM[9*16*4];
__device__ uint4 g_pBg[18*32*4];
__device__ uint4 g_pBc[18*16*4];

__device__ __forceinline__ float sigf(float x){ return 1.f/(1.f+__expf(-x)); }

// ---------------- fp16 split helpers -----------------------------------------
__device__ __forceinline__ uint packh2(__half a, __half b){
    __half2 h = __halves2half2(a, b);
    return *reinterpret_cast<uint*>(&h);
}
__device__ __forceinline__ uint2 h2pair(float v0, float v1){
    __half h0 = __float2half_rn(v0);
    __half h1 = __float2half_rn(v1);
    __half l0 = __float2half_rn(v0 - __half2float(h0));
    __half l1 = __float2half_rn(v1 - __half2float(h1));
    uint2 r; r.x = packh2(h0, h1); r.y = packh2(l0, l1); return r;
}
__device__ __forceinline__ float2 h2rec(uint2 e){
    __half2 hh = *reinterpret_cast<__half2*>(&e.x);
    __half2 ll = *reinterpret_cast<__half2*>(&e.y);
    float2 fh = __half22float2(hh), fl = __half22float2(ll);
    return make_float2(fh.x + fl.x, fh.y + fl.y);
}

__device__ __forceinline__ void mmah(float c[4], const uint a[4], uint b0, uint b1){
    asm volatile("mma.sync.aligned.m16n8k16.row.col.f32.f16.f16.f32 "
        "{%0,%1,%2,%3},{%4,%5,%6,%7},{%8,%9},{%0,%1,%2,%3};"
        : "+f"(c[0]),"+f"(c[1]),"+f"(c[2]),"+f"(c[3])
        : "r"(a[0]),"r"(a[1]),"r"(a[2]),"r"(a[3]),"r"(b0),"r"(b1));
}

__device__ __forceinline__ void ldsm4(uint r[4], uint addr){
    asm volatile("ldmatrix.sync.aligned.m8n8.x4.shared.b16 {%0,%1,%2,%3}, [%4];"
        : "=r"(r[0]),"=r"(r[1]),"=r"(r[2]),"=r"(r[3]) : "r"(addr));
}

// ---------------- weight prepack (runs once) ----------------------------------
__global__ void k_prepB(const float* __restrict__ W, uint4* __restrict__ out,
                        int CIN, int N)
{
    int KSTEPS = CIN*9/16;
    int tot = KSTEPS*N*4;
    int i = blockIdx.x*256 + threadIdx.x;
    if (i >= tot) return;
    int q = i & 3; int t = i >> 2; int n = t % N; int ks = t / N;
    float w[4]; __half h[4], l[4];
    int kk[4] = { ks*16 + 2*q, ks*16 + 2*q + 1, ks*16 + 2*q + 8, ks*16 + 2*q + 9 };
    #pragma unroll
    for (int j = 0; j < 4; j++) {
        int k = kk[j];
        w[j] = W[n*CIN*9 + (k % CIN)*9 + (k / CIN)];
        h[j] = __float2half_rn(w[j]);
        l[j] = __float2half_rn(w[j] - __half2float(h[j]));
    }
    uint4 o;
    o.x = packh2(h[0], h[1]);
    o.y = packh2(h[2], h[3]);
    o.z = packh2(l[0], l[1]);
    o.w = packh2(l[2], l[3]);
    out[(ks*N + n)*4 + q] = o;
}

// ---------------- tile loader (pixel-major) -----------------------------------
// load ncp source channel-pairs (channels 2cp,2cp+1) into half-offset hoffU*2.
__device__ __forceinline__ void load_tile_px(uint* sTu,
        const float* __restrict__ src, int ncp, int hoffU,
        int b, int p16, int q16)
{
    int nel = 324*ncp;
    for (int i = threadIdx.x; i < nel; i += 256) {
        int cp = i / 324; int pix = i - cp*324;
        int yy = pix/18, xx = pix - yy*18;
        int ly = yy - 1, lx = xx - 1;
        float v0 = 0.f, v1 = 0.f;
        if ((unsigned)ly < 16u && (unsigned)lx < 16u) {
            const float* p = &src[((b*CC + 2*cp)*128 + p16 + ly)*128 + (q16 + lx)];
            v0 = p[0]; v1 = p[PLANE];
        }
        uint2 e = h2pair(v0, v1);
        sTu[pix*TPITCH_U + hoffU + cp]       = e.x;
        sTu[LOU + pix*TPITCH_U + hoffU + cp] = e.y;
    }
}

// ---------------- fp16 3-term conv GEMM core (ldmatrix A-frags) ----------------
// M=256 pixels (mtile = image row y, A-row = pixel x), K = CIN*9 tap-major.
template<int CIN,int NT>
__device__ __forceinline__ void mma_convh(uint sbase,
                                          const uint4* __restrict__ pB,
                                          const float* s_bias,
                                          float acc[2][NT][4])
{
    constexpr int N = NT*8;
    constexpr int KSTEPS = CIN*9/16;
    int lane = threadIdx.x & 31;
    int wid  = threadIdx.x >> 5;
    int g = lane >> 2, q = lane & 3;
    int m0 = wid*2;
    int x = lane & 15, colsel = lane >> 4;

    #pragma unroll
    for (int mm = 0; mm < 2; mm++)
        #pragma unroll
        for (int nt = 0; nt < NT; nt++) {
            float b0 = s_bias[nt*8 + q*2], b1 = s_bias[nt*8 + q*2 + 1];
            acc[mm][nt][0] = b0; acc[mm][nt][1] = b1;
            acc[mm][nt][2] = b0; acc[mm][nt][3] = b1;
        }

    #pragma unroll 1
    for (int ks = 0; ks < KSTEPS; ks++) {
        int tap = (CIN == 16) ? ks : (ks >> 1);
        int sub = (CIN == 16) ? 0  : (ks & 1);
        int ty = tap/3, tx = tap - ty*3;
        uint ah[2][4], al[2][4];
        #pragma unroll
        for (int mm = 0; mm < 2; mm++) {
            int row = (m0 + mm + ty)*18 + x + tx;
            uint addr = sbase + (uint)((row*40 + sub*16 + colsel*8)*2);
            ldsm4(ah[mm], addr);
            ldsm4(al[mm], addr + LO_BYTES);
        }
        #pragma unroll
        for (int nt = 0; nt < NT; nt++) {
            uint4 bv = pB[(ks*N + nt*8 + g)*4 + q];
            #pragma unroll
            for (int mm = 0; mm < 2; mm++) {
                mmah(acc[mm][nt], ah[mm], bv.x, bv.y);
                mmah(acc[mm][nt], ah[mm], bv.z, bv.w);
                mmah(acc[mm][nt], al[mm], bv.x, bv.y);
            }
        }
    }
}

// ---------------- setup kernels ----------------------------------------------
__global__ void k_T9(const float* __restrict__ gw, float* __restrict__ T9)
{
    int tid = threadIdx.x; if (tid >= CC*9) return;
    int c = tid / 9, cls = tid - c*9, ry = cls/3, rx = cls - ry*3;
    float s = 0.f;
    #pragma unroll
    for (int ky = 0; ky < 3; ky++) {
        if ((ry == 0 && ky == 0) || (ry == 2 && ky == 2)) continue;
        #pragma unroll
        for (int kx = 0; kx < 3; kx++) {
            if ((rx == 0 && kx == 0) || (rx == 2 && kx == 2)) continue;
            s += gw[c*9 + ky*3 + kx];
        }
    }
    T9[tid] = s;
}

__global__ void k_csr(const int* __restrict__ eidx, int E,
                      int* __restrict__ off, int* __restrict__ lj)
{
    __shared__ int se[MAXE*2];
    for (int i = threadIdx.x; i < 2*E; i += blockDim.x) se[i] = eidx[i];
    __syncthreads();
    if (threadIdx.x == 0) {
        int cnt[NN];
        for (int i = 0; i < NN; i++) cnt[i] = 0;
        for (int e = 0; e < E; e++) cnt[se[2*e]]++;
        int acc = 0;
        for (int i = 0; i < NN; i++) { off[i] = acc; acc += cnt[i]; cnt[i] = 0; }
        off[NN] = acc;
        for (int e = 0; e < E; e++) {
            int i = se[2*e];
            int s = off[i] + cnt[i]++;
            lj[s] = se[2*e + 1];
        }
    }
}

// ---------------- initial conv + mean/qk/AB kernel (seed only) ----------------
__global__ __launch_bounds__(256) void k_convQ(const float* __restrict__ X,
    const uint4* __restrict__ pBM, const float* __restrict__ bm,
    const float* __restrict__ wq, const float* __restrict__ bq,
    const float* __restrict__ wk, const float* __restrict__ bk,
    const float* __restrict__ W1,
    float* __restrict__ M, float* __restrict__ AB)
{
    int bn = blockIdx.x; int b = bn >> 6, n = bn & 63;
    int p16 = (n >> 3)*16, q16 = (n & 7)*16;
    extern __shared__ uint sTu[];
    __shared__ float s_bias[16];
    __shared__ float s_red[16][8];
    __shared__ float s_xm[16];
    __shared__ float s_qk[64];
    load_tile_px(sTu, X, 8, 0, b, p16, q16);
    if (threadIdx.x < 16) s_bias[threadIdx.x] = bm[threadIdx.x];
    __syncthreads();

    int tid = threadIdx.x;
    uint sbase = (uint)__cvta_generic_to_shared(sTu);
    {
        int y = tid >> 4, x = tid & 15;
        int w = tid >> 5;
        int pix = (y + 1)*18 + (x + 1);
        #pragma unroll 1
        for (int cp = 0; cp < 8; cp++) {
            float2 v = h2rec(make_uint2(sTu[pix*TPITCH_U + cp],
                                        sTu[LOU + pix*TPITCH_U + cp]));
            #pragma unroll
            for (int o = 16; o; o >>= 1) {
                v.x += __shfl_down_sync(0xffffffffu, v.x, o);
                v.y += __shfl_down_sync(0xffffffffu, v.y, o);
            }
            if ((tid & 31) == 0) { s_red[2*cp][w] = v.x; s_red[2*cp + 1][w] = v.y; }
        }
    }

    float acc[2][2][4];
    mma_convh<16,2>(sbase, pBM, s_bias, acc);

    int lane = tid & 31, wid = tid >> 5;
    int g = lane >> 2, q = lane & 3, m0 = wid*2;
    #pragma unroll
    for (int mm = 0; mm < 2; mm++) {
        int y = m0 + mm;
        #pragma unroll
        for (int nt = 0; nt < 2; nt++) {
            int co = nt*8 + q*2;
            int r0 = ((b*CC + co)*128 + p16 + y)*128 + q16;
            int r1 = r0 + PLANE;
            M[r0 + g]     = acc[mm][nt][0];
            M[r1 + g]     = acc[mm][nt][1];
            M[r0 + g + 8] = acc[mm][nt][2];
            M[r1 + g + 8] = acc[mm][nt][3];
        }
    }
    __syncthreads();
    if (tid < 16) {
        float s = 0.f;
        #pragma unroll
        for (int w = 0; w < 8; w++) s += s_red[tid][w];
        s_xm[tid] = s * (1.f/256.f);
    }
    __syncthreads();
    if (tid < 64) {
        int d = tid & 31;
        const float* wM = (tid < 32) ? wq : wk;
        const float* bM = (tid < 32) ? bq : bk;
        float a = bM[d];
        #pragma unroll
        for (int c = 0; c < CC; c++) a += s_xm[c]*wM[c*DQK + d];
        s_qk[tid] = a;
    }
    __syncthreads();
    if (tid < 128) {
        int t = tid & 63;
        int off = (tid < 64) ? 0 : 32;
        float a = 0.f;
        #pragma unroll
        for (int d = 0; d < 32; d++) a += s_qk[off + d]*W1[(off + d)*HIDN + t];
        AB[(b*NN + n)*128 + (tid < 64 ? 0 : 64) + t] = a;
    }
}

// ---------------- fused iteration kernel ---------------------------------------
__global__ __launch_bounds__(256,3) void k_iter(const float* __restrict__ M,
    const float* __restrict__ X, const float* __restrict__ AB,
    const float* __restrict__ T9, const float* __restrict__ gbv,
    const float* __restrict__ b1, const float* __restrict__ W2,
    const float* __restrict__ b2, const float* __restrict__ wo,
    const float* __restrict__ bo,
    const uint4* __restrict__ pBg, const float* __restrict__ bgv,
    const uint4* __restrict__ pBc, const float* __restrict__ bcv,
    const uint4* __restrict__ pBM, const float* __restrict__ bm,
    const float* __restrict__ wq, const float* __restrict__ bq,
    const float* __restrict__ wk, const float* __restrict__ bk,
    const float* __restrict__ W1,
    const int* __restrict__ off, const int* __restrict__ lj,
    float* __restrict__ Xn, float* __restrict__ Mout,
    float* __restrict__ ABout, int doTail)
{
    int bn = blockIdx.x; int b = bn >> 6, i = bn & 63;
    int p16 = (i >> 3)*16, q16 = (i & 7)*16;
    extern __shared__ uint sTu[];               // TILE_BYTES = 51840
    __shared__ float sg[4*144];
    __shared__ float sT9[144];
    __shared__ float sgb[16], s_bg[32], s_bc[16], s_bm[16];
    __shared__ float sb1[64], sb2[64], swo[64];
    __shared__ float h1s[4][64], sred[4][2], sev[4];
    __shared__ float s_red[16][8], s_xm[16], s_qk[64];
    __shared__ int sbase_n[4];

    int tid = threadIdx.x;
    int o0 = off[i], deg = off[i+1] - o0;
    uint sbase = (uint)__cvta_generic_to_shared(sTu);

    // zero agg channels 0..15 (all pixels, incl halo); load X into 16..31
    for (int t = tid; t < 324*8; t += 256) {
        int cp = t / 324, pix = t - cp*324;
        sTu[pix*TPITCH_U + cp] = 0u;
        sTu[LOU + pix*TPITCH_U + cp] = 0u;
    }
    load_tile_px(sTu, X, 8, 8, b, p16, q16);

    if (tid < 144) sT9[tid] = T9[tid];
    if (tid < 16)  sgb[tid] = gbv[tid];
    if (tid < 32)  s_bg[tid] = bgv[tid];
    if (tid < 16)  s_bc[tid] = bcv[tid];
    if (tid < 16)  s_bm[tid] = bm[tid];
    if (tid < 64)  { sb1[tid] = b1[tid]; sb2[tid] = b2[tid]; swo[tid] = wo[tid]; }
    if (tid < deg) {
        int ej = lj[o0 + tid];
        sbase_n[tid] = ((b*CC)*128 + (ej >> 3)*16)*128 + (ej & 7)*16;
    }
    float bov = bo[0];
    __syncthreads();

    // ---- edge MLP for this node's incident edges (<=4) ----
    int l = tid >> 6, t = tid & 63;
    if (l < deg) {
        int ej = lj[o0 + l];
        float a = AB[(b*NN + i)*128 + t] + AB[(b*NN + ej)*128 + 64 + t] + sb1[t];
        h1s[l][t] = fmaxf(a, 0.f);
    }
    __syncthreads();
    if (l < deg) {
        float a2 = sb2[t];
        #pragma unroll
        for (int k = 0; k < HIDN; k++) a2 += h1s[l][k]*__ldg(&W2[k*HIDN + t]);
        a2 = fmaxf(a2, 0.f);
        float part = a2*swo[t];
        #pragma unroll
        for (int o = 16; o; o >>= 1) part += __shfl_down_sync(0xffffffffu, part, o);
        if ((t & 31) == 0) sred[l][t >> 5] = part;
    }
    __syncthreads();
    if (tid < deg) sev[tid] = sred[tid][0] + sred[tid][1] + bov;
    __syncthreads();

    // ---- gate table ----
    for (int t2 = tid; t2 < deg*144; t2 += 256) {
        int le = t2 / 144, r = t2 - le*144;
        int c = r / 9;
        sg[t2] = sigf(sev[le]*sT9[r] + sgb[c]);
    }
    __syncthreads();

    // ---- segment-sum of gated messages, write split into tile ch 0..15 ----
    {
        int cg = tid >> 6, pg = tid & 63;
        int y = pg >> 2, x0 = (pg & 3)*4;
        int cy = (y == 0) ? 0 : ((y == 15) ? 2 : 1);
        int cix[4];
        #pragma unroll
        for (int k = 0; k < 4; k++) {
            int x = x0 + k;
            cix[k] = cy*3 + ((x == 0) ? 0 : ((x == 15) ? 2 : 1));
        }
        int pix = y*128 + x0;
        float av[4][4];
        #pragma unroll
        for (int cc = 0; cc < 4; cc++) {
            int c = cg*4 + cc;
            float a0=0.f,a1=0.f,a2=0.f,a3=0.f;
            for (int le = 0; le < deg; le++) {
                const float* gl = &sg[le*144 + c*9];
                float4 m = *reinterpret_cast<const float4*>(&M[sbase_n[le] + c*PLANE + pix]);
                a0 += gl[cix[0]]*m.x;
                a1 += gl[cix[1]]*m.y;
                a2 += gl[cix[2]]*m.z;
                a3 += gl[cix[3]]*m.w;
            }
            av[cc][0]=a0; av[cc][1]=a1; av[cc][2]=a2; av[cc][3]=a3;
        }
        // write 4 channels (c = cg*4..+3) x 4 pixels into pixel-major tile
        #pragma unroll
        for (int k = 0; k < 4; k++) {
            int tp = ((y + 1)*18 + (x0 + 1 + k))*TPITCH_U + 2*cg;
            uint2 p0 = h2pair(av[0][k], av[1][k]);
            uint2 p1 = h2pair(av[2][k], av[3][k]);
            *reinterpret_cast<uint2*>(&sTu[tp])       = make_uint2(p0.x, p1.x);
            *reinterpret_cast<uint2*>(&sTu[LOU + tp]) = make_uint2(p0.y, p1.y);
        }
    }
    __syncthreads();

    // ---- GRU ----
    int lane = tid & 31, wid = tid >> 5;
    int g = lane >> 2, q = lane & 3, m0 = wid*2;

    float zreg[2][2][4];
    float hreg[2][2][4];

    {   // gate conv
        float acc[2][4][4];
        mma_convh<32,4>(sbase, pBg, s_bg, acc);
        __syncthreads();
        #pragma unroll
        for (int mm = 0; mm < 2; mm++) {
            int y = m0 + mm;
            #pragma unroll
            for (int nt = 0; nt < 4; nt++) {
                int co = nt*8 + q*2;
                if (nt < 2) {
                    #pragma unroll
                    for (int rr = 0; rr < 4; rr++)
                        zreg[mm][nt][rr] = sigf(acc[mm][nt][rr]);
                } else {
                    // channels co, co+1 (>=16): r gates -> rh in place
                    #pragma unroll
                    for (int half = 0; half < 2; half++) {
                        int x = g + half*8;
                        int ti = ((y + 1)*18 + (x + 1))*TPITCH_U + co/2;
                        float2 h = h2rec(make_uint2(sTu[ti], sTu[LOU + ti]));
                        float r0 = sigf(acc[mm][nt][half*2]);
                        float r1 = sigf(acc[mm][nt][half*2 + 1]);
                        hreg[mm][nt - 2][half*2]     = h.x;
                        hreg[mm][nt - 2][half*2 + 1] = h.y;
                        uint2 e = h2pair(r0*h.x, r1*h.y);
                        sTu[ti] = e.x; sTu[LOU + ti] = e.y;
                    }
                }
            }
        }
    }
    __syncthreads();

    float xn[2][2][4];
    {   // candidate conv + update
        float acc[2][2][4];
        mma_convh<32,2>(sbase, pBc, s_bc, acc);
        #pragma unroll
        for (int mm = 0; mm < 2; mm++) {
            int y = m0 + mm;
            #pragma unroll
            for (int nt = 0; nt < 2; nt++) {
                int co = nt*8 + q*2;
                #pragma unroll
                for (int rr = 0; rr < 4; rr++) {
                    int c = co + (rr & 1);
                    int x = g + (rr >= 2 ? 8 : 0);
                    float cand = tanhf(acc[mm][nt][rr]);
                    float z = zreg[mm][nt][rr];
                    float h = hreg[mm][nt][rr];
                    float v = (1.f - z)*h + z*cand;
                    xn[mm][nt][rr] = v;
                    int idx = ((b*CC + c)*128 + p16 + y)*128 + q16 + x;
                    Xn[idx] = v;
                }
            }
        }
    }

    if (!doTail) return;

    // ---- tail: next-iteration convM + mean/qk/AB from Xn (patch-local) ----
    __syncthreads();    // all cand-conv tile reads done before overwrite
    #pragma unroll
    for (int mm = 0; mm < 2; mm++) {
        int y = m0 + mm;
        #pragma unroll
        for (int nt = 0; nt < 2; nt++) {
            int co = nt*8 + q*2;
            #pragma unroll
            for (int half = 0; half < 2; half++) {
                int x = g + half*8;
                int ti = ((y + 1)*18 + (x + 1))*TPITCH_U + co/2;
                uint2 e = h2pair(xn[mm][nt][half*2], xn[mm][nt][half*2 + 1]);
                sTu[ti] = e.x; sTu[LOU + ti] = e.y;
            }
        }
    }
    __syncthreads();

    {   // patch mean from split tile
        int y = tid >> 4, x = tid & 15;
        int w = tid >> 5;
        int pix = (y + 1)*18 + (x + 1);
        #pragma unroll 1
        for (int cp = 0; cp < 8; cp++) {
            float2 v = h2rec(make_uint2(sTu[pix*TPITCH_U + cp],
                                        sTu[LOU + pix*TPITCH_U + cp]));
            #pragma unroll
            for (int o = 16; o; o >>= 1) {
                v.x += __shfl_down_sync(0xffffffffu, v.x, o);
                v.y += __shfl_down_sync(0xffffffffu, v.y, o);
            }
            if ((tid & 31) == 0) { s_red[2*cp][w] = v.x; s_red[2*cp + 1][w] = v.y; }
        }
    }

    {   // M conv for next iteration
        float acc[2][2][4];
        mma_convh<16,2>(sbase, pBM, s_bm, acc);
        #pragma unroll
        for (int mm = 0; mm < 2; mm++) {
            int y = m0 + mm;
            #pragma unroll
            for (int nt = 0; nt < 2; nt++) {
                int co = nt*8 + q*2;
                int r0 = ((b*CC + co)*128 + p16 + y)*128 + q16;
                int r1 = r0 + PLANE;
                Mout[r0 + g]     = acc[mm][nt][0];
                Mout[r1 + g]     = acc[mm][nt][1];
                Mout[r0 + g + 8] = acc[mm][nt][2];
                Mout[r1 + g + 8] = acc[mm][nt][3];
            }
        }
    }
    __syncthreads();
    if (tid < 16) {
        float s = 0.f;
        #pragma unroll
        for (int w = 0; w < 8; w++) s += s_red[tid][w];
        s_xm[tid] = s * (1.f/256.f);
    }
    __syncthreads();
    if (tid < 64) {
        int d = tid & 31;
        const float* wM = (tid < 32) ? wq : wk;
        const float* bM = (tid < 32) ? bq : bk;
        float a = bM[d];
        #pragma unroll
        for (int c = 0; c < CC; c++) a += s_xm[c]*wM[c*DQK + d];
        s_qk[tid] = a;
    }
    __syncthreads();
    if (tid < 128) {
        int t2 = tid & 63;
        int offp = (tid < 64) ? 0 : 32;
        float a = 0.f;
        #pragma unroll
        for (int d = 0; d < 32; d++) a += s_qk[offp + d]*W1[(offp + d)*HIDN + t2];
        ABout[(b*NN + i)*128 + (tid < 64 ? 0 : 64) + t2] = a;
    }
}

// ---------------- launch ------------------------------------------------------
extern "C" void kernel_launch(void* const* d_in, const int* in_sizes, int n_in,
                              void* d_out, int out_size)
{
    const float* seed = (const float*)d_in[0];
    const int*   eidx = (const int*)  d_in[1];
    const float* wq = (const float*)d_in[2];
    const float* bq = (const float*)d_in[3];
    const float* wk = (const float*)d_in[4];
    const float* bk = (const float*)d_in[5];
    const float* wm = (const float*)d_in[6];
    const float* bm = (const float*)d_in[7];
    const float* w1 = (const float*)d_in[8];
    const float* b1 = (const float*)d_in[9];
    const float* w2 = (const float*)d_in[10];
    const float* b2 = (const float*)d_in[11];
    const float* wo = (const float*)d_in[12];
    const float* bo = (const float*)d_in[13];
    const float* gw = (const float*)d_in[14];
    const float* gb = (const float*)d_in[15];
    const float* wg = (const float*)d_in[16];
    const float* bg = (const float*)d_in[17];
    const float* wc = (const float*)d_in[18];
    const float* bc = (const float*)d_in[19];
    float* out = (float*)d_out;

    int B = in_sizes[0] / (CC*128*128);
    int E = in_sizes[1] / 2;

    void *pXa,*pXb,*pM0,*pM1,*pAB0,*pAB1,*pT9,*poff,*plj,*pBM,*pBg,*pBc;
    cudaGetSymbolAddress(&pXa, g_Xa);   cudaGetSymbolAddress(&pXb, g_Xb);
    cudaGetSymbolAddress(&pM0, g_M0);   cudaGetSymbolAddress(&pM1, g_M1);
    cudaGetSymbolAddress(&pAB0,g_AB0);  cudaGetSymbolAddress(&pAB1,g_AB1);
    cudaGetSymbolAddress(&pT9, g_T9);   cudaGetSymbolAddress(&poff,g_off);
    cudaGetSymbolAddress(&plj, g_lj);
    cudaGetSymbolAddress(&pBM, g_pBM);  cudaGetSymbolAddress(&pBg, g_pBg);
    cudaGetSymbolAddress(&pBc, g_pBc);

    cudaFuncSetAttribute(k_iter, cudaFuncAttributeMaxDynamicSharedMemorySize,
                         TILE_BYTES);
    cudaFuncSetAttribute(k_convQ, cudaFuncAttributeMaxDynamicSharedMemorySize,
                         TILE_BYTES);

    k_T9  <<<1, 160>>>(gw, (float*)pT9);
    k_csr <<<1, 256>>>(eidx, E, (int*)poff, (int*)plj);
    k_prepB<<<(9*16*4  + 255)/256, 256>>>(wm, (uint4*)pBM, 16, 16);
    k_prepB<<<(18*32*4 + 255)/256, 256>>>(wg, (uint4*)pBg, 32, 32);
    k_prepB<<<(18*16*4 + 255)/256, 256>>>(wc, (uint4*)pBc, 32, 16);

    k_convQ<<<B*NN, 256, TILE_BYTES>>>(seed, (const uint4*)pBM, bm,
                           wq, bq, wk, bk, w1, (float*)pM0, (float*)pAB0);

    const float* Xc = seed;
    for (int it = 0; it < 4; it++) {
        float* Xn = (it == 3) ? out : ((it & 1) ? (float*)pXb : (float*)pXa);
        float* Mi  = (it & 1) ? (float*)pM1  : (float*)pM0;
        float* Mo  = (it & 1) ? (float*)pM0  : (float*)pM1;
        float* ABi = (it & 1) ? (float*)pAB1 : (float*)pAB0;
        float* ABo = (it & 1) ? (float*)pAB0 : (float*)pAB1;

        k_iter<<<B*NN, 256, TILE_BYTES>>>(Mi, Xc, ABi,
                        (const float*)pT9, gb, b1, w2, b2, wo, bo,
                        (const uint4*)pBg, bg,
                        (const uint4*)pBc, bc,
                        (const uint4*)pBM, bm,
                        wq, bq, wk, bk, w1,
                        (const int*)poff, (const int*)plj,
                        Xn, Mo, ABo, (it < 3) ? 1 : 0);
        Xc = Xn;
    }
}

// round 10
// speedup vs baseline: 4.1077x; 1.0055x over previous
#include <cuda_runtime.h>
#include <cuda_fp16.h>

typedef unsigned int uint;

// Problem constants (fixed by the dataset)
#define CC     16
#define NN     64
#define DQK    32
#define HIDN   64
#define MAXE   512
#define BMAX   16
#define PLANE  16384

// pixel-major split tile: [324 pixels][40 halves pitch] hi plane, then lo plane
#define TPITCH_U 20              // uints per pixel row (40 halves = 80 bytes)
#define LOU      (324*TPITCH_U)  // uint offset of lo plane
#define TILE_U   (324*TPITCH_U*2)
#define TILE_BYTES (TILE_U*4)    // 51840
#define LO_BYTES (324*80)        // byte offset of lo plane

// ---------------- scratch ----------------------------------------------------
__device__ float g_Xa [BMAX*CC*PLANE];
__device__ float g_Xb [BMAX*CC*PLANE];
__device__ float g_M0 [BMAX*CC*PLANE];
__device__ float g_M1 [BMAX*CC*PLANE];
__device__ float g_AB0[BMAX*NN*128];
__device__ float g_AB1[BMAX*NN*128];
__device__ float g_T9 [CC*9];
__device__ int   g_off[NN+1];
__device__ int   g_lj [MAXE];
// fp16-split weight fragment tables: [(ks*N + n)*4 + q] -> (b0h,b1h,b0l,b1l)
__device__ uint4 g_pBM[9*16*4];
__device__ uint4 g_pBg[18*32*4];
__device__ uint4 g_pBc[18*16*4];

__device__ __forceinline__ float sigf(float x){ return 1.f/(1.f+__expf(-x)); }

// ---------------- fp16 split helpers -----------------------------------------
__device__ __forceinline__ uint packh2(__half a, __half b){
    __half2 h = __halves2half2(a, b);
    return *reinterpret_cast<uint*>(&h);
}
// split two floats into (hi half2, lo half2) — cvt.rn.f16x2.f32 packs both
__device__ __forceinline__ uint2 h2pair(float v0, float v1){
    __half2 h = __floats2half2_rn(v0, v1);
    float2 f = __half22float2(h);
    __half2 l = __floats2half2_rn(v0 - f.x, v1 - f.y);
    uint2 r;
    r.x = *reinterpret_cast<uint*>(&h);
    r.y = *reinterpret_cast<uint*>(&l);
    return r;
}
__device__ __forceinline__ float2 h2rec(uint2 e){
    __half2 hh = *reinterpret_cast<__half2*>(&e.x);
    __half2 ll = *reinterpret_cast<__half2*>(&e.y);
    float2 fh = __half22float2(hh), fl = __half22float2(ll);
    return make_float2(fh.x + fl.x, fh.y + fl.y);
}

__device__ __forceinline__ void mmah(float c[4], const uint a[4], uint b0, uint b1){
    asm volatile("mma.sync.aligned.m16n8k16.row.col.f32.f16.f16.f32 "
        "{%0,%1,%2,%3},{%4,%5,%6,%7},{%8,%9},{%0,%1,%2,%3};"
        : "+f"(c[0]),"+f"(c[1]),"+f"(c[2]),"+f"(c[3])
        : "r"(a[0]),"r"(a[1]),"r"(a[2]),"r"(a[3]),"r"(b0),"r"(b1));
}

__device__ __forceinline__ void ldsm4(uint r[4], uint addr){
    asm volatile("ldmatrix.sync.aligned.m8n8.x4.shared.b16 {%0,%1,%2,%3}, [%4];"
        : "=r"(r[0]),"=r"(r[1]),"=r"(r[2]),"=r"(r[3]) : "r"(addr));
}

// ---------------- weight prepack (runs once) ----------------------------------
__device__ __forceinline__ void prep_one(const float* __restrict__ W,
                                         uint4* __restrict__ out,
                                         int CIN, int N, int i)
{
    int q = i & 3; int t = i >> 2; int n = t % N; int ks = t / N;
    float w[4]; __half h[4], l[4];
    int kk[4] = { ks*16 + 2*q, ks*16 + 2*q + 1, ks*16 + 2*q + 8, ks*16 + 2*q + 9 };
    #pragma unroll
    for (int j = 0; j < 4; j++) {
        int k = kk[j];
        w[j] = W[n*CIN*9 + (k % CIN)*9 + (k / CIN)];
        h[j] = __float2half_rn(w[j]);
        l[j] = __float2half_rn(w[j] - __half2float(h[j]));
    }
    uint4 o;
    o.x = packh2(h[0], h[1]);
    o.y = packh2(h[2], h[3]);
    o.z = packh2(l[0], l[1]);
    o.w = packh2(l[2], l[3]);
    out[(ks*N + n)*4 + q] = o;
}

// all three B-tables in one launch: items [0,576) M, [576,2880) g, [2880,4032) c
__global__ void k_prepAll(const float* __restrict__ wm,
                          const float* __restrict__ wg,
                          const float* __restrict__ wc,
                          uint4* __restrict__ outM, uint4* __restrict__ outG,
                          uint4* __restrict__ outC)
{
    int i = blockIdx.x*256 + threadIdx.x;
    if (i < 576)       prep_one(wm, outM, 16, 16, i);
    else if (i < 2880) prep_one(wg, outG, 32, 32, i - 576);
    else if (i < 4032) prep_one(wc, outC, 32, 16, i - 2880);
}

// csr build + T9 table in one launch
__global__ void k_csrT9(const int* __restrict__ eidx, int E,
                        int* __restrict__ off, int* __restrict__ lj,
                        const float* __restrict__ gw, float* __restrict__ T9)
{
    __shared__ int se[MAXE*2];
    int tid = threadIdx.x;
    for (int i = tid; i < 2*E; i += 256) se[i] = eidx[i];
    if (tid < CC*9) {
        int c = tid / 9, cls = tid - c*9, ry = cls/3, rx = cls - ry*3;
        float s = 0.f;
        #pragma unroll
        for (int ky = 0; ky < 3; ky++) {
            if ((ry == 0 && ky == 0) || (ry == 2 && ky == 2)) continue;
            #pragma unroll
            for (int kx = 0; kx < 3; kx++) {
                if ((rx == 0 && kx == 0) || (rx == 2 && kx == 2)) continue;
                s += gw[c*9 + ky*3 + kx];
            }
        }
        T9[tid] = s;
    }
    __syncthreads();
    if (tid == 0) {
        int cnt[NN];
        for (int i = 0; i < NN; i++) cnt[i] = 0;
        for (int e = 0; e < E; e++) cnt[se[2*e]]++;
        int acc = 0;
        for (int i = 0; i < NN; i++) { off[i] = acc; acc += cnt[i]; cnt[i] = 0; }
        off[NN] = acc;
        for (int e = 0; e < E; e++) {
            int i = se[2*e];
            int s = off[i] + cnt[i]++;
            lj[s] = se[2*e + 1];
        }
    }
}

// ---------------- tile loader (pixel-major) -----------------------------------
__device__ __forceinline__ void load_tile_px(uint* sTu,
        const float* __restrict__ src, int ncp, int hoffU,
        int b, int p16, int q16)
{
    int nel = 324*ncp;
    for (int i = threadIdx.x; i < nel; i += 256) {
        int cp = i / 324; int pix = i - cp*324;
        int yy = pix/18, xx = pix - yy*18;
        int ly = yy - 1, lx = xx - 1;
        float v0 = 0.f, v1 = 0.f;
        if ((unsigned)ly < 16u && (unsigned)lx < 16u) {
            const float* p = &src[((b*CC + 2*cp)*128 + p16 + ly)*128 + (q16 + lx)];
            v0 = p[0]; v1 = p[PLANE];
        }
        uint2 e = h2pair(v0, v1);
        sTu[pix*TPITCH_U + hoffU + cp]       = e.x;
        sTu[LOU + pix*TPITCH_U + hoffU + cp] = e.y;
    }
}

// ---------------- fp16 3-term conv GEMM core (ldmatrix A-frags) ----------------
template<int CIN,int NT>
__device__ __forceinline__ void mma_convh(uint sbase,
                                          const uint4* __restrict__ pB,
                                          const float* s_bias,
                                          float acc[2][NT][4])
{
    constexpr int N = NT*8;
    constexpr int KSTEPS = CIN*9/16;
    int lane = threadIdx.x & 31;
    int wid  = threadIdx.x >> 5;
    int g = lane >> 2, q = lane & 3;
    int m0 = wid*2;
    int x = lane & 15, colsel = lane >> 4;

    #pragma unroll
    for (int mm = 0; mm < 2; mm++)
        #pragma unroll
        for (int nt = 0; nt < NT; nt++) {
            float b0 = s_bias[nt*8 + q*2], b1 = s_bias[nt*8 + q*2 + 1];
            acc[mm][nt][0] = b0; acc[mm][nt][1] = b1;
            acc[mm][nt][2] = b0; acc[mm][nt][3] = b1;
        }

    #pragma unroll 1
    for (int ks = 0; ks < KSTEPS; ks++) {
        int tap = (CIN == 16) ? ks : (ks >> 1);
        int sub = (CIN == 16) ? 0  : (ks & 1);
        int ty = tap/3, tx = tap - ty*3;
        uint ah[2][4], al[2][4];
        #pragma unroll
        for (int mm = 0; mm < 2; mm++) {
            int row = (m0 + mm + ty)*18 + x + tx;
            uint addr = sbase + (uint)((row*40 + sub*16 + colsel*8)*2);
            ldsm4(ah[mm], addr);
            ldsm4(al[mm], addr + LO_BYTES);
        }
        #pragma unroll
        for (int nt = 0; nt < NT; nt++) {
            uint4 bv = pB[(ks*N + nt*8 + g)*4 + q];
            #pragma unroll
            for (int mm = 0; mm < 2; mm++) {
                mmah(acc[mm][nt], ah[mm], bv.x, bv.y);
                mmah(acc[mm][nt], ah[mm], bv.z, bv.w);
                mmah(acc[mm][nt], al[mm], bv.x, bv.y);
            }
        }
    }
}

// ---------------- initial conv + mean/qk/AB kernel (seed only) ----------------
__global__ __launch_bounds__(256) void k_convQ(const float* __restrict__ X,
    const uint4* __restrict__ pBM, const float* __restrict__ bm,
    const float* __restrict__ wq, const float* __restrict__ bq,
    const float* __restrict__ wk, const float* __restrict__ bk,
    const float* __restrict__ W1,
    float* __restrict__ M, float* __restrict__ AB)
{
    int bn = blockIdx.x; int b = bn >> 6, n = bn & 63;
    int p16 = (n >> 3)*16, q16 = (n & 7)*16;
    extern __shared__ uint sTu[];
    __shared__ float s_bias[16];
    __shared__ float s_red[16][8];
    __shared__ float s_xm[16];
    __shared__ float s_qk[64];
    load_tile_px(sTu, X, 8, 0, b, p16, q16);
    if (threadIdx.x < 16) s_bias[threadIdx.x] = bm[threadIdx.x];
    __syncthreads();

    int tid = threadIdx.x;
    uint sbase = (uint)__cvta_generic_to_shared(sTu);
    {
        int y = tid >> 4, x = tid & 15;
        int w = tid >> 5;
        int pix = (y + 1)*18 + (x + 1);
        #pragma unroll 1
        for (int cp = 0; cp < 8; cp++) {
            float2 v = h2rec(make_uint2(sTu[pix*TPITCH_U + cp],
                                        sTu[LOU + pix*TPITCH_U + cp]));
            #pragma unroll
            for (int o = 16; o; o >>= 1) {
                v.x += __shfl_down_sync(0xffffffffu, v.x, o);
                v.y += __shfl_down_sync(0xffffffffu, v.y, o);
            }
            if ((tid & 31) == 0) { s_red[2*cp][w] = v.x; s_red[2*cp + 1][w] = v.y; }
        }
    }

    float acc[2][2][4];
    mma_convh<16,2>(sbase, pBM, s_bias, acc);

    int lane = tid & 31, wid = tid >> 5;
    int g = lane >> 2, q = lane & 3, m0 = wid*2;
    #pragma unroll
    for (int mm = 0; mm < 2; mm++) {
        int y = m0 + mm;
        #pragma unroll
        for (int nt = 0; nt < 2; nt++) {
            int co = nt*8 + q*2;
            int r0 = ((b*CC + co)*128 + p16 + y)*128 + q16;
            int r1 = r0 + PLANE;
            M[r0 + g]     = acc[mm][nt][0];
            M[r1 + g]     = acc[mm][nt][1];
            M[r0 + g + 8] = acc[mm][nt][2];
            M[r1 + g + 8] = acc[mm][nt][3];
        }
    }
    __syncthreads();
    if (tid < 16) {
        float s = 0.f;
        #pragma unroll
        for (int w = 0; w < 8; w++) s += s_red[tid][w];
        s_xm[tid] = s * (1.f/256.f);
    }
    __syncthreads();
    if (tid < 64) {
        int d = tid & 31;
        const float* wM = (tid < 32) ? wq : wk;
        const float* bM = (tid < 32) ? bq : bk;
        float a = bM[d];
        #pragma unroll
        for (int c = 0; c < CC; c++) a += s_xm[c]*wM[c*DQK + d];
        s_qk[tid] = a;
    }
    __syncthreads();
    if (tid < 128) {
        int t = tid & 63;
        int off = (tid < 64) ? 0 : 32;
        float a = 0.f;
        #pragma unroll
        for (int d = 0; d < 32; d++) a += s_qk[off + d]*W1[(off + d)*HIDN + t];
        AB[(b*NN + n)*128 + (tid < 64 ? 0 : 64) + t] = a;
    }
}

// ---------------- fused iteration kernel ---------------------------------------
__global__ __launch_bounds__(256,3) void k_iter(const float* __restrict__ M,
    const float* __restrict__ X, const float* __restrict__ AB,
    const float* __restrict__ T9, const float* __restrict__ gbv,
    const float* __restrict__ b1, const float* __restrict__ W2,
    const float* __restrict__ b2, const float* __restrict__ wo,
    const float* __restrict__ bo,
    const uint4* __restrict__ pBg, const float* __restrict__ bgv,
    const uint4* __restrict__ pBc, const float* __restrict__ bcv,
    const uint4* __restrict__ pBM, const float* __restrict__ bm,
    const float* __restrict__ wq, const float* __restrict__ bq,
    const float* __restrict__ wk, const float* __restrict__ bk,
    const float* __restrict__ W1,
    const int* __restrict__ off, const int* __restrict__ lj,
    float* __restrict__ Xn, float* __restrict__ Mout,
    float* __restrict__ ABout, int doTail)
{
    int bn = blockIdx.x; int b = bn >> 6, i = bn & 63;
    int p16 = (i >> 3)*16, q16 = (i & 7)*16;
    extern __shared__ uint sTu[];               // TILE_BYTES = 51840
    __shared__ float sg[4*144];
    __shared__ float sT9[144];
    __shared__ float sgb[16], s_bg[32], s_bc[16], s_bm[16];
    __shared__ float sb1[64], sb2[64], swo[64];
    __shared__ float h1s[4][64], sred[4][2], sev[4];
    __shared__ float s_red[16][8], s_xm[16], s_qk[64];
    __shared__ int sbase_n[4];

    int tid = threadIdx.x;
    int o0 = off[i], deg = off[i+1] - o0;
    uint sbase = (uint)__cvta_generic_to_shared(sTu);

    // zero agg channels 0..15 (all pixels, incl halo); load X into 16..31
    for (int t = tid; t < 324*8; t += 256) {
        int cp = t / 324, pix = t - cp*324;
        sTu[pix*TPITCH_U + cp] = 0u;
        sTu[LOU + pix*TPITCH_U + cp] = 0u;
    }
    load_tile_px(sTu, X, 8, 8, b, p16, q16);

    if (tid < 144) sT9[tid] = T9[tid];
    if (tid < 16)  sgb[tid] = gbv[tid];
    if (tid < 32)  s_bg[tid] = bgv[tid];
    if (tid < 16)  s_bc[tid] = bcv[tid];
    if (tid < 16)  s_bm[tid] = bm[tid];
    if (tid < 64)  { sb1[tid] = b1[tid]; sb2[tid] = b2[tid]; swo[tid] = wo[tid]; }
    if (tid < deg) {
        int ej = lj[o0 + tid];
        sbase_n[tid] = ((b*CC)*128 + (ej >> 3)*16)*128 + (ej & 7)*16;
    }
    float bov = bo[0];
    __syncthreads();

    // ---- edge MLP for this node's incident edges (<=4) ----
    int l = tid >> 6, t = tid & 63;
    if (l < deg) {
        int ej = lj[o0 + l];
        float a = AB[(b*NN + i)*128 + t] + AB[(b*NN + ej)*128 + 64 + t] + sb1[t];
        h1s[l][t] = fmaxf(a, 0.f);
    }
    __syncthreads();
    if (l < deg) {
        float a2 = sb2[t];
        #pragma unroll
        for (int k = 0; k < HIDN; k++) a2 += h1s[l][k]*__ldg(&W2[k*HIDN + t]);
        a2 = fmaxf(a2, 0.f);
        float part = a2*swo[t];
        #pragma unroll
        for (int o = 16; o; o >>= 1) part += __shfl_down_sync(0xffffffffu, part, o);
        if ((t & 31) == 0) sred[l][t >> 5] = part;
    }
    __syncthreads();
    if (tid < deg) sev[tid] = sred[tid][0] + sred[tid][1] + bov;
    __syncthreads();

    // ---- gate table ----
    for (int t2 = tid; t2 < deg*144; t2 += 256) {
        int le = t2 / 144, r = t2 - le*144;
        int c = r / 9;
        sg[t2] = sigf(sev[le]*sT9[r] + sgb[c]);
    }
    __syncthreads();

    // ---- segment-sum of gated messages, write split into tile ch 0..15 ----
    {
        int cg = tid >> 6, pg = tid & 63;
        int y = pg >> 2, x0 = (pg & 3)*4;
        int cy = (y == 0) ? 0 : ((y == 15) ? 2 : 1);
        int cix[4];
        #pragma unroll
        for (int k = 0; k < 4; k++) {
            int x = x0 + k;
            cix[k] = cy*3 + ((x == 0) ? 0 : ((x == 15) ? 2 : 1));
        }
        int pix = y*128 + x0;
        float av[4][4];
        #pragma unroll
        for (int cc = 0; cc < 4; cc++) {
            int c = cg*4 + cc;
            float a0=0.f,a1=0.f,a2=0.f,a3=0.f;
            for (int le = 0; le < deg; le++) {
                const float* gl = &sg[le*144 + c*9];
                float4 m = *reinterpret_cast<const float4*>(&M[sbase_n[le] + c*PLANE + pix]);
                a0 += gl[cix[0]]*m.x;
                a1 += gl[cix[1]]*m.y;
                a2 += gl[cix[2]]*m.z;
                a3 += gl[cix[3]]*m.w;
            }
            av[cc][0]=a0; av[cc][1]=a1; av[cc][2]=a2; av[cc][3]=a3;
        }
        #pragma unroll
        for (int k = 0; k < 4; k++) {
            int tp = ((y + 1)*18 + (x0 + 1 + k))*TPITCH_U + 2*cg;
            uint2 p0 = h2pair(av[0][k], av[1][k]);
            uint2 p1 = h2pair(av[2][k], av[3][k]);
            *reinterpret_cast<uint2*>(&sTu[tp])       = make_uint2(p0.x, p1.x);
            *reinterpret_cast<uint2*>(&sTu[LOU + tp]) = make_uint2(p0.y, p1.y);
        }
    }
    __syncthreads();

    // ---- GRU ----
    int lane = tid & 31, wid = tid >> 5;
    int g = lane >> 2, q = lane & 3, m0 = wid*2;

    float zreg[2][2][4];
    float hreg[2][2][4];

    {   // gate conv
        float acc[2][4][4];
        mma_convh<32,4>(sbase, pBg, s_bg, acc);
        __syncthreads();
        #pragma unroll
        for (int mm = 0; mm < 2; mm++) {
            int y = m0 + mm;
            #pragma unroll
            for (int nt = 0; nt < 4; nt++) {
                int co = nt*8 + q*2;
                if (nt < 2) {
                    #pragma unroll
                    for (int rr = 0; rr < 4; rr++)
                        zreg[mm][nt][rr] = sigf(acc[mm][nt][rr]);
                } else {
                    // channels co, co+1 (>=16): r gates -> rh in place
                    #pragma unroll
                    for (int half = 0; half < 2; half++) {
                        int x = g + half*8;
                        int ti = ((y + 1)*18 + (x + 1))*TPITCH_U + co/2;
                        float2 h = h2rec(make_uint2(sTu[ti], sTu[LOU + ti]));
                        float r0 = sigf(acc[mm][nt][half*2]);
                        float r1 = sigf(acc[mm][nt][half*2 + 1]);
                        hreg[mm][nt - 2][half*2]     = h.x;
                        hreg[mm][nt - 2][half*2 + 1] = h.y;
                        uint2 e = h2pair(r0*h.x, r1*h.y);
                        sTu[ti] = e.x; sTu[LOU + ti] = e.y;
                    }
                }
            }
        }
    }
    __syncthreads();

    {   // candidate conv + update (+ tile refill for tail)
        float acc[2][2][4];
        mma_convh<32,2>(sbase, pBc, s_bc, acc);
        __syncthreads();   // all warps' tile reads done before tile overwrite
        #pragma unroll
        for (int mm = 0; mm < 2; mm++) {
            int y = m0 + mm;
            #pragma unroll
            for (int nt = 0; nt < 2; nt++) {
                int co = nt*8 + q*2;
                #pragma unroll
                for (int half = 0; half < 2; half++) {
                    int x = g + half*8;
                    float cand0 = tanhf(acc[mm][nt][half*2]);
                    float cand1 = tanhf(acc[mm][nt][half*2 + 1]);
                    float z0 = zreg[mm][nt][half*2], z1 = zreg[mm][nt][half*2 + 1];
                    float h0 = hreg[mm][nt][half*2], h1 = hreg[mm][nt][half*2 + 1];
                    float v0 = (1.f - z0)*h0 + z0*cand0;
                    float v1 = (1.f - z1)*h1 + z1*cand1;
                    int idx = ((b*CC + co)*128 + p16 + y)*128 + q16 + x;
                    Xn[idx]         = v0;
                    Xn[idx + PLANE] = v1;
                    if (doTail) {
                        int ti = ((y + 1)*18 + (x + 1))*TPITCH_U + co/2;
                        uint2 e = h2pair(v0, v1);
                        sTu[ti] = e.x; sTu[LOU + ti] = e.y;
                    }
                }
            }
        }
    }

    if (!doTail) return;
    __syncthreads();

    {   // patch mean from split tile
        int y = tid >> 4, x = tid & 15;
        int w = tid >> 5;
        int pix = (y + 1)*18 + (x + 1);
        #pragma unroll 1
        for (int cp = 0; cp < 8; cp++) {
            float2 v = h2rec(make_uint2(sTu[pix*TPITCH_U + cp],
                                        sTu[LOU + pix*TPITCH_U + cp]));
            #pragma unroll
            for (int o = 16; o; o >>= 1) {
                v.x += __shfl_down_sync(0xffffffffu, v.x, o);
                v.y += __shfl_down_sync(0xffffffffu, v.y, o);
            }
            if ((tid & 31) == 0) { s_red[2*cp][w] = v.x; s_red[2*cp + 1][w] = v.y; }
        }
    }

    {   // M conv for next iteration
        float acc[2][2][4];
        mma_convh<16,2>(sbase, pBM, s_bm, acc);
        #pragma unroll
        for (int mm = 0; mm < 2; mm++) {
            int y = m0 + mm;
            #pragma unroll
            for (int nt = 0; nt < 2; nt++) {
                int co = nt*8 + q*2;
                int r0 = ((b*CC + co)*128 + p16 + y)*128 + q16;
                int r1 = r0 + PLANE;
                Mout[r0 + g]     = acc[mm][nt][0];
                Mout[r1 + g]     = acc[mm][nt][1];
                Mout[r0 + g + 8] = acc[mm][nt][2];
                Mout[r1 + g + 8] = acc[mm][nt][3];
            }
        }
    }
    __syncthreads();
    if (tid < 16) {
        float s = 0.f;
        #pragma unroll
        for (int w = 0; w < 8; w++) s += s_red[tid][w];
        s_xm[tid] = s * (1.f/256.f);
    }
    __syncthreads();
    if (tid < 64) {
        int d = tid & 31;
        const float* wM = (tid < 32) ? wq : wk;
        const float* bM = (tid < 32) ? bq : bk;
        float a = bM[d];
        #pragma unroll
        for (int c = 0; c < CC; c++) a += s_xm[c]*wM[c*DQK + d];
        s_qk[tid] = a;
    }
    __syncthreads();
    if (tid < 128) {
        int t2 = tid & 63;
        int offp = (tid < 64) ? 0 : 32;
        float a = 0.f;
        #pragma unroll
        for (int d = 0; d < 32; d++) a += s_qk[offp + d]*W1[(offp + d)*HIDN + t2];
        ABout[(b*NN + i)*128 + (tid < 64 ? 0 : 64) + t2] = a;
    }
}

// ---------------- launch ------------------------------------------------------
extern "C" void kernel_launch(void* const* d_in, const int* in_sizes, int n_in,
                              void* d_out, int out_size)
{
    const float* seed = (const float*)d_in[0];
    const int*   eidx = (const int*)  d_in[1];
    const float* wq = (const float*)d_in[2];
    const float* bq = (const float*)d_in[3];
    const float* wk = (const float*)d_in[4];
    const float* bk = (const float*)d_in[5];
    const float* wm = (const float*)d_in[6];
    const float* bm = (const float*)d_in[7];
    const float* w1 = (const float*)d_in[8];
    const float* b1 = (const float*)d_in[9];
    const float* w2 = (const float*)d_in[10];
    const float* b2 = (const float*)d_in[11];
    const float* wo = (const float*)d_in[12];
    const float* bo = (const float*)d_in[13];
    const float* gw = (const float*)d_in[14];
    const float* gb = (const float*)d_in[15];
    const float* wg = (const float*)d_in[16];
    const float* bg = (const float*)d_in[17];
    const float* wc = (const float*)d_in[18];
    const float* bc = (const float*)d_in[19];
    float* out = (float*)d_out;

    int B = in_sizes[0] / (CC*128*128);
    int E = in_sizes[1] / 2;

    void *pXa,*pXb,*pM0,*pM1,*pAB0,*pAB1,*pT9,*poff,*plj,*pBM,*pBg,*pBc;
    cudaGetSymbolAddress(&pXa, g_Xa);   cudaGetSymbolAddress(&pXb, g_Xb);
    cudaGetSymbolAddress(&pM0, g_M0);   cudaGetSymbolAddress(&pM1, g_M1);
    cudaGetSymbolAddress(&pAB0,g_AB0);  cudaGetSymbolAddress(&pAB1,g_AB1);
    cudaGetSymbolAddress(&pT9, g_T9);   cudaGetSymbolAddress(&poff,g_off);
    cudaGetSymbolAddress(&plj, g_lj);
    cudaGetSymbolAddress(&pBM, g_pBM);  cudaGetSymbolAddress(&pBg, g_pBg);
    cudaGetSymbolAddress(&pBc, g_pBc);

    cudaFuncSetAttribute(k_iter, cudaFuncAttributeMaxDynamicSharedMemorySize,
                         TILE_BYTES);
    cudaFuncSetAttribute(k_convQ, cudaFuncAttributeMaxDynamicSharedMemorySize,
                         TILE_BYTES);

    // launch order fixed so ncu (-s 5 -c 1) captures a full k_iter (6th launch)
    k_csrT9 <<<1, 256>>>(eidx, E, (int*)poff, (int*)plj, gw, (float*)pT9);
    k_prepAll<<<16, 256>>>(wm, wg, wc, (uint4*)pBM, (uint4*)pBg, (uint4*)pBc);
    k_convQ<<<B*NN, 256, TILE_BYTES>>>(seed, (const uint4*)pBM, bm,
                           wq, bq, wk, bk, w1, (float*)pM0, (float*)pAB0);

    const float* Xc = seed;
    for (int it = 0; it < 4; it++) {
        float* Xn = (it == 3) ? out : ((it & 1) ? (float*)pXb : (float*)pXa);
        float* Mi  = (it & 1) ? (float*)pM1  : (float*)pM0;
        float* Mo  = (it & 1) ? (float*)pM0  : (float*)pM1;
        float* ABi = (it & 1) ? (float*)pAB1 : (float*)pAB0;
        float* ABo = (it & 1) ? (float*)pAB0 : (float*)pAB1;

        k_iter<<<B*NN, 256, TILE_BYTES>>>(Mi, Xc, ABi,
                        (const float*)pT9, gb, b1, w2, b2, wo, bo,
                        (const uint4*)pBg, bg,
                        (const uint4*)pBc, bc,
                        (const uint4*)pBM, bm,
                        wq, bq, wk, bk, w1,
                        (const int*)poff, (const int*)plj,
                        Xn, Mo, ABo, (it < 3) ? 1 : 0);
        Xc = Xn;
    }
}

// round 11
// speedup vs baseline: 4.2515x; 1.0350x over previous
#include <cuda_runtime.h>
#include <cuda_fp16.h>

typedef unsigned int uint;

// Problem constants (fixed by the dataset)
#define CC     16
#define NN     64
#define DQK    32
#define HIDN   64
#define MAXE   512
#define BMAX   16
#define PLANE  16384

// pixel-major split tile: [324 pixels][40 halves pitch] hi plane, then lo plane
#define TPITCH_U 20              // uints per pixel row (40 halves = 80 bytes)
#define LOU      (324*TPITCH_U)  // uint offset of lo plane
#define TILE_U   (324*TPITCH_U*2)
#define TILE_BYTES (TILE_U*4)    // 51840
#define LO_BYTES (324*80)        // byte offset of lo plane

// ---------------- scratch ----------------------------------------------------
__device__ float g_Xa [BMAX*CC*PLANE];
__device__ float g_Xb [BMAX*CC*PLANE];
__device__ float g_M0 [BMAX*CC*PLANE];
__device__ float g_M1 [BMAX*CC*PLANE];
__device__ float g_AB0[BMAX*NN*128];
__device__ float g_AB1[BMAX*NN*128];
__device__ float g_T9 [CC*9];
__device__ int   g_off[NN+1];
__device__ int   g_lj [MAXE];
// fp16-split weight fragment tables: [(ks*N + n)*4 + q] -> (b0h,b1h,b0l,b1l)
__device__ uint4 g_pBM[9*16*4];
__device__ uint4 g_pBg[18*32*4];
__device__ uint4 g_pBc[18*16*4];

__device__ __forceinline__ float sigf(float x){ return 1.f/(1.f+__expf(-x)); }

// ---------------- fp16 split helpers -----------------------------------------
__device__ __forceinline__ uint packh2(__half a, __half b){
    __half2 h = __halves2half2(a, b);
    return *reinterpret_cast<uint*>(&h);
}
// split two floats into (hi half2, lo half2) — cvt.rn.f16x2.f32 packs both
__device__ __forceinline__ uint2 h2pair(float v0, float v1){
    __half2 h = __floats2half2_rn(v0, v1);
    float2 f = __half22float2(h);
    __half2 l = __floats2half2_rn(v0 - f.x, v1 - f.y);
    uint2 r;
    r.x = *reinterpret_cast<uint*>(&h);
    r.y = *reinterpret_cast<uint*>(&l);
    return r;
}
__device__ __forceinline__ float2 h2rec(uint2 e){
    __half2 hh = *reinterpret_cast<__half2*>(&e.x);
    __half2 ll = *reinterpret_cast<__half2*>(&e.y);
    float2 fh = __half22float2(hh), fl = __half22float2(ll);
    return make_float2(fh.x + fl.x, fh.y + fl.y);
}

__device__ __forceinline__ void mmah(float c[4], const uint a[4], uint b0, uint b1){
    asm volatile("mma.sync.aligned.m16n8k16.row.col.f32.f16.f16.f32 "
        "{%0,%1,%2,%3},{%4,%5,%6,%7},{%8,%9},{%0,%1,%2,%3};"
        : "+f"(c[0]),"+f"(c[1]),"+f"(c[2]),"+f"(c[3])
        : "r"(a[0]),"r"(a[1]),"r"(a[2]),"r"(a[3]),"r"(b0),"r"(b1));
}

__device__ __forceinline__ void ldsm4(uint r[4], uint addr){
    asm volatile("ldmatrix.sync.aligned.m8n8.x4.shared.b16 {%0,%1,%2,%3}, [%4];"
        : "=r"(r[0]),"=r"(r[1]),"=r"(r[2]),"=r"(r[3]) : "r"(addr));
}

// ---------------- weight prepack (runs once) ----------------------------------
__device__ __forceinline__ void prep_one(const float* __restrict__ W,
                                         uint4* __restrict__ out,
                                         int CIN, int N, int i)
{
    int q = i & 3; int t = i >> 2; int n = t % N; int ks = t / N;
    float w[4]; __half h[4], l[4];
    int kk[4] = { ks*16 + 2*q, ks*16 + 2*q + 1, ks*16 + 2*q + 8, ks*16 + 2*q + 9 };
    #pragma unroll
    for (int j = 0; j < 4; j++) {
        int k = kk[j];
        w[j] = W[n*CIN*9 + (k % CIN)*9 + (k / CIN)];
        h[j] = __float2half_rn(w[j]);
        l[j] = __float2half_rn(w[j] - __half2float(h[j]));
    }
    uint4 o;
    o.x = packh2(h[0], h[1]);
    o.y = packh2(h[2], h[3]);
    o.z = packh2(l[0], l[1]);
    o.w = packh2(l[2], l[3]);
    out[(ks*N + n)*4 + q] = o;
}

// all three B-tables in one launch: items [0,576) M, [576,2880) g, [2880,4032) c
__global__ void k_prepAll(const float* __restrict__ wm,
                          const float* __restrict__ wg,
                          const float* __restrict__ wc,
                          uint4* __restrict__ outM, uint4* __restrict__ outG,
                          uint4* __restrict__ outC)
{
    int i = blockIdx.x*256 + threadIdx.x;
    if (i < 576)       prep_one(wm, outM, 16, 16, i);
    else if (i < 2880) prep_one(wg, outG, 32, 32, i - 576);
    else if (i < 4032) prep_one(wc, outC, 32, 16, i - 2880);
}

// csr build + T9 table in one launch
__global__ void k_csrT9(const int* __restrict__ eidx, int E,
                        int* __restrict__ off, int* __restrict__ lj,
                        const float* __restrict__ gw, float* __restrict__ T9)
{
    __shared__ int se[MAXE*2];
    int tid = threadIdx.x;
    for (int i = tid; i < 2*E; i += 256) se[i] = eidx[i];
    if (tid < CC*9) {
        int c = tid / 9, cls = tid - c*9, ry = cls/3, rx = cls - ry*3;
        float s = 0.f;
        #pragma unroll
        for (int ky = 0; ky < 3; ky++) {
            if ((ry == 0 && ky == 0) || (ry == 2 && ky == 2)) continue;
            #pragma unroll
            for (int kx = 0; kx < 3; kx++) {
                if ((rx == 0 && kx == 0) || (rx == 2 && kx == 2)) continue;
                s += gw[c*9 + ky*3 + kx];
            }
        }
        T9[tid] = s;
    }
    __syncthreads();
    if (tid == 0) {
        int cnt[NN];
        for (int i = 0; i < NN; i++) cnt[i] = 0;
        for (int e = 0; e < E; e++) cnt[se[2*e]]++;
        int acc = 0;
        for (int i = 0; i < NN; i++) { off[i] = acc; acc += cnt[i]; cnt[i] = 0; }
        off[NN] = acc;
        for (int e = 0; e < E; e++) {
            int i = se[2*e];
            int s = off[i] + cnt[i]++;
            lj[s] = se[2*e + 1];
        }
    }
}

// ---------------- tile loader (pixel-major) -----------------------------------
__device__ __forceinline__ void load_tile_px(uint* sTu,
        const float* __restrict__ src, int ncp, int hoffU,
        int b, int p16, int q16)
{
    int nel = 324*ncp;
    for (int i = threadIdx.x; i < nel; i += 256) {
        int cp = i / 324; int pix = i - cp*324;
        int yy = pix/18, xx = pix - yy*18;
        int ly = yy - 1, lx = xx - 1;
        float v0 = 0.f, v1 = 0.f;
        if ((unsigned)ly < 16u && (unsigned)lx < 16u) {
            const float* p = &src[((b*CC + 2*cp)*128 + p16 + ly)*128 + (q16 + lx)];
            v0 = p[0]; v1 = p[PLANE];
        }
        uint2 e = h2pair(v0, v1);
        sTu[pix*TPITCH_U + hoffU + cp]       = e.x;
        sTu[LOU + pix*TPITCH_U + hoffU + cp] = e.y;
    }
}

// ---------------- fp16 3-term conv GEMM core (ldmatrix, sw-pipelined) ----------
template<int CIN,int NT>
__device__ __forceinline__ void mma_convh(uint sbase,
                                          const uint4* __restrict__ pB,
                                          const float* s_bias,
                                          float acc[2][NT][4])
{
    constexpr int N = NT*8;
    constexpr int KSTEPS = CIN*9/16;
    int lane = threadIdx.x & 31;
    int wid  = threadIdx.x >> 5;
    int g = lane >> 2, q = lane & 3;
    int m0 = wid*2;
    int x = lane & 15, colsel = lane >> 4;

    #pragma unroll
    for (int mm = 0; mm < 2; mm++)
        #pragma unroll
        for (int nt = 0; nt < NT; nt++) {
            float b0 = s_bias[nt*8 + q*2], b1 = s_bias[nt*8 + q*2 + 1];
            acc[mm][nt][0] = b0; acc[mm][nt][1] = b1;
            acc[mm][nt][2] = b0; acc[mm][nt][3] = b1;
        }

    #pragma unroll 2
    for (int ks = 0; ks < KSTEPS; ks++) {
        int tap = (CIN == 16) ? ks : (ks >> 1);
        int sub = (CIN == 16) ? 0  : (ks & 1);
        int ty = tap/3, tx = tap - ty*3;
        uint ah[2][4], al[2][4];
        uint4 bv[NT];
        #pragma unroll
        for (int mm = 0; mm < 2; mm++) {
            int row = (m0 + mm + ty)*18 + x + tx;
            uint addr = sbase + (uint)((row*40 + sub*16 + colsel*8)*2);
            ldsm4(ah[mm], addr);
            ldsm4(al[mm], addr + LO_BYTES);
        }
        #pragma unroll
        for (int nt = 0; nt < NT; nt++)
            bv[nt] = pB[(ks*N + nt*8 + g)*4 + q];
        #pragma unroll
        for (int nt = 0; nt < NT; nt++) {
            #pragma unroll
            for (int mm = 0; mm < 2; mm++) {
                mmah(acc[mm][nt], ah[mm], bv[nt].x, bv[nt].y);
                mmah(acc[mm][nt], ah[mm], bv[nt].z, bv[nt].w);
                mmah(acc[mm][nt], al[mm], bv[nt].x, bv[nt].y);
            }
        }
    }
}

// ---------------- initial conv + mean/qk/AB kernel (seed only) ----------------
__global__ __launch_bounds__(256) void k_convQ(const float* __restrict__ X,
    const uint4* __restrict__ pBM, const float* __restrict__ bm,
    const float* __restrict__ wq, const float* __restrict__ bq,
    const float* __restrict__ wk, const float* __restrict__ bk,
    const float* __restrict__ W1,
    float* __restrict__ M, float* __restrict__ AB)
{
    int bn = blockIdx.x; int b = bn >> 6, n = bn & 63;
    int p16 = (n >> 3)*16, q16 = (n & 7)*16;
    extern __shared__ uint sTu[];
    __shared__ float s_bias[16];
    __shared__ float s_red[16][8];
    __shared__ float s_xm[16];
    __shared__ float s_qk[64];
    load_tile_px(sTu, X, 8, 0, b, p16, q16);
    if (threadIdx.x < 16) s_bias[threadIdx.x] = bm[threadIdx.x];
    __syncthreads();

    int tid = threadIdx.x;
    uint sbase = (uint)__cvta_generic_to_shared(sTu);
    {
        int y = tid >> 4, x = tid & 15;
        int w = tid >> 5;
        int pix = (y + 1)*18 + (x + 1);
        #pragma unroll 1
        for (int cp = 0; cp < 8; cp++) {
            float2 v = h2rec(make_uint2(sTu[pix*TPITCH_U + cp],
                                        sTu[LOU + pix*TPITCH_U + cp]));
            #pragma unroll
            for (int o = 16; o; o >>= 1) {
                v.x += __shfl_down_sync(0xffffffffu, v.x, o);
                v.y += __shfl_down_sync(0xffffffffu, v.y, o);
            }
            if ((tid & 31) == 0) { s_red[2*cp][w] = v.x; s_red[2*cp + 1][w] = v.y; }
        }
    }

    float acc[2][2][4];
    mma_convh<16,2>(sbase, pBM, s_bias, acc);

    int lane = tid & 31, wid = tid >> 5;
    int g = lane >> 2, q = lane & 3, m0 = wid*2;
    #pragma unroll
    for (int mm = 0; mm < 2; mm++) {
        int y = m0 + mm;
        #pragma unroll
        for (int nt = 0; nt < 2; nt++) {
            int co = nt*8 + q*2;
            int r0 = ((b*CC + co)*128 + p16 + y)*128 + q16;
            int r1 = r0 + PLANE;
            M[r0 + g]     = acc[mm][nt][0];
            M[r1 + g]     = acc[mm][nt][1];
            M[r0 + g + 8] = acc[mm][nt][2];
            M[r1 + g + 8] = acc[mm][nt][3];
        }
    }
    __syncthreads();
    if (tid < 16) {
        float s = 0.f;
        #pragma unroll
        for (int w = 0; w < 8; w++) s += s_red[tid][w];
        s_xm[tid] = s * (1.f/256.f);
    }
    __syncthreads();
    if (tid < 64) {
        int d = tid & 31;
        const float* wM = (tid < 32) ? wq : wk;
        const float* bM = (tid < 32) ? bq : bk;
        float a = bM[d];
        #pragma unroll
        for (int c = 0; c < CC; c++) a += s_xm[c]*wM[c*DQK + d];
        s_qk[tid] = a;
    }
    __syncthreads();
    if (tid < 128) {
        int t = tid & 63;
        int off = (tid < 64) ? 0 : 32;
        float a = 0.f;
        #pragma unroll
        for (int d = 0; d < 32; d++) a += s_qk[off + d]*W1[(off + d)*HIDN + t];
        AB[(b*NN + n)*128 + (tid < 64 ? 0 : 64) + t] = a;
    }
}

// ---------------- fused iteration kernel ---------------------------------------
__global__ __launch_bounds__(256,3) void k_iter(const float* __restrict__ M,
    const float* __restrict__ X, const float* __restrict__ AB,
    const float* __restrict__ T9, const float* __restrict__ gbv,
    const float* __restrict__ b1, const float* __restrict__ W2,
    const float* __restrict__ b2, const float* __restrict__ wo,
    const float* __restrict__ bo,
    const uint4* __restrict__ pBg, const float* __restrict__ bgv,
    const uint4* __restrict__ pBc, const float* __restrict__ bcv,
    const uint4* __restrict__ pBM, const float* __restrict__ bm,
    const float* __restrict__ wq, const float* __restrict__ bq,
    const float* __restrict__ wk, const float* __restrict__ bk,
    const float* __restrict__ W1,
    const int* __restrict__ off, const int* __restrict__ lj,
    float* __restrict__ Xn, float* __restrict__ Mout,
    float* __restrict__ ABout, int doTail)
{
    int bn = blockIdx.x; int b = bn >> 6, i = bn & 63;
    int p16 = (i >> 3)*16, q16 = (i & 7)*16;
    extern __shared__ uint sTu[];               // TILE_BYTES = 51840
    __shared__ float sg[4*144];
    __shared__ float sT9[144];
    __shared__ float sgb[16], s_bg[32], s_bc[16], s_bm[16];
    __shared__ float sb1[64], sb2[64], swo[64];
    __shared__ float h1s[4][64], sred[4][2], sev[4];
    __shared__ float s_red[16][8], s_xm[16], s_qk[64];
    __shared__ int sbase_n[4];

    int tid = threadIdx.x;
    int o0 = off[i], deg = off[i+1] - o0;
    uint sbase = (uint)__cvta_generic_to_shared(sTu);

    // zero agg channels 0..15 (all pixels, incl halo); load X into 16..31
    for (int t = tid; t < 324*8; t += 256) {
        int cp = t / 324, pix = t - cp*324;
        sTu[pix*TPITCH_U + cp] = 0u;
        sTu[LOU + pix*TPITCH_U + cp] = 0u;
    }
    load_tile_px(sTu, X, 8, 8, b, p16, q16);

    if (tid < 144) sT9[tid] = T9[tid];
    if (tid < 16)  sgb[tid] = gbv[tid];
    if (tid < 32)  s_bg[tid] = bgv[tid];
    if (tid < 16)  s_bc[tid] = bcv[tid];
    if (tid < 16)  s_bm[tid] = bm[tid];
    if (tid < 64)  { sb1[tid] = b1[tid]; sb2[tid] = b2[tid]; swo[tid] = wo[tid]; }
    if (tid < deg) {
        int ej = lj[o0 + tid];
        sbase_n[tid] = ((b*CC)*128 + (ej >> 3)*16)*128 + (ej & 7)*16;
    }
    float bov = bo[0];
    __syncthreads();

    // ---- edge MLP for this node's incident edges (<=4) ----
    int l = tid >> 6, t = tid & 63;
    if (l < deg) {
        int ej = lj[o0 + l];
        float a = AB[(b*NN + i)*128 + t] + AB[(b*NN + ej)*128 + 64 + t] + sb1[t];
        h1s[l][t] = fmaxf(a, 0.f);
    }
    __syncthreads();
    if (l < deg) {
        float a2 = sb2[t];
        #pragma unroll
        for (int k = 0; k < HIDN; k++) a2 += h1s[l][k]*__ldg(&W2[k*HIDN + t]);
        a2 = fmaxf(a2, 0.f);
        float part = a2*swo[t];
        #pragma unroll
        for (int o = 16; o; o >>= 1) part += __shfl_down_sync(0xffffffffu, part, o);
        if ((t & 31) == 0) sred[l][t >> 5] = part;
    }
    __syncthreads();
    if (tid < deg) sev[tid] = sred[tid][0] + sred[tid][1] + bov;
    __syncthreads();

    // ---- gate table ----
    for (int t2 = tid; t2 < deg*144; t2 += 256) {
        int le = t2 / 144, r = t2 - le*144;
        int c = r / 9;
        sg[t2] = sigf(sev[le]*sT9[r] + sgb[c]);
    }
    __syncthreads();

    // ---- segment-sum of gated messages, write split into tile ch 0..15 ----
    {
        int cg = tid >> 6, pg = tid & 63;
        int y = pg >> 2, x0 = (pg & 3)*4;
        int cy = (y == 0) ? 0 : ((y == 15) ? 2 : 1);
        int cix[4];
        #pragma unroll
        for (int k = 0; k < 4; k++) {
            int x = x0 + k;
            cix[k] = cy*3 + ((x == 0) ? 0 : ((x == 15) ? 2 : 1));
        }
        int pix = y*128 + x0;
        float av[4][4];
        #pragma unroll
        for (int cc = 0; cc < 4; cc++) {
            int c = cg*4 + cc;
            float a0=0.f,a1=0.f,a2=0.f,a3=0.f;
            for (int le = 0; le < deg; le++) {
                const float* gl = &sg[le*144 + c*9];
                float4 m = *reinterpret_cast<const float4*>(&M[sbase_n[le] + c*PLANE + pix]);
                a0 += gl[cix[0]]*m.x;
                a1 += gl[cix[1]]*m.y;
                a2 += gl[cix[2]]*m.z;
                a3 += gl[cix[3]]*m.w;
            }
            av[cc][0]=a0; av[cc][1]=a1; av[cc][2]=a2; av[cc][3]=a3;
        }
        #pragma unroll
        for (int k = 0; k < 4; k++) {
            int tp = ((y + 1)*18 + (x0 + 1 + k))*TPITCH_U + 2*cg;
            uint2 p0 = h2pair(av[0][k], av[1][k]);
            uint2 p1 = h2pair(av[2][k], av[3][k]);
            *reinterpret_cast<uint2*>(&sTu[tp])       = make_uint2(p0.x, p1.x);
            *reinterpret_cast<uint2*>(&sTu[LOU + tp]) = make_uint2(p0.y, p1.y);
        }
    }
    __syncthreads();

    // ---- GRU ----
    int lane = tid & 31, wid = tid >> 5;
    int g = lane >> 2, q = lane & 3, m0 = wid*2;

    float zreg[2][2][4];
    float hreg[2][2][4];

    {   // gate conv
        float acc[2][4][4];
        mma_convh<32,4>(sbase, pBg, s_bg, acc);
        __syncthreads();
        #pragma unroll
        for (int mm = 0; mm < 2; mm++) {
            int y = m0 + mm;
            #pragma unroll
            for (int nt = 0; nt < 4; nt++) {
                int co = nt*8 + q*2;
                if (nt < 2) {
                    #pragma unroll
                    for (int rr = 0; rr < 4; rr++)
                        zreg[mm][nt][rr] = sigf(acc[mm][nt][rr]);
                } else {
                    // channels co, co+1 (>=16): r gates -> rh in place
                    #pragma unroll
                    for (int half = 0; half < 2; half++) {
                        int x = g + half*8;
                        int ti = ((y + 1)*18 + (x + 1))*TPITCH_U + co/2;
                        float2 h = h2rec(make_uint2(sTu[ti], sTu[LOU + ti]));
                        float r0 = sigf(acc[mm][nt][half*2]);
                        float r1 = sigf(acc[mm][nt][half*2 + 1]);
                        hreg[mm][nt - 2][half*2]     = h.x;
                        hreg[mm][nt - 2][half*2 + 1] = h.y;
                        uint2 e = h2pair(r0*h.x, r1*h.y);
                        sTu[ti] = e.x; sTu[LOU + ti] = e.y;
                    }
                }
            }
        }
    }
    __syncthreads();

    {   // candidate conv + update (+ tile refill for tail)
        float acc[2][2][4];
        mma_convh<32,2>(sbase, pBc, s_bc, acc);
        __syncthreads();   // all warps' tile reads done before tile overwrite
        #pragma unroll
        for (int mm = 0; mm < 2; mm++) {
            int y = m0 + mm;
            #pragma unroll
            for (int nt = 0; nt < 2; nt++) {
                int co = nt*8 + q*2;
                #pragma unroll
                for (int half = 0; half < 2; half++) {
                    int x = g + half*8;
                    float cand0 = tanhf(acc[mm][nt][half*2]);
                    float cand1 = tanhf(acc[mm][nt][half*2 + 1]);
                    float z0 = zreg[mm][nt][half*2], z1 = zreg[mm][nt][half*2 + 1];
                    float h0 = hreg[mm][nt][half*2], h1 = hreg[mm][nt][half*2 + 1];
                    float v0 = (1.f - z0)*h0 + z0*cand0;
                    float v1 = (1.f - z1)*h1 + z1*cand1;
                    int idx = ((b*CC + co)*128 + p16 + y)*128 + q16 + x;
                    Xn[idx]         = v0;
                    Xn[idx + PLANE] = v1;
                    if (doTail) {
                        int ti = ((y + 1)*18 + (x + 1))*TPITCH_U + co/2;
                        uint2 e = h2pair(v0, v1);
                        sTu[ti] = e.x; sTu[LOU + ti] = e.y;
                    }
                }
            }
        }
    }

    if (!doTail) return;
    __syncthreads();

    {   // patch mean from split tile
        int y = tid >> 4, x = tid & 15;
        int w = tid >> 5;
        int pix = (y + 1)*18 + (x + 1);
        #pragma unroll 1
        for (int cp = 0; cp < 8; cp++) {
            float2 v = h2rec(make_uint2(sTu[pix*TPITCH_U + cp],
                                        sTu[LOU + pix*TPITCH_U + cp]));
            #pragma unroll
            for (int o = 16; o; o >>= 1) {
                v.x += __shfl_down_sync(0xffffffffu, v.x, o);
                v.y += __shfl_down_sync(0xffffffffu, v.y, o);
            }
            if ((tid & 31) == 0) { s_red[2*cp][w] = v.x; s_red[2*cp + 1][w] = v.y; }
        }
    }

    {   // M conv for next iteration
        float acc[2][2][4];
        mma_convh<16,2>(sbase, pBM, s_bm, acc);
        #pragma unroll
        for (int mm = 0; mm < 2; mm++) {
            int y = m0 + mm;
            #pragma unroll
            for (int nt = 0; nt < 2; nt++) {
                int co = nt*8 + q*2;
                int r0 = ((b*CC + co)*128 + p16 + y)*128 + q16;
                int r1 = r0 + PLANE;
                Mout[r0 + g]     = acc[mm][nt][0];
                Mout[r1 + g]     = acc[mm][nt][1];
                Mout[r0 + g + 8] = acc[mm][nt][2];
                Mout[r1 + g + 8] = acc[mm][nt][3];
            }
        }
    }
    __syncthreads();
    if (tid < 16) {
        float s = 0.f;
        #pragma unroll
        for (int w = 0; w < 8; w++) s += s_red[tid][w];
        s_xm[tid] = s * (1.f/256.f);
    }
    __syncthreads();
    if (tid < 64) {
        int d = tid & 31;
        const float* wM = (tid < 32) ? wq : wk;
        const float* bM = (tid < 32) ? bq : bk;
        float a = bM[d];
        #pragma unroll
        for (int c = 0; c < CC; c++) a += s_xm[c]*wM[c*DQK + d];
        s_qk[tid] = a;
    }
    __syncthreads();
    if (tid < 128) {
        int t2 = tid & 63;
        int offp = (tid < 64) ? 0 : 32;
        float a = 0.f;
        #pragma unroll
        for (int d = 0; d < 32; d++) a += s_qk[offp + d]*W1[(offp + d)*HIDN + t2];
        ABout[(b*NN + i)*128 + (tid < 64 ? 0 : 64) + t2] = a;
    }
}

// ---------------- launch ------------------------------------------------------
extern "C" void kernel_launch(void* const* d_in, const int* in_sizes, int n_in,
                              void* d_out, int out_size)
{
    const float* seed = (const float*)d_in[0];
    const int*   eidx = (const int*)  d_in[1];
    const float* wq = (const float*)d_in[2];
    const float* bq = (const float*)d_in[3];
    const float* wk = (const float*)d_in[4];
    const float* bk = (const float*)d_in[5];
    const float* wm = (const float*)d_in[6];
    const float* bm = (const float*)d_in[7];
    const float* w1 = (const float*)d_in[8];
    const float* b1 = (const float*)d_in[9];
    const float* w2 = (const float*)d_in[10];
    const float* b2 = (const float*)d_in[11];
    const float* wo = (const float*)d_in[12];
    const float* bo = (const float*)d_in[13];
    const float* gw = (const float*)d_in[14];
    const float* gb = (const float*)d_in[15];
    const float* wg = (const float*)d_in[16];
    const float* bg = (const float*)d_in[17];
    const float* wc = (const float*)d_in[18];
    const float* bc = (const float*)d_in[19];
    float* out = (float*)d_out;

    int B = in_sizes[0] / (CC*128*128);
    int E = in_sizes[1] / 2;

    void *pXa,*pXb,*pM0,*pM1,*pAB0,*pAB1,*pT9,*poff,*plj,*pBM,*pBg,*pBc;
    cudaGetSymbolAddress(&pXa, g_Xa);   cudaGetSymbolAddress(&pXb, g_Xb);
    cudaGetSymbolAddress(&pM0, g_M0);   cudaGetSymbolAddress(&pM1, g_M1);
    cudaGetSymbolAddress(&pAB0,g_AB0);  cudaGetSymbolAddress(&pAB1,g_AB1);
    cudaGetSymbolAddress(&pT9, g_T9);   cudaGetSymbolAddress(&poff,g_off);
    cudaGetSymbolAddress(&plj, g_lj);
    cudaGetSymbolAddress(&pBM, g_pBM);  cudaGetSymbolAddress(&pBg, g_pBg);
    cudaGetSymbolAddress(&pBc, g_pBc);

    cudaFuncSetAttribute(k_iter, cudaFuncAttributeMaxDynamicSharedMemorySize,
                         TILE_BYTES);
    cudaFuncSetAttribute(k_convQ, cudaFuncAttributeMaxDynamicSharedMemorySize,
                         TILE_BYTES);

    // launch order fixed so ncu (-s 5 -c 1) captures a full k_iter (6th launch)
    k_csrT9 <<<1, 256>>>(eidx, E, (int*)poff, (int*)plj, gw, (float*)pT9);
    k_prepAll<<<16, 256>>>(wm, wg, wc, (uint4*)pBM, (uint4*)pBg, (uint4*)pBc);
    k_convQ<<<B*NN, 256, TILE_BYTES>>>(seed, (const uint4*)pBM, bm,
                           wq, bq, wk, bk, w1, (float*)pM0, (float*)pAB0);

    const float* Xc = seed;
    for (int it = 0; it < 4; it++) {
        float* Xn = (it == 3) ? out : ((it & 1) ? (float*)pXb : (float*)pXa);
        float* Mi  = (it & 1) ? (float*)pM1  : (float*)pM0;
        float* Mo  = (it & 1) ? (float*)pM0  : (float*)pM1;
        float* ABi = (it & 1) ? (float*)pAB1 : (float*)pAB0;
        float* ABo = (it & 1) ? (float*)pAB0 : (float*)pAB1;

        k_iter<<<B*NN, 256, TILE_BYTES>>>(Mi, Xc, ABi,
                        (const float*)pT9, gb, b1, w2, b2, wo, bo,
                        (const uint4*)pBg, bg,
                        (const uint4*)pBc, bc,
                        (const uint4*)pBM, bm,
                        wq, bq, wk, bk, w1,
                        (const int*)poff, (const int*)plj,
                        Xn, Mo, ABo, (it < 3) ? 1 : 0);
        Xc = Xn;
    }
}

// round 12
// speedup vs baseline: 4.3080x; 1.0133x over previous
#include <cuda_runtime.h>
#include <cuda_fp16.h>

typedef unsigned int uint;

// Problem constants (fixed by the dataset)
#define CC     16
#define NN     64
#define DQK    32
#define HIDN   64
#define MAXE   512
#define BMAX   16
#define PLANE  16384

// pixel-major split tile: [324 pixels][40 halves pitch] hi plane, then lo plane
#define TPITCH_U 20              // uints per pixel row (40 halves = 80 bytes)
#define LOU      (324*TPITCH_U)  // uint offset of lo plane
#define TILE_U   (324*TPITCH_U*2)
#define TILE_BYTES (TILE_U*4)    // 51840
#define LO_BYTES (324*80)        // byte offset of lo plane

// ---------------- scratch ----------------------------------------------------
__device__ float g_Xa [BMAX*CC*PLANE];
__device__ float g_Xb [BMAX*CC*PLANE];
__device__ float g_M0 [BMAX*CC*PLANE];
__device__ float g_M1 [BMAX*CC*PLANE];
__device__ float g_AB0[BMAX*NN*128];
__device__ float g_AB1[BMAX*NN*128];
__device__ float g_T9 [CC*9];
__device__ int   g_off[NN+1];
__device__ int   g_lj [MAXE];
// fp16-split weight fragment tables: [(ks*N + n)*4 + q] -> (b0h,b1h,b0l,b1l)
__device__ uint4 g_pBM[9*16*4];
__device__ uint4 g_pBg[18*32*4];
__device__ uint4 g_pBc[18*16*4];

__device__ __forceinline__ float sigf(float x){ return 1.f/(1.f+__expf(-x)); }

// ---------------- fp16 split helpers -----------------------------------------
__device__ __forceinline__ uint packh2(__half a, __half b){
    __half2 h = __halves2half2(a, b);
    return *reinterpret_cast<uint*>(&h);
}
// split two floats into (hi half2, lo half2) — cvt.rn.f16x2.f32 packs both
__device__ __forceinline__ uint2 h2pair(float v0, float v1){
    __half2 h = __floats2half2_rn(v0, v1);
    float2 f = __half22float2(h);
    __half2 l = __floats2half2_rn(v0 - f.x, v1 - f.y);
    uint2 r;
    r.x = *reinterpret_cast<uint*>(&h);
    r.y = *reinterpret_cast<uint*>(&l);
    return r;
}
__device__ __forceinline__ float2 h2rec(uint2 e){
    __half2 hh = *reinterpret_cast<__half2*>(&e.x);
    __half2 ll = *reinterpret_cast<__half2*>(&e.y);
    float2 fh = __half22float2(hh), fl = __half22float2(ll);
    return make_float2(fh.x + fl.x, fh.y + fl.y);
}

__device__ __forceinline__ void mmah(float c[4], const uint a[4], uint b0, uint b1){
    asm volatile("mma.sync.aligned.m16n8k16.row.col.f32.f16.f16.f32 "
        "{%0,%1,%2,%3},{%4,%5,%6,%7},{%8,%9},{%0,%1,%2,%3};"
        : "+f"(c[0]),"+f"(c[1]),"+f"(c[2]),"+f"(c[3])
        : "r"(a[0]),"r"(a[1]),"r"(a[2]),"r"(a[3]),"r"(b0),"r"(b1));
}

__device__ __forceinline__ void ldsm4(uint r[4], uint addr){
    asm volatile("ldmatrix.sync.aligned.m8n8.x4.shared.b16 {%0,%1,%2,%3}, [%4];"
        : "=r"(r[0]),"=r"(r[1]),"=r"(r[2]),"=r"(r[3]) : "r"(addr));
}

// ---------------- weight prepack (runs once) ----------------------------------
__device__ __forceinline__ void prep_one(const float* __restrict__ W,
                                         uint4* __restrict__ out,
                                         int CIN, int N, int i)
{
    int q = i & 3; int t = i >> 2; int n = t % N; int ks = t / N;
    float w[4]; __half h[4], l[4];
    int kk[4] = { ks*16 + 2*q, ks*16 + 2*q + 1, ks*16 + 2*q + 8, ks*16 + 2*q + 9 };
    #pragma unroll
    for (int j = 0; j < 4; j++) {
        int k = kk[j];
        w[j] = W[n*CIN*9 + (k % CIN)*9 + (k / CIN)];
        h[j] = __float2half_rn(w[j]);
        l[j] = __float2half_rn(w[j] - __half2float(h[j]));
    }
    uint4 o;
    o.x = packh2(h[0], h[1]);
    o.y = packh2(h[2], h[3]);
    o.z = packh2(l[0], l[1]);
    o.w = packh2(l[2], l[3]);
    out[(ks*N + n)*4 + q] = o;
}

// all three B-tables in one launch: items [0,576) M, [576,2880) g, [2880,4032) c
__global__ void k_prepAll(const float* __restrict__ wm,
                          const float* __restrict__ wg,
                          const float* __restrict__ wc,
                          uint4* __restrict__ outM, uint4* __restrict__ outG,
                          uint4* __restrict__ outC)
{
    int i = blockIdx.x*256 + threadIdx.x;
    if (i < 576)       prep_one(wm, outM, 16, 16, i);
    else if (i < 2880) prep_one(wg, outG, 32, 32, i - 576);
    else if (i < 4032) prep_one(wc, outC, 32, 16, i - 2880);
}

// csr build + T9 table in one launch
__global__ void k_csrT9(const int* __restrict__ eidx, int E,
                        int* __restrict__ off, int* __restrict__ lj,
                        const float* __restrict__ gw, float* __restrict__ T9)
{
    __shared__ int se[MAXE*2];
    int tid = threadIdx.x;
    for (int i = tid; i < 2*E; i += 256) se[i] = eidx[i];
    if (tid < CC*9) {
        int c = tid / 9, cls = tid - c*9, ry = cls/3, rx = cls - ry*3;
        float s = 0.f;
        #pragma unroll
        for (int ky = 0; ky < 3; ky++) {
            if ((ry == 0 && ky == 0) || (ry == 2 && ky == 2)) continue;
            #pragma unroll
            for (int kx = 0; kx < 3; kx++) {
                if ((rx == 0 && kx == 0) || (rx == 2 && kx == 2)) continue;
                s += gw[c*9 + ky*3 + kx];
            }
        }
        T9[tid] = s;
    }
    __syncthreads();
    if (tid == 0) {
        int cnt[NN];
        for (int i = 0; i < NN; i++) cnt[i] = 0;
        for (int e = 0; e < E; e++) cnt[se[2*e]]++;
        int acc = 0;
        for (int i = 0; i < NN; i++) { off[i] = acc; acc += cnt[i]; cnt[i] = 0; }
        off[NN] = acc;
        for (int e = 0; e < E; e++) {
            int i = se[2*e];
            int s = off[i] + cnt[i]++;
            lj[s] = se[2*e + 1];
        }
    }
}

// ---------------- tile loader (pixel-major) -----------------------------------
__device__ __forceinline__ void load_tile_px(uint* sTu,
        const float* __restrict__ src, int ncp, int hoffU,
        int b, int p16, int q16)
{
    int nel = 324*ncp;
    for (int i = threadIdx.x; i < nel; i += 256) {
        int cp = i / 324; int pix = i - cp*324;
        int yy = pix/18, xx = pix - yy*18;
        int ly = yy - 1, lx = xx - 1;
        float v0 = 0.f, v1 = 0.f;
        if ((unsigned)ly < 16u && (unsigned)lx < 16u) {
            const float* p = &src[((b*CC + 2*cp)*128 + p16 + ly)*128 + (q16 + lx)];
            v0 = p[0]; v1 = p[PLANE];
        }
        uint2 e = h2pair(v0, v1);
        sTu[pix*TPITCH_U + hoffU + cp]       = e.x;
        sTu[LOU + pix*TPITCH_U + hoffU + cp] = e.y;
    }
}

// ---------------- fp16 conv GEMM core (ldmatrix, sw-pipelined) -----------------
// TERMS=3: exact-split (ah*bh + ah*bl + al*bh). TERMS=2: A rounded to fp16
// (ah*bh + ah*bl) — used only where output feeds a saturating nonlinearity.
template<int CIN,int NT,int TERMS>
__device__ __forceinline__ void mma_convh(uint sbase,
                                          const uint4* __restrict__ pB,
                                          const float* s_bias,
                                          float acc[2][NT][4])
{
    constexpr int N = NT*8;
    constexpr int KSTEPS = CIN*9/16;
    int lane = threadIdx.x & 31;
    int wid  = threadIdx.x >> 5;
    int g = lane >> 2, q = lane & 3;
    int m0 = wid*2;
    int x = lane & 15, colsel = lane >> 4;

    #pragma unroll
    for (int mm = 0; mm < 2; mm++)
        #pragma unroll
        for (int nt = 0; nt < NT; nt++) {
            float b0 = s_bias[nt*8 + q*2], b1 = s_bias[nt*8 + q*2 + 1];
            acc[mm][nt][0] = b0; acc[mm][nt][1] = b1;
            acc[mm][nt][2] = b0; acc[mm][nt][3] = b1;
        }

    #pragma unroll 2
    for (int ks = 0; ks < KSTEPS; ks++) {
        int tap = (CIN == 16) ? ks : (ks >> 1);
        int sub = (CIN == 16) ? 0  : (ks & 1);
        int ty = tap/3, tx = tap - ty*3;
        uint ah[2][4], al[2][4];
        uint4 bv[NT];
        #pragma unroll
        for (int mm = 0; mm < 2; mm++) {
            int row = (m0 + mm + ty)*18 + x + tx;
            uint addr = sbase + (uint)((row*40 + sub*16 + colsel*8)*2);
            ldsm4(ah[mm], addr);
            if (TERMS == 3) ldsm4(al[mm], addr + LO_BYTES);
        }
        #pragma unroll
        for (int nt = 0; nt < NT; nt++)
            bv[nt] = pB[(ks*N + nt*8 + g)*4 + q];
        #pragma unroll
        for (int nt = 0; nt < NT; nt++) {
            #pragma unroll
            for (int mm = 0; mm < 2; mm++) {
                mmah(acc[mm][nt], ah[mm], bv[nt].x, bv[nt].y);
                mmah(acc[mm][nt], ah[mm], bv[nt].z, bv[nt].w);
                if (TERMS == 3) mmah(acc[mm][nt], al[mm], bv[nt].x, bv[nt].y);
            }
        }
    }
}

// ---------------- initial conv + mean/qk/AB kernel (seed only) ----------------
__global__ __launch_bounds__(256) void k_convQ(const float* __restrict__ X,
    const uint4* __restrict__ pBM, const float* __restrict__ bm,
    const float* __restrict__ wq, const float* __restrict__ bq,
    const float* __restrict__ wk, const float* __restrict__ bk,
    const float* __restrict__ W1,
    float* __restrict__ M, float* __restrict__ AB)
{
    int bn = blockIdx.x; int b = bn >> 6, n = bn & 63;
    int p16 = (n >> 3)*16, q16 = (n & 7)*16;
    extern __shared__ uint sTu[];
    __shared__ float s_bias[16];
    __shared__ float s_red[16][8];
    __shared__ float s_xm[16];
    __shared__ float s_qk[64];
    load_tile_px(sTu, X, 8, 0, b, p16, q16);
    if (threadIdx.x < 16) s_bias[threadIdx.x] = bm[threadIdx.x];
    __syncthreads();

    int tid = threadIdx.x;
    uint sbase = (uint)__cvta_generic_to_shared(sTu);
    {
        int y = tid >> 4, x = tid & 15;
        int w = tid >> 5;
        int pix = (y + 1)*18 + (x + 1);
        #pragma unroll 1
        for (int cp = 0; cp < 8; cp++) {
            float2 v = h2rec(make_uint2(sTu[pix*TPITCH_U + cp],
                                        sTu[LOU + pix*TPITCH_U + cp]));
            #pragma unroll
            for (int o = 16; o; o >>= 1) {
                v.x += __shfl_down_sync(0xffffffffu, v.x, o);
                v.y += __shfl_down_sync(0xffffffffu, v.y, o);
            }
            if ((tid & 31) == 0) { s_red[2*cp][w] = v.x; s_red[2*cp + 1][w] = v.y; }
        }
    }

    float acc[2][2][4];
    mma_convh<16,2,3>(sbase, pBM, s_bias, acc);

    int lane = tid & 31, wid = tid >> 5;
    int g = lane >> 2, q = lane & 3, m0 = wid*2;
    #pragma unroll
    for (int mm = 0; mm < 2; mm++) {
        int y = m0 + mm;
        #pragma unroll
        for (int nt = 0; nt < 2; nt++) {
            int co = nt*8 + q*2;
            int r0 = ((b*CC + co)*128 + p16 + y)*128 + q16;
            int r1 = r0 + PLANE;
            M[r0 + g]     = acc[mm][nt][0];
            M[r1 + g]     = acc[mm][nt][1];
            M[r0 + g + 8] = acc[mm][nt][2];
            M[r1 + g + 8] = acc[mm][nt][3];
        }
    }
    __syncthreads();
    if (tid < 16) {
        float s = 0.f;
        #pragma unroll
        for (int w = 0; w < 8; w++) s += s_red[tid][w];
        s_xm[tid] = s * (1.f/256.f);
    }
    __syncthreads();
    if (tid < 64) {
        int d = tid & 31;
        const float* wM = (tid < 32) ? wq : wk;
        const float* bM = (tid < 32) ? bq : bk;
        float a = bM[d];
        #pragma unroll
        for (int c = 0; c < CC; c++) a += s_xm[c]*wM[c*DQK + d];
        s_qk[tid] = a;
    }
    __syncthreads();
    if (tid < 128) {
        int t = tid & 63;
        int off = (tid < 64) ? 0 : 32;
        float a = 0.f;
        #pragma unroll
        for (int d = 0; d < 32; d++) a += s_qk[off + d]*W1[(off + d)*HIDN + t];
        AB[(b*NN + n)*128 + (tid < 64 ? 0 : 64) + t] = a;
    }
}

// ---------------- fused iteration kernel ---------------------------------------
__global__ __launch_bounds__(256,3) void k_iter(const float* __restrict__ M,
    const float* __restrict__ X, const float* __restrict__ AB,
    const float* __restrict__ T9, const float* __restrict__ gbv,
    const float* __restrict__ b1, const float* __restrict__ W2,
    const float* __restrict__ b2, const float* __restrict__ wo,
    const float* __restrict__ bo,
    const uint4* __restrict__ pBg, const float* __restrict__ bgv,
    const uint4* __restrict__ pBc, const float* __restrict__ bcv,
    const uint4* __restrict__ pBM, const float* __restrict__ bm,
    const float* __restrict__ wq, const float* __restrict__ bq,
    const float* __restrict__ wk, const float* __restrict__ bk,
    const float* __restrict__ W1,
    const int* __restrict__ off, const int* __restrict__ lj,
    float* __restrict__ Xn, float* __restrict__ Mout,
    float* __restrict__ ABout, int doTail)
{
    int bn = blockIdx.x; int b = bn >> 6, i = bn & 63;
    int p16 = (i >> 3)*16, q16 = (i & 7)*16;
    extern __shared__ uint sTu[];               // TILE_BYTES = 51840
    __shared__ float sg[4*144];
    __shared__ float sT9[144];
    __shared__ float sgb[16], s_bg[32], s_bc[16], s_bm[16];
    __shared__ float sb1[64], sb2[64], swo[64];
    __shared__ float h1s[4][64], sred[4][2], sev[4];
    __shared__ float s_red[16][8], s_xm[16], s_qk[64];
    __shared__ int sbase_n[4];

    int tid = threadIdx.x;
    int o0 = off[i], deg = off[i+1] - o0;
    uint sbase = (uint)__cvta_generic_to_shared(sTu);

    // zero agg channels 0..15 (all pixels, incl halo); load X into 16..31
    for (int t = tid; t < 324*8; t += 256) {
        int cp = t / 324, pix = t - cp*324;
        sTu[pix*TPITCH_U + cp] = 0u;
        sTu[LOU + pix*TPITCH_U + cp] = 0u;
    }
    load_tile_px(sTu, X, 8, 8, b, p16, q16);

    if (tid < 144) sT9[tid] = T9[tid];
    if (tid < 16)  sgb[tid] = gbv[tid];
    if (tid < 32)  s_bg[tid] = bgv[tid];
    if (tid < 16)  s_bc[tid] = bcv[tid];
    if (tid < 16)  s_bm[tid] = bm[tid];
    if (tid < 64)  { sb1[tid] = b1[tid]; sb2[tid] = b2[tid]; swo[tid] = wo[tid]; }
    if (tid < deg) {
        int ej = lj[o0 + tid];
        sbase_n[tid] = ((b*CC)*128 + (ej >> 3)*16)*128 + (ej & 7)*16;
    }
    float bov = bo[0];
    __syncthreads();

    // ---- edge MLP for this node's incident edges (<=4) ----
    int l = tid >> 6, t = tid & 63;
    if (l < deg) {
        int ej = lj[o0 + l];
        float a = AB[(b*NN + i)*128 + t] + AB[(b*NN + ej)*128 + 64 + t] + sb1[t];
        h1s[l][t] = fmaxf(a, 0.f);
    }
    __syncthreads();
    if (l < deg) {
        float a2 = sb2[t];
        #pragma unroll
        for (int k = 0; k < HIDN; k++) a2 += h1s[l][k]*__ldg(&W2[k*HIDN + t]);
        a2 = fmaxf(a2, 0.f);
        float part = a2*swo[t];
        #pragma unroll
        for (int o = 16; o; o >>= 1) part += __shfl_down_sync(0xffffffffu, part, o);
        if ((t & 31) == 0) sred[l][t >> 5] = part;
    }
    __syncthreads();
    if (tid < deg) sev[tid] = sred[tid][0] + sred[tid][1] + bov;
    __syncthreads();

    // ---- gate table ----
    for (int t2 = tid; t2 < deg*144; t2 += 256) {
        int le = t2 / 144, r = t2 - le*144;
        int c = r / 9;
        sg[t2] = sigf(sev[le]*sT9[r] + sgb[c]);
    }
    __syncthreads();

    // ---- segment-sum of gated messages, write split into tile ch 0..15 ----
    {
        int cg = tid >> 6, pg = tid & 63;
        int y = pg >> 2, x0 = (pg & 3)*4;
        int cy = (y == 0) ? 0 : ((y == 15) ? 2 : 1);
        int cix[4];
        #pragma unroll
        for (int k = 0; k < 4; k++) {
            int x = x0 + k;
            cix[k] = cy*3 + ((x == 0) ? 0 : ((x == 15) ? 2 : 1));
        }
        int pix = y*128 + x0;
        float av[4][4];
        #pragma unroll
        for (int cc = 0; cc < 4; cc++) {
            int c = cg*4 + cc;
            float a0=0.f,a1=0.f,a2=0.f,a3=0.f;
            for (int le = 0; le < deg; le++) {
                const float* gl = &sg[le*144 + c*9];
                float4 m = *reinterpret_cast<const float4*>(&M[sbase_n[le] + c*PLANE + pix]);
                a0 += gl[cix[0]]*m.x;
                a1 += gl[cix[1]]*m.y;
                a2 += gl[cix[2]]*m.z;
                a3 += gl[cix[3]]*m.w;
            }
            av[cc][0]=a0; av[cc][1]=a1; av[cc][2]=a2; av[cc][3]=a3;
        }
        #pragma unroll
        for (int k = 0; k < 4; k++) {
            int tp = ((y + 1)*18 + (x0 + 1 + k))*TPITCH_U + 2*cg;
            uint2 p0 = h2pair(av[0][k], av[1][k]);
            uint2 p1 = h2pair(av[2][k], av[3][k]);
            *reinterpret_cast<uint2*>(&sTu[tp])       = make_uint2(p0.x, p1.x);
            *reinterpret_cast<uint2*>(&sTu[LOU + tp]) = make_uint2(p0.y, p1.y);
        }
    }
    __syncthreads();

    // ---- GRU ----
    int lane = tid & 31, wid = tid >> 5;
    int g = lane >> 2, q = lane & 3, m0 = wid*2;

    float zreg[2][2][4];
    float hreg[2][2][4];

    {   // gate conv (2-term: output feeds sigmoid, error ~2^-11 damped 4x)
        float acc[2][4][4];
        mma_convh<32,4,2>(sbase, pBg, s_bg, acc);
        __syncthreads();
        #pragma unroll
        for (int mm = 0; mm < 2; mm++) {
            int y = m0 + mm;
            #pragma unroll
            for (int nt = 0; nt < 4; nt++) {
                int co = nt*8 + q*2;
                if (nt < 2) {
                    #pragma unroll
                    for (int rr = 0; rr < 4; rr++)
                        zreg[mm][nt][rr] = sigf(acc[mm][nt][rr]);
                } else {
                    // channels co, co+1 (>=16): r gates -> rh in place
                    #pragma unroll
                    for (int half = 0; half < 2; half++) {
                        int x = g + half*8;
                        int ti = ((y + 1)*18 + (x + 1))*TPITCH_U + co/2;
                        float2 h = h2rec(make_uint2(sTu[ti], sTu[LOU + ti]));
                        float r0 = sigf(acc[mm][nt][half*2]);
                        float r1 = sigf(acc[mm][nt][half*2 + 1]);
                        hreg[mm][nt - 2][half*2]     = h.x;
                        hreg[mm][nt - 2][half*2 + 1] = h.y;
                        uint2 e = h2pair(r0*h.x, r1*h.y);
                        sTu[ti] = e.x; sTu[LOU + ti] = e.y;
                    }
                }
            }
        }
    }
    __syncthreads();

    {   // candidate conv + update (+ tile refill for tail)
        float acc[2][2][4];
        mma_convh<32,2,3>(sbase, pBc, s_bc, acc);
        __syncthreads();   // all warps' tile reads done before tile overwrite
        #pragma unroll
        for (int mm = 0; mm < 2; mm++) {
            int y = m0 + mm;
            #pragma unroll
            for (int nt = 0; nt < 2; nt++) {
                int co = nt*8 + q*2;
                #pragma unroll
                for (int half = 0; half < 2; half++) {
                    int x = g + half*8;
                    float cand0 = tanhf(acc[mm][nt][half*2]);
                    float cand1 = tanhf(acc[mm][nt][half*2 + 1]);
                    float z0 = zreg[mm][nt][half*2], z1 = zreg[mm][nt][half*2 + 1];
                    float h0 = hreg[mm][nt][half*2], h1 = hreg[mm][nt][half*2 + 1];
                    float v0 = (1.f - z0)*h0 + z0*cand0;
                    float v1 = (1.f - z1)*h1 + z1*cand1;
                    int idx = ((b*CC + co)*128 + p16 + y)*128 + q16 + x;
                    Xn[idx]         = v0;
                    Xn[idx + PLANE] = v1;
                    if (doTail) {
                        int ti = ((y + 1)*18 + (x + 1))*TPITCH_U + co/2;
                        uint2 e = h2pair(v0, v1);
                        sTu[ti] = e.x; sTu[LOU + ti] = e.y;
                    }
                }
            }
        }
    }

    if (!doTail) return;
    __syncthreads();

    {   // patch mean from split tile
        int y = tid >> 4, x = tid & 15;
        int w = tid >> 5;
        int pix = (y + 1)*18 + (x + 1);
        #pragma unroll 1
        for (int cp = 0; cp < 8; cp++) {
            float2 v = h2rec(make_uint2(sTu[pix*TPITCH_U + cp],
                                        sTu[LOU + pix*TPITCH_U + cp]));
            #pragma unroll
            for (int o = 16; o; o >>= 1) {
                v.x += __shfl_down_sync(0xffffffffu, v.x, o);
                v.y += __shfl_down_sync(0xffffffffu, v.y, o);
            }
            if ((tid & 31) == 0) { s_red[2*cp][w] = v.x; s_red[2*cp + 1][w] = v.y; }
        }
    }

    {   // M conv for next iteration
        float acc[2][2][4];
        mma_convh<16,2,3>(sbase, pBM, s_bm, acc);
        #pragma unroll
        for (int mm = 0; mm < 2; mm++) {
            int y = m0 + mm;
            #pragma unroll
            for (int nt = 0; nt < 2; nt++) {
                int co = nt*8 + q*2;
                int r0 = ((b*CC + co)*128 + p16 + y)*128 + q16;
                int r1 = r0 + PLANE;
                Mout[r0 + g]     = acc[mm][nt][0];
                Mout[r1 + g]     = acc[mm][nt][1];
                Mout[r0 + g + 8] = acc[mm][nt][2];
                Mout[r1 + g + 8] = acc[mm][nt][3];
            }
        }
    }
    __syncthreads();
    if (tid < 16) {
        float s = 0.f;
        #pragma unroll
        for (int w = 0; w < 8; w++) s += s_red[tid][w];
        s_xm[tid] = s * (1.f/256.f);
    }
    __syncthreads();
    if (tid < 64) {
        int d = tid & 31;
        const float* wM = (tid < 32) ? wq : wk;
        const float* bM = (tid < 32) ? bq : bk;
        float a = bM[d];
        #pragma unroll
        for (int c = 0; c < CC; c++) a += s_xm[c]*wM[c*DQK + d];
        s_qk[tid] = a;
    }
    __syncthreads();
    if (tid < 128) {
        int t2 = tid & 63;
        int offp = (tid < 64) ? 0 : 32;
        float a = 0.f;
        #pragma unroll
        for (int d = 0; d < 32; d++) a += s_qk[offp + d]*W1[(offp + d)*HIDN + t2];
        ABout[(b*NN + i)*128 + (tid < 64 ? 0 : 64) + t2] = a;
    }
}

// ---------------- launch ------------------------------------------------------
extern "C" void kernel_launch(void* const* d_in, const int* in_sizes, int n_in,
                              void* d_out, int out_size)
{
    const float* seed = (const float*)d_in[0];
    const int*   eidx = (const int*)  d_in[1];
    const float* wq = (const float*)d_in[2];
    const float* bq = (const float*)d_in[3];
    const float* wk = (const float*)d_in[4];
    const float* bk = (const float*)d_in[5];
    const float* wm = (const float*)d_in[6];
    const float* bm = (const float*)d_in[7];
    const float* w1 = (const float*)d_in[8];
    const float* b1 = (const float*)d_in[9];
    const float* w2 = (const float*)d_in[10];
    const float* b2 = (const float*)d_in[11];
    const float* wo = (const float*)d_in[12];
    const float* bo = (const float*)d_in[13];
    const float* gw = (const float*)d_in[14];
    const float* gb = (const float*)d_in[15];
    const float* wg = (const float*)d_in[16];
    const float* bg = (const float*)d_in[17];
    const float* wc = (const float*)d_in[18];
    const float* bc = (const float*)d_in[19];
    float* out = (float*)d_out;

    int B = in_sizes[0] / (CC*128*128);
    int E = in_sizes[1] / 2;

    void *pXa,*pXb,*pM0,*pM1,*pAB0,*pAB1,*pT9,*poff,*plj,*pBM,*pBg,*pBc;
    cudaGetSymbolAddress(&pXa, g_Xa);   cudaGetSymbolAddress(&pXb, g_Xb);
    cudaGetSymbolAddress(&pM0, g_M0);   cudaGetSymbolAddress(&pM1, g_M1);
    cudaGetSymbolAddress(&pAB0,g_AB0);  cudaGetSymbolAddress(&pAB1,g_AB1);
    cudaGetSymbolAddress(&pT9, g_T9);   cudaGetSymbolAddress(&poff,g_off);
    cudaGetSymbolAddress(&plj, g_lj);
    cudaGetSymbolAddress(&pBM, g_pBM);  cudaGetSymbolAddress(&pBg, g_pBg);
    cudaGetSymbolAddress(&pBc, g_pBc);

    cudaFuncSetAttribute(k_iter, cudaFuncAttributeMaxDynamicSharedMemorySize,
                         TILE_BYTES);
    cudaFuncSetAttribute(k_convQ, cudaFuncAttributeMaxDynamicSharedMemorySize,
                         TILE_BYTES);

    // launch order fixed so ncu (-s 5 -c 1) captures a full k_iter (6th launch)
    k_csrT9 <<<1, 256>>>(eidx, E, (int*)poff, (int*)plj, gw, (float*)pT9);
    k_prepAll<<<16, 256>>>(wm, wg, wc, (uint4*)pBM, (uint4*)pBg, (uint4*)pBc);
    k_convQ<<<B*NN, 256, TILE_BYTES>>>(seed, (const uint4*)pBM, bm,
                           wq, bq, wk, bk, w1, (float*)pM0, (float*)pAB0);

    const float* Xc = seed;
    for (int it = 0; it < 4; it++) {
        float* Xn = (it == 3) ? out : ((it & 1) ? (float*)pXb : (float*)pXa);
        float* Mi  = (it & 1) ? (float*)pM1  : (float*)pM0;
        float* Mo  = (it & 1) ? (float*)pM0  : (float*)pM1;
        float* ABi = (it & 1) ? (float*)pAB1 : (float*)pAB0;
        float* ABo = (it & 1) ? (float*)pAB0 : (float*)pAB1;

        k_iter<<<B*NN, 256, TILE_BYTES>>>(Mi, Xc, ABi,
                        (const float*)pT9, gb, b1, w2, b2, wo, bo,
                        (const uint4*)pBg, bg,
                        (const uint4*)pBc, bc,
                        (const uint4*)pBM, bm,
                        wq, bq, wk, bk, w1,
                        (const int*)poff, (const int*)plj,
                        Xn, Mo, ABo, (it < 3) ? 1 : 0);
        Xc = Xn;
    }
}

// round 13
// speedup vs baseline: 4.7999x; 1.1142x over previous
#include <cuda_runtime.h>
#include <cuda_fp16.h>

typedef unsigned int uint;

// Problem constants (fixed by the dataset)
#define CC     16
#define NN     64
#define DQK    32
#define HIDN   64
#define MAXE   512
#define BMAX   16
#define PLANE  16384

// pixel-major split tile: [324 pixels][40 halves pitch] hi plane, then lo plane
#define TPITCH_U 20              // uints per pixel row (40 halves = 80 bytes)
#define LOU      (324*TPITCH_U)  // uint offset of lo plane
#define TILE_U   (324*TPITCH_U*2)
#define TILE_BYTES (TILE_U*4)    // 51840
#define LO_BYTES (324*80)        // byte offset of lo plane

// ---------------- scratch ----------------------------------------------------
__device__ float g_Xa [BMAX*CC*PLANE];
__device__ float g_Xb [BMAX*CC*PLANE];
__device__ float g_M0 [BMAX*CC*PLANE];
__device__ float g_M1 [BMAX*CC*PLANE];
__device__ float g_AB0[BMAX*NN*128];
__device__ float g_AB1[BMAX*NN*128];
__device__ float g_T9 [CC*9];
__device__ int   g_off[NN+1];
__device__ int   g_lj [MAXE];
// fp16-split weight fragment tables: [(ks*N + n)*4 + q] -> (b0h,b1h,b0l,b1l)
__device__ uint4 g_pBM[9*16*4];
__device__ uint4 g_pBg[18*32*4];
__device__ uint4 g_pBc[18*16*4];

__device__ __forceinline__ float sigf(float x){ return 1.f/(1.f+__expf(-x)); }

// ---------------- fp16 split helpers -----------------------------------------
__device__ __forceinline__ uint packh2(__half a, __half b){
    __half2 h = __halves2half2(a, b);
    return *reinterpret_cast<uint*>(&h);
}
// split two floats into (hi half2, lo half2) — cvt.rn.f16x2.f32 packs both
__device__ __forceinline__ uint2 h2pair(float v0, float v1){
    __half2 h = __floats2half2_rn(v0, v1);
    float2 f = __half22float2(h);
    __half2 l = __floats2half2_rn(v0 - f.x, v1 - f.y);
    uint2 r;
    r.x = *reinterpret_cast<uint*>(&h);
    r.y = *reinterpret_cast<uint*>(&l);
    return r;
}
__device__ __forceinline__ float2 h2rec(uint2 e){
    __half2 hh = *reinterpret_cast<__half2*>(&e.x);
    __half2 ll = *reinterpret_cast<__half2*>(&e.y);
    float2 fh = __half22float2(hh), fl = __half22float2(ll);
    return make_float2(fh.x + fl.x, fh.y + fl.y);
}

__device__ __forceinline__ void mmah(float c[4], const uint a[4], uint b0, uint b1){
    asm volatile("mma.sync.aligned.m16n8k16.row.col.f32.f16.f16.f32 "
        "{%0,%1,%2,%3},{%4,%5,%6,%7},{%8,%9},{%0,%1,%2,%3};"
        : "+f"(c[0]),"+f"(c[1]),"+f"(c[2]),"+f"(c[3])
        : "r"(a[0]),"r"(a[1]),"r"(a[2]),"r"(a[3]),"r"(b0),"r"(b1));
}

__device__ __forceinline__ void ldsm4(uint r[4], uint addr){
    asm volatile("ldmatrix.sync.aligned.m8n8.x4.shared.b16 {%0,%1,%2,%3}, [%4];"
        : "=r"(r[0]),"=r"(r[1]),"=r"(r[2]),"=r"(r[3]) : "r"(addr));
}

// ---------------- weight prepack (runs once) ----------------------------------
__device__ __forceinline__ void prep_one(const float* __restrict__ W,
                                         uint4* __restrict__ out,
                                         int CIN, int N, int i)
{
    int q = i & 3; int t = i >> 2; int n = t % N; int ks = t / N;
    float w[4]; __half h[4], l[4];
    int kk[4] = { ks*16 + 2*q, ks*16 + 2*q + 1, ks*16 + 2*q + 8, ks*16 + 2*q + 9 };
    #pragma unroll
    for (int j = 0; j < 4; j++) {
        int k = kk[j];
        w[j] = W[n*CIN*9 + (k % CIN)*9 + (k / CIN)];
        h[j] = __float2half_rn(w[j]);
        l[j] = __float2half_rn(w[j] - __half2float(h[j]));
    }
    uint4 o;
    o.x = packh2(h[0], h[1]);
    o.y = packh2(h[2], h[3]);
    o.z = packh2(l[0], l[1]);
    o.w = packh2(l[2], l[3]);
    out[(ks*N + n)*4 + q] = o;
}

// all three B-tables in one launch: items [0,576) M, [576,2880) g, [2880,4032) c
__global__ void k_prepAll(const float* __restrict__ wm,
                          const float* __restrict__ wg,
                          const float* __restrict__ wc,
                          uint4* __restrict__ outM, uint4* __restrict__ outG,
                          uint4* __restrict__ outC)
{
    int i = blockIdx.x*256 + threadIdx.x;
    if (i < 576)       prep_one(wm, outM, 16, 16, i);
    else if (i < 2880) prep_one(wg, outG, 32, 32, i - 576);
    else if (i < 4032) prep_one(wc, outC, 32, 16, i - 2880);
}

// csr build + T9 table in one launch
__global__ void k_csrT9(const int* __restrict__ eidx, int E,
                        int* __restrict__ off, int* __restrict__ lj,
                        const float* __restrict__ gw, float* __restrict__ T9)
{
    __shared__ int se[MAXE*2];
    int tid = threadIdx.x;
    for (int i = tid; i < 2*E; i += 256) se[i] = eidx[i];
    if (tid < CC*9) {
        int c = tid / 9, cls = tid - c*9, ry = cls/3, rx = cls - ry*3;
        float s = 0.f;
        #pragma unroll
        for (int ky = 0; ky < 3; ky++) {
            if ((ry == 0 && ky == 0) || (ry == 2 && ky == 2)) continue;
            #pragma unroll
            for (int kx = 0; kx < 3; kx++) {
                if ((rx == 0 && kx == 0) || (rx == 2 && kx == 2)) continue;
                s += gw[c*9 + ky*3 + kx];
            }
        }
        T9[tid] = s;
    }
    __syncthreads();
    if (tid == 0) {
        int cnt[NN];
        for (int i = 0; i < NN; i++) cnt[i] = 0;
        for (int e = 0; e < E; e++) cnt[se[2*e]]++;
        int acc = 0;
        for (int i = 0; i < NN; i++) { off[i] = acc; acc += cnt[i]; cnt[i] = 0; }
        off[NN] = acc;
        for (int e = 0; e < E; e++) {
            int i = se[2*e];
            int s = off[i] + cnt[i]++;
            lj[s] = se[2*e + 1];
        }
    }
}

// ---------------- tile loader (pixel-major) -----------------------------------
__device__ __forceinline__ void load_tile_px(uint* sTu,
        const float* __restrict__ src, int ncp, int hoffU,
        int b, int p16, int q16)
{
    int nel = 324*ncp;
    for (int i = threadIdx.x; i < nel; i += 256) {
        int cp = i / 324; int pix = i - cp*324;
        int yy = pix/18, xx = pix - yy*18;
        int ly = yy - 1, lx = xx - 1;
        float v0 = 0.f, v1 = 0.f;
        if ((unsigned)ly < 16u && (unsigned)lx < 16u) {
            const float* p = &src[((b*CC + 2*cp)*128 + p16 + ly)*128 + (q16 + lx)];
            v0 = p[0]; v1 = p[PLANE];
        }
        uint2 e = h2pair(v0, v1);
        sTu[pix*TPITCH_U + hoffU + cp]       = e.x;
        sTu[LOU + pix*TPITCH_U + hoffU + cp] = e.y;
    }
}

// ---------------- fp16 conv GEMM core (ldmatrix, sw-pipelined) -----------------
// TERMS=3: exact-split (ah*bh + ah*bl + al*bh). TERMS=2: A rounded to fp16
// (ah*bh + ah*bl) — used only where output feeds a saturating nonlinearity.
template<int CIN,int NT,int TERMS>
__device__ __forceinline__ void mma_convh(uint sbase,
                                          const uint4* __restrict__ pB,
                                          const float* s_bias,
                                          float acc[2][NT][4])
{
    constexpr int N = NT*8;
    constexpr int KSTEPS = CIN*9/16;
    int lane = threadIdx.x & 31;
    int wid  = threadIdx.x >> 5;
    int g = lane >> 2, q = lane & 3;
    int m0 = wid*2;
    int x = lane & 15, colsel = lane >> 4;

    #pragma unroll
    for (int mm = 0; mm < 2; mm++)
        #pragma unroll
        for (int nt = 0; nt < NT; nt++) {
            float b0 = s_bias[nt*8 + q*2], b1 = s_bias[nt*8 + q*2 + 1];
            acc[mm][nt][0] = b0; acc[mm][nt][1] = b1;
            acc[mm][nt][2] = b0; acc[mm][nt][3] = b1;
        }

    #pragma unroll 2
    for (int ks = 0; ks < KSTEPS; ks++) {
        int tap = (CIN == 16) ? ks : (ks >> 1);
        int sub = (CIN == 16) ? 0  : (ks & 1);
        int ty = tap/3, tx = tap - ty*3;
        uint ah[2][4], al[2][4];
        uint4 bv[NT];
        #pragma unroll
        for (int mm = 0; mm < 2; mm++) {
            int row = (m0 + mm + ty)*18 + x + tx;
            uint addr = sbase + (uint)((row*40 + sub*16 + colsel*8)*2);
            ldsm4(ah[mm], addr);
            if (TERMS == 3) ldsm4(al[mm], addr + LO_BYTES);
        }
        #pragma unroll
        for (int nt = 0; nt < NT; nt++)
            bv[nt] = pB[(ks*N + nt*8 + g)*4 + q];
        #pragma unroll
        for (int nt = 0; nt < NT; nt++) {
            #pragma unroll
            for (int mm = 0; mm < 2; mm++) {
                mmah(acc[mm][nt], ah[mm], bv[nt].x, bv[nt].y);
                mmah(acc[mm][nt], ah[mm], bv[nt].z, bv[nt].w);
                if (TERMS == 3) mmah(acc[mm][nt], al[mm], bv[nt].x, bv[nt].y);
            }
        }
    }
}

// ---------------- initial conv + mean/qk/AB kernel (seed only) ----------------
__global__ __launch_bounds__(256) void k_convQ(const float* __restrict__ X,
    const uint4* __restrict__ pBM, const float* __restrict__ bm,
    const float* __restrict__ wq, const float* __restrict__ bq,
    const float* __restrict__ wk, const float* __restrict__ bk,
    const float* __restrict__ W1,
    float* __restrict__ M, float* __restrict__ AB)
{
    int bn = blockIdx.x; int b = bn >> 6, n = bn & 63;
    int p16 = (n >> 3)*16, q16 = (n & 7)*16;
    extern __shared__ uint sTu[];
    __shared__ float s_bias[16];
    __shared__ float s_red[16][8];
    __shared__ float s_xm[16];
    __shared__ float s_qk[64];
    load_tile_px(sTu, X, 8, 0, b, p16, q16);
    if (threadIdx.x < 16) s_bias[threadIdx.x] = bm[threadIdx.x];
    __syncthreads();

    int tid = threadIdx.x;
    uint sbase = (uint)__cvta_generic_to_shared(sTu);
    {
        int y = tid >> 4, x = tid & 15;
        int w = tid >> 5;
        int pix = (y + 1)*18 + (x + 1);
        #pragma unroll 1
        for (int cp = 0; cp < 8; cp++) {
            float2 v = h2rec(make_uint2(sTu[pix*TPITCH_U + cp],
                                        sTu[LOU + pix*TPITCH_U + cp]));
            #pragma unroll
            for (int o = 16; o; o >>= 1) {
                v.x += __shfl_down_sync(0xffffffffu, v.x, o);
                v.y += __shfl_down_sync(0xffffffffu, v.y, o);
            }
            if ((tid & 31) == 0) { s_red[2*cp][w] = v.x; s_red[2*cp + 1][w] = v.y; }
        }
    }

    float acc[2][2][4];
    mma_convh<16,2,3>(sbase, pBM, s_bias, acc);

    int lane = tid & 31, wid = tid >> 5;
    int g = lane >> 2, q = lane & 3, m0 = wid*2;
    #pragma unroll
    for (int mm = 0; mm < 2; mm++) {
        int y = m0 + mm;
        #pragma unroll
        for (int nt = 0; nt < 2; nt++) {
            int co = nt*8 + q*2;
            int r0 = ((b*CC + co)*128 + p16 + y)*128 + q16;
            int r1 = r0 + PLANE;
            M[r0 + g]     = acc[mm][nt][0];
            M[r1 + g]     = acc[mm][nt][1];
            M[r0 + g + 8] = acc[mm][nt][2];
            M[r1 + g + 8] = acc[mm][nt][3];
        }
    }
    __syncthreads();
    if (tid < 16) {
        float s = 0.f;
        #pragma unroll
        for (int w = 0; w < 8; w++) s += s_red[tid][w];
        s_xm[tid] = s * (1.f/256.f);
    }
    __syncthreads();
    if (tid < 64) {
        int d = tid & 31;
        const float* wM = (tid < 32) ? wq : wk;
        const float* bM = (tid < 32) ? bq : bk;
        float a = bM[d];
        #pragma unroll
        for (int c = 0; c < CC; c++) a += s_xm[c]*wM[c*DQK + d];
        s_qk[tid] = a;
    }
    __syncthreads();
    if (tid < 128) {
        int t = tid & 63;
        int off = (tid < 64) ? 0 : 32;
        float a = 0.f;
        #pragma unroll
        for (int d = 0; d < 32; d++) a += s_qk[off + d]*W1[(off + d)*HIDN + t];
        AB[(b*NN + n)*128 + (tid < 64 ? 0 : 64) + t] = a;
    }
}

// ---------------- fused iteration kernel ---------------------------------------
__global__ __launch_bounds__(256,4) void k_iter(const float* __restrict__ M,
    const float* __restrict__ X, const float* __restrict__ AB,
    const float* __restrict__ T9, const float* __restrict__ gbv,
    const float* __restrict__ b1, const float* __restrict__ W2,
    const float* __restrict__ b2, const float* __restrict__ wo,
    const float* __restrict__ bo,
    const uint4* __restrict__ pBg, const float* __restrict__ bgv,
    const uint4* __restrict__ pBc, const float* __restrict__ bcv,
    const uint4* __restrict__ pBM, const float* __restrict__ bm,
    const float* __restrict__ wq, const float* __restrict__ bq,
    const float* __restrict__ wk, const float* __restrict__ bk,
    const float* __restrict__ W1,
    const int* __restrict__ off, const int* __restrict__ lj,
    float* __restrict__ Xn, float* __restrict__ Mout,
    float* __restrict__ ABout, int doTail)
{
    int bn = blockIdx.x; int b = bn >> 6, i = bn & 63;
    int p16 = (i >> 3)*16, q16 = (i & 7)*16;
    extern __shared__ uint sTu[];               // TILE_BYTES = 51840
    __shared__ float sg[4*144];
    __shared__ float sT9[144];
    __shared__ float sgb[16], s_bg[32], s_bc[16], s_bm[16];
    __shared__ float sb1[64], sb2[64], swo[64];
    // lifetime union: head (edgeMLP) vs tail (mean/qk) buffers never coexist
    __shared__ union {
        struct { float h1s[4][64]; float sred[4][2]; float sev[4]; } head;
        struct { float s_red[16][8]; float s_xm[16]; float s_qk[64]; } tail;
    } u;
    __shared__ int sbase_n[4];

    int tid = threadIdx.x;
    int o0 = off[i], deg = off[i+1] - o0;
    uint sbase = (uint)__cvta_generic_to_shared(sTu);

    // zero agg channels 0..15 (all pixels, incl halo); load X into 16..31
    for (int t = tid; t < 324*8; t += 256) {
        int cp = t / 324, pix = t - cp*324;
        sTu[pix*TPITCH_U + cp] = 0u;
        sTu[LOU + pix*TPITCH_U + cp] = 0u;
    }
    load_tile_px(sTu, X, 8, 8, b, p16, q16);

    if (tid < 144) sT9[tid] = T9[tid];
    if (tid < 16)  sgb[tid] = gbv[tid];
    if (tid < 32)  s_bg[tid] = bgv[tid];
    if (tid < 16)  s_bc[tid] = bcv[tid];
    if (tid < 16)  s_bm[tid] = bm[tid];
    if (tid < 64)  { sb1[tid] = b1[tid]; sb2[tid] = b2[tid]; swo[tid] = wo[tid]; }
    if (tid < deg) {
        int ej = lj[o0 + tid];
        sbase_n[tid] = ((b*CC)*128 + (ej >> 3)*16)*128 + (ej & 7)*16;
    }
    float bov = bo[0];
    __syncthreads();

    // ---- edge MLP for this node's incident edges (<=4) ----
    int l = tid >> 6, t = tid & 63;
    if (l < deg) {
        int ej = lj[o0 + l];
        float a = AB[(b*NN + i)*128 + t] + AB[(b*NN + ej)*128 + 64 + t] + sb1[t];
        u.head.h1s[l][t] = fmaxf(a, 0.f);
    }
    __syncthreads();
    if (l < deg) {
        float a2 = sb2[t];
        #pragma unroll
        for (int k = 0; k < HIDN; k++) a2 += u.head.h1s[l][k]*__ldg(&W2[k*HIDN + t]);
        a2 = fmaxf(a2, 0.f);
        float part = a2*swo[t];
        #pragma unroll
        for (int o = 16; o; o >>= 1) part += __shfl_down_sync(0xffffffffu, part, o);
        if ((t & 31) == 0) u.head.sred[l][t >> 5] = part;
    }
    __syncthreads();
    if (tid < deg) u.head.sev[tid] = u.head.sred[tid][0] + u.head.sred[tid][1] + bov;
    __syncthreads();

    // ---- gate table ----
    for (int t2 = tid; t2 < deg*144; t2 += 256) {
        int le = t2 / 144, r = t2 - le*144;
        int c = r / 9;
        sg[t2] = sigf(u.head.sev[le]*sT9[r] + sgb[c]);
    }
    __syncthreads();

    // ---- segment-sum of gated messages, write split into tile ch 0..15 ----
    {
        int cg = tid >> 6, pg = tid & 63;
        int y = pg >> 2, x0 = (pg & 3)*4;
        int cy = (y == 0) ? 0 : ((y == 15) ? 2 : 1);
        int cix[4];
        #pragma unroll
        for (int k = 0; k < 4; k++) {
            int x = x0 + k;
            cix[k] = cy*3 + ((x == 0) ? 0 : ((x == 15) ? 2 : 1));
        }
        int pix = y*128 + x0;
        float av[4][4];
        #pragma unroll
        for (int cc = 0; cc < 4; cc++) {
            int c = cg*4 + cc;
            float a0=0.f,a1=0.f,a2=0.f,a3=0.f;
            for (int le = 0; le < deg; le++) {
                const float* gl = &sg[le*144 + c*9];
                float4 m = *reinterpret_cast<const float4*>(&M[sbase_n[le] + c*PLANE + pix]);
                a0 += gl[cix[0]]*m.x;
                a1 += gl[cix[1]]*m.y;
                a2 += gl[cix[2]]*m.z;
                a3 += gl[cix[3]]*m.w;
            }
            av[cc][0]=a0; av[cc][1]=a1; av[cc][2]=a2; av[cc][3]=a3;
        }
        #pragma unroll
        for (int k = 0; k < 4; k++) {
            int tp = ((y + 1)*18 + (x0 + 1 + k))*TPITCH_U + 2*cg;
            uint2 p0 = h2pair(av[0][k], av[1][k]);
            uint2 p1 = h2pair(av[2][k], av[3][k]);
            *reinterpret_cast<uint2*>(&sTu[tp])       = make_uint2(p0.x, p1.x);
            *reinterpret_cast<uint2*>(&sTu[LOU + tp]) = make_uint2(p0.y, p1.y);
        }
    }
    __syncthreads();

    // ---- GRU ----
    int lane = tid & 31, wid = tid >> 5;
    int g = lane >> 2, q = lane & 3, m0 = wid*2;

    float zreg[2][2][4];

    {   // gate conv (2-term: output feeds sigmoid, error ~2^-11 damped 4x)
        float acc[2][4][4];
        mma_convh<32,4,2>(sbase, pBg, s_bg, acc);
        __syncthreads();
        #pragma unroll
        for (int mm = 0; mm < 2; mm++) {
            int y = m0 + mm;
            #pragma unroll
            for (int nt = 0; nt < 4; nt++) {
                int co = nt*8 + q*2;
                if (nt < 2) {
                    #pragma unroll
                    for (int rr = 0; rr < 4; rr++)
                        zreg[mm][nt][rr] = sigf(acc[mm][nt][rr]);
                } else {
                    // channels co, co+1 (>=16): r gates -> rh in place
                    #pragma unroll
                    for (int half = 0; half < 2; half++) {
                        int x = g + half*8;
                        int ti = ((y + 1)*18 + (x + 1))*TPITCH_U + co/2;
                        float2 h = h2rec(make_uint2(sTu[ti], sTu[LOU + ti]));
                        float r0 = sigf(acc[mm][nt][half*2]);
                        float r1 = sigf(acc[mm][nt][half*2 + 1]);
                        uint2 e = h2pair(r0*h.x, r1*h.y);
                        sTu[ti] = e.x; sTu[LOU + ti] = e.y;
                    }
                }
            }
        }
    }
    __syncthreads();

    {   // candidate conv + update (+ tile refill for tail); h re-read from X
        float acc[2][2][4];
        mma_convh<32,2,3>(sbase, pBc, s_bc, acc);
        __syncthreads();   // all warps' tile reads done before tile overwrite
        #pragma unroll
        for (int mm = 0; mm < 2; mm++) {
            int y = m0 + mm;
            #pragma unroll
            for (int nt = 0; nt < 2; nt++) {
                int co = nt*8 + q*2;
                #pragma unroll
                for (int half = 0; half < 2; half++) {
                    int x = g + half*8;
                    int idx = ((b*CC + co)*128 + p16 + y)*128 + q16 + x;
                    float h0 = X[idx];
                    float h1 = X[idx + PLANE];
                    float cand0 = tanhf(acc[mm][nt][half*2]);
                    float cand1 = tanhf(acc[mm][nt][half*2 + 1]);
                    float z0 = zreg[mm][nt][half*2], z1 = zreg[mm][nt][half*2 + 1];
                    float v0 = (1.f - z0)*h0 + z0*cand0;
                    float v1 = (1.f - z1)*h1 + z1*cand1;
                    Xn[idx]         = v0;
                    Xn[idx + PLANE] = v1;
                    if (doTail) {
                        int ti = ((y + 1)*18 + (x + 1))*TPITCH_U + co/2;
                        uint2 e = h2pair(v0, v1);
                        sTu[ti] = e.x; sTu[LOU + ti] = e.y;
                    }
                }
            }
        }
    }

    if (!doTail) return;
    __syncthreads();

    {   // patch mean from split tile
        int y = tid >> 4, x = tid & 15;
        int w = tid >> 5;
        int pix = (y + 1)*18 + (x + 1);
        #pragma unroll 1
        for (int cp = 0; cp < 8; cp++) {
            float2 v = h2rec(make_uint2(sTu[pix*TPITCH_U + cp],
                                        sTu[LOU + pix*TPITCH_U + cp]));
            #pragma unroll
            for (int o = 16; o; o >>= 1) {
                v.x += __shfl_down_sync(0xffffffffu, v.x, o);
                v.y += __shfl_down_sync(0xffffffffu, v.y, o);
            }
            if ((tid & 31) == 0) { u.tail.s_red[2*cp][w] = v.x; u.tail.s_red[2*cp + 1][w] = v.y; }
        }
    }

    {   // M conv for next iteration
        float acc[2][2][4];
        mma_convh<16,2,3>(sbase, pBM, s_bm, acc);
        #pragma unroll
        for (int mm = 0; mm < 2; mm++) {
            int y = m0 + mm;
            #pragma unroll
            for (int nt = 0; nt < 2; nt++) {
                int co = nt*8 + q*2;
                int r0 = ((b*CC + co)*128 + p16 + y)*128 + q16;
                int r1 = r0 + PLANE;
                Mout[r0 + g]     = acc[mm][nt][0];
                Mout[r1 + g]     = acc[mm][nt][1];
                Mout[r0 + g + 8] = acc[mm][nt][2];
                Mout[r1 + g + 8] = acc[mm][nt][3];
            }
        }
    }
    __syncthreads();
    if (tid < 16) {
        float s = 0.f;
        #pragma unroll
        for (int w = 0; w < 8; w++) s += u.tail.s_red[tid][w];
        u.tail.s_xm[tid] = s * (1.f/256.f);
    }
    __syncthreads();
    if (tid < 64) {
        int d = tid & 31;
        const float* wM = (tid < 32) ? wq : wk;
        const float* bM = (tid < 32) ? bq : bk;
        float a = bM[d];
        #pragma unroll
        for (int c = 0; c < CC; c++) a += u.tail.s_xm[c]*wM[c*DQK + d];
        u.tail.s_qk[tid] = a;
    }
    __syncthreads();
    if (tid < 128) {
        int t2 = tid & 63;
        int offp = (tid < 64) ? 0 : 32;
        float a = 0.f;
        #pragma unroll
        for (int d = 0; d < 32; d++) a += u.tail.s_qk[offp + d]*W1[(offp + d)*HIDN + t2];
        ABout[(b*NN + i)*128 + (tid < 64 ? 0 : 64) + t2] = a;
    }
}

// ---------------- launch ------------------------------------------------------
extern "C" void kernel_launch(void* const* d_in, const int* in_sizes, int n_in,
                              void* d_out, int out_size)
{
    const float* seed = (const float*)d_in[0];
    const int*   eidx = (const int*)  d_in[1];
    const float* wq = (const float*)d_in[2];
    const float* bq = (const float*)d_in[3];
    const float* wk = (const float*)d_in[4];
    const float* bk = (const float*)d_in[5];
    const float* wm = (const float*)d_in[6];
    const float* bm = (const float*)d_in[7];
    const float* w1 = (const float*)d_in[8];
    const float* b1 = (const float*)d_in[9];
    const float* w2 = (const float*)d_in[10];
    const float* b2 = (const float*)d_in[11];
    const float* wo = (const float*)d_in[12];
    const float* bo = (const float*)d_in[13];
    const float* gw = (const float*)d_in[14];
    const float* gb = (const float*)d_in[15];
    const float* wg = (const float*)d_in[16];
    const float* bg = (const float*)d_in[17];
    const float* wc = (const float*)d_in[18];
    const float* bc = (const float*)d_in[19];
    float* out = (float*)d_out;

    int B = in_sizes[0] / (CC*128*128);
    int E = in_sizes[1] / 2;

    void *pXa,*pXb,*pM0,*pM1,*pAB0,*pAB1,*pT9,*poff,*plj,*pBM,*pBg,*pBc;
    cudaGetSymbolAddress(&pXa, g_Xa);   cudaGetSymbolAddress(&pXb, g_Xb);
    cudaGetSymbolAddress(&pM0, g_M0);   cudaGetSymbolAddress(&pM1, g_M1);
    cudaGetSymbolAddress(&pAB0,g_AB0);  cudaGetSymbolAddress(&pAB1,g_AB1);
    cudaGetSymbolAddress(&pT9, g_T9);   cudaGetSymbolAddress(&poff,g_off);
    cudaGetSymbolAddress(&plj, g_lj);
    cudaGetSymbolAddress(&pBM, g_pBM);  cudaGetSymbolAddress(&pBg, g_pBg);
    cudaGetSymbolAddress(&pBc, g_pBc);

    cudaFuncSetAttribute(k_iter, cudaFuncAttributeMaxDynamicSharedMemorySize,
                         TILE_BYTES);
    cudaFuncSetAttribute(k_convQ, cudaFuncAttributeMaxDynamicSharedMemorySize,
                         TILE_BYTES);

    // launch order fixed so ncu (-s 5 -c 1) captures a full k_iter (6th launch)
    k_csrT9 <<<1, 256>>>(eidx, E, (int*)poff, (int*)plj, gw, (float*)pT9);
    k_prepAll<<<16, 256>>>(wm, wg, wc, (uint4*)pBM, (uint4*)pBg, (uint4*)pBc);
    k_convQ<<<B*NN, 256, TILE_BYTES>>>(seed, (const uint4*)pBM, bm,
                           wq, bq, wk, bk, w1, (float*)pM0, (float*)pAB0);

    const float* Xc = seed;
    for (int it = 0; it < 4; it++) {
        float* Xn = (it == 3) ? out : ((it & 1) ? (float*)pXb : (float*)pXa);
        float* Mi  = (it & 1) ? (float*)pM1  : (float*)pM0;
        float* Mo  = (it & 1) ? (float*)pM0  : (float*)pM1;
        float* ABi = (it & 1) ? (float*)pAB1 : (float*)pAB0;
        float* ABo = (it & 1) ? (float*)pAB0 : (float*)pAB1;

        k_iter<<<B*NN, 256, TILE_BYTES>>>(Mi, Xc, ABi,
                        (const float*)pT9, gb, b1, w2, b2, wo, bo,
                        (const uint4*)pBg, bg,
                        (const uint4*)pBc, bc,
                        (const uint4*)pBM, bm,
                        wq, bq, wk, bk, w1,
                        (const int*)poff, (const int*)plj,
                        Xn, Mo, ABo, (it < 3) ? 1 : 0);
        Xc = Xn;
    }
}

// round 14
// speedup vs baseline: 5.0344x; 1.0489x over previous
#include <cuda_runtime.h>
#include <cuda_fp16.h>

typedef unsigned int uint;

// Problem constants (fixed by the dataset)
#define CC     16
#define NN     64
#define DQK    32
#define HIDN   64
#define MAXE   512
#define BMAX   16
#define PLANE  16384

// pixel-major split tile:
//   hi plane: [324 pixels][20 uints pitch] (16 channel-pairs used)
//   lo plane: [324 pixels][12 uints pitch] (8 channel-pairs used, ch 0..15 only)
#define TPITCH_U 20
#define LPITCH_U 12
#define HI_U     (324*TPITCH_U)          // 6480 uints
#define TILE_U   (HI_U + 324*LPITCH_U)   // 10368 uints
#define TILE_BYTES (TILE_U*4)            // 41472
#define LO_BYTES (HI_U*4)                // 25920 byte offset of lo plane

// ---------------- scratch ----------------------------------------------------
__device__ float g_Xa [BMAX*CC*PLANE];
__device__ float g_Xb [BMAX*CC*PLANE];
__device__ float g_M0 [BMAX*CC*PLANE];
__device__ float g_M1 [BMAX*CC*PLANE];
__device__ float g_AB0[BMAX*NN*128];
__device__ float g_AB1[BMAX*NN*128];
__device__ float g_T9 [CC*9];
__device__ int   g_off[NN+1];
__device__ int   g_lj [MAXE];
// fp16-split weight fragment tables: [(ks*N + n)*4 + q] -> (b0h,b1h,b0l,b1l)
__device__ uint4 g_pBM[9*16*4];
__device__ uint4 g_pBg[18*32*4];
__device__ uint4 g_pBc[18*16*4];

__device__ __forceinline__ float sigf(float x){ return 1.f/(1.f+__expf(-x)); }

// ---------------- fp16 split helpers -----------------------------------------
__device__ __forceinline__ uint packh2(__half a, __half b){
    __half2 h = __halves2half2(a, b);
    return *reinterpret_cast<uint*>(&h);
}
__device__ __forceinline__ uint pkhi(float v0, float v1){
    __half2 h = __floats2half2_rn(v0, v1);
    return *reinterpret_cast<uint*>(&h);
}
// full split (hi half2, lo half2)
__device__ __forceinline__ uint2 h2pair(float v0, float v1){
    __half2 h = __floats2half2_rn(v0, v1);
    float2 f = __half22float2(h);
    __half2 l = __floats2half2_rn(v0 - f.x, v1 - f.y);
    uint2 r;
    r.x = *reinterpret_cast<uint*>(&h);
    r.y = *reinterpret_cast<uint*>(&l);
    return r;
}
__device__ __forceinline__ float2 h2rec(uint2 e){
    __half2 hh = *reinterpret_cast<__half2*>(&e.x);
    __half2 ll = *reinterpret_cast<__half2*>(&e.y);
    float2 fh = __half22float2(hh), fl = __half22float2(ll);
    return make_float2(fh.x + fl.x, fh.y + fl.y);
}
__device__ __forceinline__ float2 hirec(uint e){
    __half2 hh = *reinterpret_cast<__half2*>(&e);
    return __half22float2(hh);
}

__device__ __forceinline__ void mmah(float c[4], const uint a[4], uint b0, uint b1){
    asm volatile("mma.sync.aligned.m16n8k16.row.col.f32.f16.f16.f32 "
        "{%0,%1,%2,%3},{%4,%5,%6,%7},{%8,%9},{%0,%1,%2,%3};"
        : "+f"(c[0]),"+f"(c[1]),"+f"(c[2]),"+f"(c[3])
        : "r"(a[0]),"r"(a[1]),"r"(a[2]),"r"(a[3]),"r"(b0),"r"(b1));
}

__device__ __forceinline__ void ldsm4(uint r[4], uint addr){
    asm volatile("ldmatrix.sync.aligned.m8n8.x4.shared.b16 {%0,%1,%2,%3}, [%4];"
        : "=r"(r[0]),"=r"(r[1]),"=r"(r[2]),"=r"(r[3]) : "r"(addr));
}

// ---------------- weight prepack (runs once) ----------------------------------
__device__ __forceinline__ void prep_one(const float* __restrict__ W,
                                         uint4* __restrict__ out,
                                         int CIN, int N, int i)
{
    int q = i & 3; int t = i >> 2; int n = t % N; int ks = t / N;
    float w[4]; __half h[4], l[4];
    int kk[4] = { ks*16 + 2*q, ks*16 + 2*q + 1, ks*16 + 2*q + 8, ks*16 + 2*q + 9 };
    #pragma unroll
    for (int j = 0; j < 4; j++) {
        int k = kk[j];
        w[j] = W[n*CIN*9 + (k % CIN)*9 + (k / CIN)];
        h[j] = __float2half_rn(w[j]);
        l[j] = __float2half_rn(w[j] - __half2float(h[j]));
    }
    uint4 o;
    o.x = packh2(h[0], h[1]);
    o.y = packh2(h[2], h[3]);
    o.z = packh2(l[0], l[1]);
    o.w = packh2(l[2], l[3]);
    out[(ks*N + n)*4 + q] = o;
}

// all three B-tables in one launch
__global__ void k_prepAll(const float* __restrict__ wm,
                          const float* __restrict__ wg,
                          const float* __restrict__ wc,
                          uint4* __restrict__ outM, uint4* __restrict__ outG,
                          uint4* __restrict__ outC)
{
    int i = blockIdx.x*256 + threadIdx.x;
    if (i < 576)       prep_one(wm, outM, 16, 16, i);
    else if (i < 2880) prep_one(wg, outG, 32, 32, i - 576);
    else if (i < 4032) prep_one(wc, outC, 32, 16, i - 2880);
}

// csr build + T9 table in one launch
__global__ void k_csrT9(const int* __restrict__ eidx, int E,
                        int* __restrict__ off, int* __restrict__ lj,
                        const float* __restrict__ gw, float* __restrict__ T9)
{
    __shared__ int se[MAXE*2];
    int tid = threadIdx.x;
    for (int i = tid; i < 2*E; i += 256) se[i] = eidx[i];
    if (tid < CC*9) {
        int c = tid / 9, cls = tid - c*9, ry = cls/3, rx = cls - ry*3;
        float s = 0.f;
        #pragma unroll
        for (int ky = 0; ky < 3; ky++) {
            if ((ry == 0 && ky == 0) || (ry == 2 && ky == 2)) continue;
            #pragma unroll
            for (int kx = 0; kx < 3; kx++) {
                if ((rx == 0 && kx == 0) || (rx == 2 && kx == 2)) continue;
                s += gw[c*9 + ky*3 + kx];
            }
        }
        T9[tid] = s;
    }
    __syncthreads();
    if (tid == 0) {
        int cnt[NN];
        for (int i = 0; i < NN; i++) cnt[i] = 0;
        for (int e = 0; e < E; e++) cnt[se[2*e]]++;
        int acc = 0;
        for (int i = 0; i < NN; i++) { off[i] = acc; acc += cnt[i]; cnt[i] = 0; }
        off[NN] = acc;
        for (int e = 0; e < E; e++) {
            int i = se[2*e];
            int s = off[i] + cnt[i]++;
            lj[s] = se[2*e + 1];
        }
    }
}

// ---------------- tile loaders (pixel-major) -----------------------------------
// X into hi-only slots cp0..cp0+7 (lo not needed: consumers are 2-term convs)
__device__ __forceinline__ void load_tile_hi(uint* sTu,
        const float* __restrict__ src, int cp0,
        int b, int p16, int q16)
{
    for (int i = threadIdx.x; i < 324*8; i += 256) {
        int cp = i / 324; int pix = i - cp*324;
        int yy = pix/18, xx = pix - yy*18;
        int ly = yy - 1, lx = xx - 1;
        float v0 = 0.f, v1 = 0.f;
        if ((unsigned)ly < 16u && (unsigned)lx < 16u) {
            const float* p = &src[((b*CC + 2*cp)*128 + p16 + ly)*128 + (q16 + lx)];
            v0 = p[0]; v1 = p[PLANE];
        }
        sTu[pix*TPITCH_U + cp0 + cp] = pkhi(v0, v1);
    }
}

// X into hi+lo slots cp 0..7 (for 3-term M conv in k_convQ)
__device__ __forceinline__ void load_tile_hilo(uint* sTu,
        const float* __restrict__ src,
        int b, int p16, int q16)
{
    for (int i = threadIdx.x; i < 324*8; i += 256) {
        int cp = i / 324; int pix = i - cp*324;
        int yy = pix/18, xx = pix - yy*18;
        int ly = yy - 1, lx = xx - 1;
        float v0 = 0.f, v1 = 0.f;
        if ((unsigned)ly < 16u && (unsigned)lx < 16u) {
            const float* p = &src[((b*CC + 2*cp)*128 + p16 + ly)*128 + (q16 + lx)];
            v0 = p[0]; v1 = p[PLANE];
        }
        uint2 e = h2pair(v0, v1);
        sTu[pix*TPITCH_U + cp]            = e.x;
        sTu[HI_U + pix*LPITCH_U + cp]     = e.y;
    }
}

// ---------------- fp16 conv GEMM core (ldmatrix, sw-pipelined) -----------------
// TERMS=3 (CIN=16 only): exact-split. TERMS=2: A fp16-rounded (ah*bh + ah*bl),
// used where output feeds a saturating nonlinearity.
template<int CIN,int NT,int TERMS>
__device__ __forceinline__ void mma_convh(uint sbase,
                                          const uint4* __restrict__ pB,
                                          const float* s_bias,
                                          float acc[2][NT][4])
{
    constexpr int N = NT*8;
    constexpr int KSTEPS = CIN*9/16;
    int lane = threadIdx.x & 31;
    int wid  = threadIdx.x >> 5;
    int g = lane >> 2, q = lane & 3;
    int m0 = wid*2;
    int x = lane & 15, colsel = lane >> 4;

    #pragma unroll
    for (int mm = 0; mm < 2; mm++)
        #pragma unroll
        for (int nt = 0; nt < NT; nt++) {
            float b0 = s_bias[nt*8 + q*2], b1 = s_bias[nt*8 + q*2 + 1];
            acc[mm][nt][0] = b0; acc[mm][nt][1] = b1;
            acc[mm][nt][2] = b0; acc[mm][nt][3] = b1;
        }

    #pragma unroll 2
    for (int ks = 0; ks < KSTEPS; ks++) {
        int tap = (CIN == 16) ? ks : (ks >> 1);
        int sub = (CIN == 16) ? 0  : (ks & 1);
        int ty = tap/3, tx = tap - ty*3;
        uint ah[2][4], al[2][4];
        uint4 bv[NT];
        #pragma unroll
        for (int mm = 0; mm < 2; mm++) {
            int row = (m0 + mm + ty)*18 + x + tx;
            uint addr = sbase + (uint)((row*40 + sub*16 + colsel*8)*2);
            ldsm4(ah[mm], addr);
            if (TERMS == 3) {
                uint addrl = sbase + LO_BYTES + (uint)((row*24 + colsel*8)*2);
                ldsm4(al[mm], addrl);
            }
        }
        #pragma unroll
        for (int nt = 0; nt < NT; nt++)
            bv[nt] = pB[(ks*N + nt*8 + g)*4 + q];
        #pragma unroll
        for (int nt = 0; nt < NT; nt++) {
            #pragma unroll
            for (int mm = 0; mm < 2; mm++) {
                mmah(acc[mm][nt], ah[mm], bv[nt].x, bv[nt].y);
                mmah(acc[mm][nt], ah[mm], bv[nt].z, bv[nt].w);
                if (TERMS == 3) mmah(acc[mm][nt], al[mm], bv[nt].x, bv[nt].y);
            }
        }
    }
}

// ---------------- initial conv + mean/qk/AB kernel (seed only) ----------------
__global__ __launch_bounds__(256) void k_convQ(const float* __restrict__ X,
    const uint4* __restrict__ pBM, const float* __restrict__ bm,
    const float* __restrict__ wq, const float* __restrict__ bq,
    const float* __restrict__ wk, const float* __restrict__ bk,
    const float* __restrict__ W1,
    float* __restrict__ M, float* __restrict__ AB)
{
    int bn = blockIdx.x; int b = bn >> 6, n = bn & 63;
    int p16 = (n >> 3)*16, q16 = (n & 7)*16;
    extern __shared__ uint sTu[];
    __shared__ float s_bias[16];
    __shared__ float s_red[16][8];
    __shared__ float s_xm[16];
    __shared__ float s_qk[64];
    load_tile_hilo(sTu, X, b, p16, q16);
    if (threadIdx.x < 16) s_bias[threadIdx.x] = bm[threadIdx.x];
    __syncthreads();

    int tid = threadIdx.x;
    uint sbase = (uint)__cvta_generic_to_shared(sTu);
    {
        int y = tid >> 4, x = tid & 15;
        int w = tid >> 5;
        int pix = (y + 1)*18 + (x + 1);
        #pragma unroll 1
        for (int cp = 0; cp < 8; cp++) {
            float2 v = h2rec(make_uint2(sTu[pix*TPITCH_U + cp],
                                        sTu[HI_U + pix*LPITCH_U + cp]));
            #pragma unroll
            for (int o = 16; o; o >>= 1) {
                v.x += __shfl_down_sync(0xffffffffu, v.x, o);
                v.y += __shfl_down_sync(0xffffffffu, v.y, o);
            }
            if ((tid & 31) == 0) { s_red[2*cp][w] = v.x; s_red[2*cp + 1][w] = v.y; }
        }
    }

    float acc[2][2][4];
    mma_convh<16,2,3>(sbase, pBM, s_bias, acc);

    int lane = tid & 31, wid = tid >> 5;
    int g = lane >> 2, q = lane & 3, m0 = wid*2;
    #pragma unroll
    for (int mm = 0; mm < 2; mm++) {
        int y = m0 + mm;
        #pragma unroll
        for (int nt = 0; nt < 2; nt++) {
            int co = nt*8 + q*2;
            int r0 = ((b*CC + co)*128 + p16 + y)*128 + q16;
            int r1 = r0 + PLANE;
            M[r0 + g]     = acc[mm][nt][0];
            M[r1 + g]     = acc[mm][nt][1];
            M[r0 + g + 8] = acc[mm][nt][2];
            M[r1 + g + 8] = acc[mm][nt][3];
        }
    }
    __syncthreads();
    if (tid < 16) {
        float s = 0.f;
        #pragma unroll
        for (int w = 0; w < 8; w++) s += s_red[tid][w];
        s_xm[tid] = s * (1.f/256.f);
    }
    __syncthreads();
    if (tid < 64) {
        int d = tid & 31;
        const float* wM = (tid < 32) ? wq : wk;
        const float* bM = (tid < 32) ? bq : bk;
        float a = bM[d];
        #pragma unroll
        for (int c = 0; c < CC; c++) a += s_xm[c]*wM[c*DQK + d];
        s_qk[tid] = a;
    }
    __syncthreads();
    if (tid < 128) {
        int t = tid & 63;
        int off = (tid < 64) ? 0 : 32;
        float a = 0.f;
        #pragma unroll
        for (int d = 0; d < 32; d++) a += s_qk[off + d]*W1[(off + d)*HIDN + t];
        AB[(b*NN + n)*128 + (tid < 64 ? 0 : 64) + t] = a;
    }
}

// ---------------- fused iteration kernel ---------------------------------------
__global__ __launch_bounds__(256,4) void k_iter(const float* __restrict__ M,
    const float* __restrict__ X, const float* __restrict__ AB,
    const float* __restrict__ T9, const float* __restrict__ gbv,
    const float* __restrict__ b1, const float* __restrict__ W2,
    const float* __restrict__ b2, const float* __restrict__ wo,
    const float* __restrict__ bo,
    const uint4* __restrict__ pBg, const float* __restrict__ bgv,
    const uint4* __restrict__ pBc, const float* __restrict__ bcv,
    const uint4* __restrict__ pBM, const float* __restrict__ bm,
    const float* __restrict__ wq, const float* __restrict__ bq,
    const float* __restrict__ wk, const float* __restrict__ bk,
    const float* __restrict__ W1,
    const int* __restrict__ off, const int* __restrict__ lj,
    float* __restrict__ Xn, float* __restrict__ Mout,
    float* __restrict__ ABout, int doTail)
{
    int bn = blockIdx.x; int b = bn >> 6, i = bn & 63;
    int p16 = (i >> 3)*16, q16 = (i & 7)*16;
    extern __shared__ uint sTu[];               // TILE_BYTES = 41472
    __shared__ float sg[4*144];
    __shared__ float sT9[144];
    __shared__ float sgb[16], s_bg[32], s_bc[16], s_bm[16];
    __shared__ float sb1[64], sb2[64], swo[64];
    __shared__ union {
        struct { float h1s[4][64]; float sred[4][2]; float sev[4]; } head;
        struct { float s_red[16][8]; float s_xm[16]; float s_qk[64]; } tail;
    } u;
    __shared__ int sbase_n[4];

    int tid = threadIdx.x;
    int o0 = off[i], deg = off[i+1] - o0;
    uint sbase = (uint)__cvta_generic_to_shared(sTu);

    // zero agg hi cp0..7 + lo cp0..7 (incl halo); load X hi-only into cp8..15
    for (int t = tid; t < 324*8; t += 256) {
        int cp = t / 324, pix = t - cp*324;
        sTu[pix*TPITCH_U + cp] = 0u;
        sTu[HI_U + pix*LPITCH_U + cp] = 0u;
    }
    load_tile_hi(sTu, X, 8, b, p16, q16);

    if (tid < 144) sT9[tid] = T9[tid];
    if (tid < 16)  sgb[tid] = gbv[tid];
    if (tid < 32)  s_bg[tid] = bgv[tid];
    if (tid < 16)  s_bc[tid] = bcv[tid];
    if (tid < 16)  s_bm[tid] = bm[tid];
    if (tid < 64)  { sb1[tid] = b1[tid]; sb2[tid] = b2[tid]; swo[tid] = wo[tid]; }
    if (tid < deg) {
        int ej = lj[o0 + tid];
        sbase_n[tid] = ((b*CC)*128 + (ej >> 3)*16)*128 + (ej & 7)*16;
    }
    float bov = bo[0];
    __syncthreads();

    // ---- edge MLP for this node's incident edges (<=4) ----
    int l = tid >> 6, t = tid & 63;
    if (l < deg) {
        int ej = lj[o0 + l];
        float a = AB[(b*NN + i)*128 + t] + AB[(b*NN + ej)*128 + 64 + t] + sb1[t];
        u.head.h1s[l][t] = fmaxf(a, 0.f);
    }
    __syncthreads();
    if (l < deg) {
        float a2 = sb2[t];
        #pragma unroll
        for (int k = 0; k < HIDN; k++) a2 += u.head.h1s[l][k]*__ldg(&W2[k*HIDN + t]);
        a2 = fmaxf(a2, 0.f);
        float part = a2*swo[t];
        #pragma unroll
        for (int o = 16; o; o >>= 1) part += __shfl_down_sync(0xffffffffu, part, o);
        if ((t & 31) == 0) u.head.sred[l][t >> 5] = part;
    }
    __syncthreads();
    if (tid < deg) u.head.sev[tid] = u.head.sred[tid][0] + u.head.sred[tid][1] + bov;
    __syncthreads();

    // ---- gate table ----
    for (int t2 = tid; t2 < deg*144; t2 += 256) {
        int le = t2 / 144, r = t2 - le*144;
        int c = r / 9;
        sg[t2] = sigf(u.head.sev[le]*sT9[r] + sgb[c]);
    }
    __syncthreads();

    // ---- segment-sum of gated messages, hi-only write into tile ch 0..15 ----
    {
        int cg = tid >> 6, pg = tid & 63;
        int y = pg >> 2, x0 = (pg & 3)*4;
        int cy = (y == 0) ? 0 : ((y == 15) ? 2 : 1);
        int cix[4];
        #pragma unroll
        for (int k = 0; k < 4; k++) {
            int x = x0 + k;
            cix[k] = cy*3 + ((x == 0) ? 0 : ((x == 15) ? 2 : 1));
        }
        int pix = y*128 + x0;
        float av[4][4];
        #pragma unroll
        for (int cc = 0; cc < 4; cc++) {
            int c = cg*4 + cc;
            float a0=0.f,a1=0.f,a2=0.f,a3=0.f;
            for (int le = 0; le < deg; le++) {
                const float* gl = &sg[le*144 + c*9];
                float4 m = *reinterpret_cast<const float4*>(&M[sbase_n[le] + c*PLANE + pix]);
                a0 += gl[cix[0]]*m.x;
                a1 += gl[cix[1]]*m.y;
                a2 += gl[cix[2]]*m.z;
                a3 += gl[cix[3]]*m.w;
            }
            av[cc][0]=a0; av[cc][1]=a1; av[cc][2]=a2; av[cc][3]=a3;
        }
        #pragma unroll
        for (int k = 0; k < 4; k++) {
            int tp = ((y + 1)*18 + (x0 + 1 + k))*TPITCH_U + 2*cg;
            *reinterpret_cast<uint2*>(&sTu[tp]) =
                make_uint2(pkhi(av[0][k], av[1][k]), pkhi(av[2][k], av[3][k]));
        }
    }
    __syncthreads();

    // ---- GRU ----
    int lane = tid & 31, wid = tid >> 5;
    int g = lane >> 2, q = lane & 3, m0 = wid*2;

    float zreg[2][2][4];

    {   // gate conv (2-term)
        float acc[2][4][4];
        mma_convh<32,4,2>(sbase, pBg, s_bg, acc);
        __syncthreads();
        #pragma unroll
        for (int mm = 0; mm < 2; mm++) {
            int y = m0 + mm;
            #pragma unroll
            for (int nt = 0; nt < 4; nt++) {
                int co = nt*8 + q*2;
                if (nt < 2) {
                    #pragma unroll
                    for (int rr = 0; rr < 4; rr++)
                        zreg[mm][nt][rr] = sigf(acc[mm][nt][rr]);
                } else {
                    // channels co, co+1 (>=16): r gates -> rh in place (hi-only)
                    #pragma unroll
                    for (int half = 0; half < 2; half++) {
                        int x = g + half*8;
                        int ti = ((y + 1)*18 + (x + 1))*TPITCH_U + co/2;
                        float2 h = hirec(sTu[ti]);
                        float r0 = sigf(acc[mm][nt][half*2]);
                        float r1 = sigf(acc[mm][nt][half*2 + 1]);
                        sTu[ti] = pkhi(r0*h.x, r1*h.y);
                    }
                }
            }
        }
    }
    __syncthreads();

    {   // candidate conv (2-term) + update (+ hi/lo tile refill for tail)
        float acc[2][2][4];
        mma_convh<32,2,2>(sbase, pBc, s_bc, acc);
        __syncthreads();   // all warps' tile reads done before tile overwrite
        #pragma unroll
        for (int mm = 0; mm < 2; mm++) {
            int y = m0 + mm;
            #pragma unroll
            for (int nt = 0; nt < 2; nt++) {
                int co = nt*8 + q*2;
                #pragma unroll
                for (int half = 0; half < 2; half++) {
                    int x = g + half*8;
                    int idx = ((b*CC + co)*128 + p16 + y)*128 + q16 + x;
                    float h0 = X[idx];
                    float h1 = X[idx + PLANE];
                    float cand0 = tanhf(acc[mm][nt][half*2]);
                    float cand1 = tanhf(acc[mm][nt][half*2 + 1]);
                    float z0 = zreg[mm][nt][half*2], z1 = zreg[mm][nt][half*2 + 1];
                    float v0 = (1.f - z0)*h0 + z0*cand0;
                    float v1 = (1.f - z1)*h1 + z1*cand1;
                    Xn[idx]         = v0;
                    Xn[idx + PLANE] = v1;
                    if (doTail) {
                        int pix = (y + 1)*18 + (x + 1);
                        uint2 e = h2pair(v0, v1);
                        sTu[pix*TPITCH_U + co/2]        = e.x;
                        sTu[HI_U + pix*LPITCH_U + co/2] = e.y;
                    }
                }
            }
        }
    }

    if (!doTail) return;
    __syncthreads();

    {   // patch mean from split tile (cp 0..7, hi+lo)
        int y = tid >> 4, x = tid & 15;
        int w = tid >> 5;
        int pix = (y + 1)*18 + (x + 1);
        #pragma unroll 1
        for (int cp = 0; cp < 8; cp++) {
            float2 v = h2rec(make_uint2(sTu[pix*TPITCH_U + cp],
                                        sTu[HI_U + pix*LPITCH_U + cp]));
            #pragma unroll
            for (int o = 16; o; o >>= 1) {
                v.x += __shfl_down_sync(0xffffffffu, v.x, o);
                v.y += __shfl_down_sync(0xffffffffu, v.y, o);
            }
            if ((tid & 31) == 0) { u.tail.s_red[2*cp][w] = v.x; u.tail.s_red[2*cp + 1][w] = v.y; }
        }
    }

    {   // M conv for next iteration (exact 3-term)
        float acc[2][2][4];
        mma_convh<16,2,3>(sbase, pBM, s_bm, acc);
        #pragma unroll
        for (int mm = 0; mm < 2; mm++) {
            int y = m0 + mm;
            #pragma unroll
            for (int nt = 0; nt < 2; nt++) {
                int co = nt*8 + q*2;
                int r0 = ((b*CC + co)*128 + p16 + y)*128 + q16;
                int r1 = r0 + PLANE;
                Mout[r0 + g]     = acc[mm][nt][0];
                Mout[r1 + g]     = acc[mm][nt][1];
                Mout[r0 + g + 8] = acc[mm][nt][2];
                Mout[r1 + g + 8] = acc[mm][nt][3];
            }
        }
    }
    __syncthreads();
    if (tid < 16) {
        float s = 0.f;
        #pragma unroll
        for (int w = 0; w < 8; w++) s += u.tail.s_red[tid][w];
        u.tail.s_xm[tid] = s * (1.f/256.f);
    }
    __syncthreads();
    if (tid < 64) {
        int d = tid & 31;
        const float* wM = (tid < 32) ? wq : wk;
        const float* bM = (tid < 32) ? bq : bk;
        float a = bM[d];
        #pragma unroll
        for (int c = 0; c < CC; c++) a += u.tail.s_xm[c]*wM[c*DQK + d];
        u.tail.s_qk[tid] = a;
    }
    __syncthreads();
    if (tid < 128) {
        int t2 = tid & 63;
        int offp = (tid < 64) ? 0 : 32;
        float a = 0.f;
        #pragma unroll
        for (int d = 0; d < 32; d++) a += u.tail.s_qk[offp + d]*W1[(offp + d)*HIDN + t2];
        ABout[(b*NN + i)*128 + (tid < 64 ? 0 : 64) + t2] = a;
    }
}

// ---------------- launch ------------------------------------------------------
extern "C" void kernel_launch(void* const* d_in, const int* in_sizes, int n_in,
                              void* d_out, int out_size)
{
    const float* seed = (const float*)d_in[0];
    const int*   eidx = (const int*)  d_in[1];
    const float* wq = (const float*)d_in[2];
    const float* bq = (const float*)d_in[3];
    const float* wk = (const float*)d_in[4];
    const float* bk = (const float*)d_in[5];
    const float* wm = (const float*)d_in[6];
    const float* bm = (const float*)d_in[7];
    const float* w1 = (const float*)d_in[8];
    const float* b1 = (const float*)d_in[9];
    const float* w2 = (const float*)d_in[10];
    const float* b2 = (const float*)d_in[11];
    const float* wo = (const float*)d_in[12];
    const float* bo = (const float*)d_in[13];
    const float* gw = (const float*)d_in[14];
    const float* gb = (const float*)d_in[15];
    const float* wg = (const float*)d_in[16];
    const float* bg = (const float*)d_in[17];
    const float* wc = (const float*)d_in[18];
    const float* bc = (const float*)d_in[19];
    float* out = (float*)d_out;

    int B = in_sizes[0] / (CC*128*128);
    int E = in_sizes[1] / 2;

    void *pXa,*pXb,*pM0,*pM1,*pAB0,*pAB1,*pT9,*poff,*plj,*pBM,*pBg,*pBc;
    cudaGetSymbolAddress(&pXa, g_Xa);   cudaGetSymbolAddress(&pXb, g_Xb);
    cudaGetSymbolAddress(&pM0, g_M0);   cudaGetSymbolAddress(&pM1, g_M1);
    cudaGetSymbolAddress(&pAB0,g_AB0);  cudaGetSymbolAddress(&pAB1,g_AB1);
    cudaGetSymbolAddress(&pT9, g_T9);   cudaGetSymbolAddress(&poff,g_off);
    cudaGetSymbolAddress(&plj, g_lj);
    cudaGetSymbolAddress(&pBM, g_pBM);  cudaGetSymbolAddress(&pBg, g_pBg);
    cudaGetSymbolAddress(&pBc, g_pBc);

    cudaFuncSetAttribute(k_iter, cudaFuncAttributeMaxDynamicSharedMemorySize,
                         TILE_BYTES);
    cudaFuncSetAttribute(k_convQ, cudaFuncAttributeMaxDynamicSharedMemorySize,
                         TILE_BYTES);

    // launch order fixed so ncu (-s 5 -c 1) captures a full k_iter (6th launch)
    k_csrT9 <<<1, 256>>>(eidx, E, (int*)poff, (int*)plj, gw, (float*)pT9);
    k_prepAll<<<16, 256>>>(wm, wg, wc, (uint4*)pBM, (uint4*)pBg, (uint4*)pBc);
    k_convQ<<<B*NN, 256, TILE_BYTES>>>(seed, (const uint4*)pBM, bm,
                           wq, bq, wk, bk, w1, (float*)pM0, (float*)pAB0);

    const float* Xc = seed;
    for (int it = 0; it < 4; it++) {
        float* Xn = (it == 3) ? out : ((it & 1) ? (float*)pXb : (float*)pXa);
        float* Mi  = (it & 1) ? (float*)pM1  : (float*)pM0;
        float* Mo  = (it & 1) ? (float*)pM0  : (float*)pM1;
        float* ABi = (it & 1) ? (float*)pAB1 : (float*)pAB0;
        float* ABo = (it & 1) ? (float*)pAB0 : (float*)pAB1;

        k_iter<<<B*NN, 256, TILE_BYTES>>>(Mi, Xc, ABi,
                        (const float*)pT9, gb, b1, w2, b2, wo, bo,
                        (const uint4*)pBg, bg,
                        (const uint4*)pBc, bc,
                        (const uint4*)pBM, bm,
                        wq, bq, wk, bk, w1,
                        (const int*)poff, (const int*)plj,
                        Xn, Mo, ABo, (it < 3) ? 1 : 0);
        Xc = Xn;
    }
}

// round 15
// speedup vs baseline: 5.5746x; 1.1073x over previous
#include <cuda_runtime.h>
#include <cuda_fp16.h>

typedef unsigned int uint;

// Problem constants (fixed by the dataset)
#define CC     16
#define NN     64
#define DQK    32
#define HIDN   64
#define MAXE   512
#define BMAX   16
#define PLANE  16384

// pixel-major fp16 tile (hi only): [324 pixels][20 uints pitch], 16 ch-pairs
#define TPITCH_U 20
#define TILE_U   (324*TPITCH_U)
#define TILE_BYTES (TILE_U*4)            // 25920

// ---------------- scratch ----------------------------------------------------
__device__ float g_Xa [BMAX*CC*PLANE];
__device__ float g_Xb [BMAX*CC*PLANE];
__device__ float g_M0 [BMAX*CC*PLANE];
__device__ float g_M1 [BMAX*CC*PLANE];
__device__ float g_AB0[BMAX*NN*128];
__device__ float g_AB1[BMAX*NN*128];
__device__ float g_T9 [CC*9];
__device__ int   g_off[NN+1];
__device__ int   g_lj [MAXE];
// fp16-split weight fragment tables: [(ks*N + n)*4 + q] -> (b0h,b1h,b0l,b1l)
__device__ uint4 g_pBM[9*16*4];
__device__ uint4 g_pBg[18*32*4];
__device__ uint4 g_pBc[18*16*4];

__device__ __forceinline__ float sigf(float x){ return 1.f/(1.f+__expf(-x)); }

// ---------------- fp16 helpers ------------------------------------------------
__device__ __forceinline__ uint packh2(__half a, __half b){
    __half2 h = __halves2half2(a, b);
    return *reinterpret_cast<uint*>(&h);
}
__device__ __forceinline__ uint pkhi(float v0, float v1){
    __half2 h = __floats2half2_rn(v0, v1);
    return *reinterpret_cast<uint*>(&h);
}
__device__ __forceinline__ float2 hirec(uint e){
    __half2 hh = *reinterpret_cast<__half2*>(&e);
    return __half22float2(hh);
}

__device__ __forceinline__ void mmah(float c[4], const uint a[4], uint b0, uint b1){
    asm volatile("mma.sync.aligned.m16n8k16.row.col.f32.f16.f16.f32 "
        "{%0,%1,%2,%3},{%4,%5,%6,%7},{%8,%9},{%0,%1,%2,%3};"
        : "+f"(c[0]),"+f"(c[1]),"+f"(c[2]),"+f"(c[3])
        : "r"(a[0]),"r"(a[1]),"r"(a[2]),"r"(a[3]),"r"(b0),"r"(b1));
}

__device__ __forceinline__ void ldsm4(uint r[4], uint addr){
    asm volatile("ldmatrix.sync.aligned.m8n8.x4.shared.b16 {%0,%1,%2,%3}, [%4];"
        : "=r"(r[0]),"=r"(r[1]),"=r"(r[2]),"=r"(r[3]) : "r"(addr));
}

// ---------------- weight prepack (runs once) ----------------------------------
__device__ __forceinline__ void prep_one(const float* __restrict__ W,
                                         uint4* __restrict__ out,
                                         int CIN, int N, int i)
{
    int q = i & 3; int t = i >> 2; int n = t % N; int ks = t / N;
    float w[4]; __half h[4], l[4];
    int kk[4] = { ks*16 + 2*q, ks*16 + 2*q + 1, ks*16 + 2*q + 8, ks*16 + 2*q + 9 };
    #pragma unroll
    for (int j = 0; j < 4; j++) {
        int k = kk[j];
        w[j] = W[n*CIN*9 + (k % CIN)*9 + (k / CIN)];
        h[j] = __float2half_rn(w[j]);
        l[j] = __float2half_rn(w[j] - __half2float(h[j]));
    }
    uint4 o;
    o.x = packh2(h[0], h[1]);
    o.y = packh2(h[2], h[3]);
    o.z = packh2(l[0], l[1]);
    o.w = packh2(l[2], l[3]);
    out[(ks*N + n)*4 + q] = o;
}

__global__ void k_prepAll(const float* __restrict__ wm,
                          const float* __restrict__ wg,
                          const float* __restrict__ wc,
                          uint4* __restrict__ outM, uint4* __restrict__ outG,
                          uint4* __restrict__ outC)
{
    int i = blockIdx.x*256 + threadIdx.x;
    if (i < 576)       prep_one(wm, outM, 16, 16, i);
    else if (i < 2880) prep_one(wg, outG, 32, 32, i - 576);
    else if (i < 4032) prep_one(wc, outC, 32, 16, i - 2880);
}

// csr build + T9 table in one launch
__global__ void k_csrT9(const int* __restrict__ eidx, int E,
                        int* __restrict__ off, int* __restrict__ lj,
                        const float* __restrict__ gw, float* __restrict__ T9)
{
    __shared__ int se[MAXE*2];
    int tid = threadIdx.x;
    for (int i = tid; i < 2*E; i += 256) se[i] = eidx[i];
    if (tid < CC*9) {
        int c = tid / 9, cls = tid - c*9, ry = cls/3, rx = cls - ry*3;
        float s = 0.f;
        #pragma unroll
        for (int ky = 0; ky < 3; ky++) {
            if ((ry == 0 && ky == 0) || (ry == 2 && ky == 2)) continue;
            #pragma unroll
            for (int kx = 0; kx < 3; kx++) {
                if ((rx == 0 && kx == 0) || (rx == 2 && kx == 2)) continue;
                s += gw[c*9 + ky*3 + kx];
            }
        }
        T9[tid] = s;
    }
    __syncthreads();
    if (tid == 0) {
        int cnt[NN];
        for (int i = 0; i < NN; i++) cnt[i] = 0;
        for (int e = 0; e < E; e++) cnt[se[2*e]]++;
        int acc = 0;
        for (int i = 0; i < NN; i++) { off[i] = acc; acc += cnt[i]; cnt[i] = 0; }
        off[NN] = acc;
        for (int e = 0; e < E; e++) {
            int i = se[2*e];
            int s = off[i] + cnt[i]++;
            lj[s] = se[2*e + 1];
        }
    }
}

// ---------------- tile loader (pixel-major, hi only) ---------------------------
__device__ __forceinline__ void load_tile_hi(uint* sTu,
        const float* __restrict__ src, int cp0,
        int b, int p16, int q16)
{
    for (int i = threadIdx.x; i < 324*8; i += 256) {
        int cp = i / 324; int pix = i - cp*324;
        int yy = pix/18, xx = pix - yy*18;
        int ly = yy - 1, lx = xx - 1;
        float v0 = 0.f, v1 = 0.f;
        if ((unsigned)ly < 16u && (unsigned)lx < 16u) {
            const float* p = &src[((b*CC + 2*cp)*128 + p16 + ly)*128 + (q16 + lx)];
            v0 = p[0]; v1 = p[PLANE];
        }
        sTu[pix*TPITCH_U + cp0 + cp] = pkhi(v0, v1);
    }
}

// ---------------- fp16 2-term conv GEMM core (ldmatrix, sw-pipelined) ----------
// A fp16-rounded; B exactly split: ah*bh + ah*bl. All conv outputs feed
// saturating nonlinearities or tolerate ~2^-11 relative error.
template<int CIN,int NT>
__device__ __forceinline__ void mma_convh(uint sbase,
                                          const uint4* __restrict__ pB,
                                          const float* s_bias,
                                          float acc[2][NT][4])
{
    constexpr int N = NT*8;
    constexpr int KSTEPS = CIN*9/16;
    int lane = threadIdx.x & 31;
    int wid  = threadIdx.x >> 5;
    int g = lane >> 2, q = lane & 3;
    int m0 = wid*2;
    int x = lane & 15, colsel = lane >> 4;

    #pragma unroll
    for (int mm = 0; mm < 2; mm++)
        #pragma unroll
        for (int nt = 0; nt < NT; nt++) {
            float b0 = s_bias[nt*8 + q*2], b1 = s_bias[nt*8 + q*2 + 1];
            acc[mm][nt][0] = b0; acc[mm][nt][1] = b1;
            acc[mm][nt][2] = b0; acc[mm][nt][3] = b1;
        }

    #pragma unroll 2
    for (int ks = 0; ks < KSTEPS; ks++) {
        int tap = (CIN == 16) ? ks : (ks >> 1);
        int sub = (CIN == 16) ? 0  : (ks & 1);
        int ty = tap/3, tx = tap - ty*3;
        uint ah[2][4];
        uint4 bv[NT];
        #pragma unroll
        for (int mm = 0; mm < 2; mm++) {
            int row = (m0 + mm + ty)*18 + x + tx;
            uint addr = sbase + (uint)((row*40 + sub*16 + colsel*8)*2);
            ldsm4(ah[mm], addr);
        }
        #pragma unroll
        for (int nt = 0; nt < NT; nt++)
            bv[nt] = pB[(ks*N + nt*8 + g)*4 + q];
        #pragma unroll
        for (int nt = 0; nt < NT; nt++) {
            #pragma unroll
            for (int mm = 0; mm < 2; mm++) {
                mmah(acc[mm][nt], ah[mm], bv[nt].x, bv[nt].y);
                mmah(acc[mm][nt], ah[mm], bv[nt].z, bv[nt].w);
            }
        }
    }
}

// ---------------- initial conv + mean/qk/AB kernel (seed only) ----------------
__global__ __launch_bounds__(256) void k_convQ(const float* __restrict__ X,
    const uint4* __restrict__ pBM, const float* __restrict__ bm,
    const float* __restrict__ wq, const float* __restrict__ bq,
    const float* __restrict__ wk, const float* __restrict__ bk,
    const float* __restrict__ W1,
    float* __restrict__ M, float* __restrict__ AB)
{
    int bn = blockIdx.x; int b = bn >> 6, n = bn & 63;
    int p16 = (n >> 3)*16, q16 = (n & 7)*16;
    extern __shared__ uint sTu[];
    __shared__ float s_bias[16];
    __shared__ float s_xm[16];
    __shared__ float s_qk[64];
    load_tile_hi(sTu, X, 0, b, p16, q16);
    if (threadIdx.x < 16) s_bias[threadIdx.x] = bm[threadIdx.x];

    int tid = threadIdx.x;
    uint sbase = (uint)__cvta_generic_to_shared(sTu);
    // exact fp32 patch mean straight from global X (each warp: 2 channels)
    {
        int w = tid >> 5, lane = tid & 31;
        for (int c = w*2; c < w*2 + 2; c++) {
            float s = 0.f;
            for (int i = lane; i < 256; i += 32) {
                int y = i >> 4, x = i & 15;
                s += X[((b*CC + c)*128 + p16 + y)*128 + q16 + x];
            }
            #pragma unroll
            for (int o = 16; o; o >>= 1) s += __shfl_down_sync(0xffffffffu, s, o);
            if (!lane) s_xm[c] = s * (1.f/256.f);
        }
    }
    __syncthreads();

    float acc[2][2][4];
    mma_convh<16,2>(sbase, pBM, s_bias, acc);

    int lane = tid & 31, wid = tid >> 5;
    int g = lane >> 2, q = lane & 3, m0 = wid*2;
    #pragma unroll
    for (int mm = 0; mm < 2; mm++) {
        int y = m0 + mm;
        #pragma unroll
        for (int nt = 0; nt < 2; nt++) {
            int co = nt*8 + q*2;
            int r0 = ((b*CC + co)*128 + p16 + y)*128 + q16;
            int r1 = r0 + PLANE;
            M[r0 + g]     = acc[mm][nt][0];
            M[r1 + g]     = acc[mm][nt][1];
            M[r0 + g + 8] = acc[mm][nt][2];
            M[r1 + g + 8] = acc[mm][nt][3];
        }
    }
    __syncthreads();
    if (tid < 64) {
        int d = tid & 31;
        const float* wM = (tid < 32) ? wq : wk;
        const float* bM = (tid < 32) ? bq : bk;
        float a = bM[d];
        #pragma unroll
        for (int c = 0; c < CC; c++) a += s_xm[c]*wM[c*DQK + d];
        s_qk[tid] = a;
    }
    __syncthreads();
    if (tid < 128) {
        int t = tid & 63;
        int off = (tid < 64) ? 0 : 32;
        float a = 0.f;
        #pragma unroll
        for (int d = 0; d < 32; d++) a += s_qk[off + d]*W1[(off + d)*HIDN + t];
        AB[(b*NN + n)*128 + (tid < 64 ? 0 : 64) + t] = a;
    }
}

// ---------------- fused iteration kernel ---------------------------------------
__global__ __launch_bounds__(256,4) void k_iter(const float* __restrict__ M,
    const float* __restrict__ X, const float* __restrict__ AB,
    const float* __restrict__ T9, const float* __restrict__ gbv,
    const float* __restrict__ b1, const float* __restrict__ W2,
    const float* __restrict__ b2, const float* __restrict__ wo,
    const float* __restrict__ bo,
    const uint4* __restrict__ pBg, const float* __restrict__ bgv,
    const uint4* __restrict__ pBc, const float* __restrict__ bcv,
    const uint4* __restrict__ pBM, const float* __restrict__ bm,
    const float* __restrict__ wq, const float* __restrict__ bq,
    const float* __restrict__ wk, const float* __restrict__ bk,
    const float* __restrict__ W1,
    const int* __restrict__ off, const int* __restrict__ lj,
    float* __restrict__ Xn, float* __restrict__ Mout,
    float* __restrict__ ABout, int doTail)
{
    int bn = blockIdx.x; int b = bn >> 6, i = bn & 63;
    int p16 = (i >> 3)*16, q16 = (i & 7)*16;
    extern __shared__ uint sTu[];               // TILE_BYTES = 25920
    __shared__ float sg[4*144];
    __shared__ float sT9[144];
    __shared__ float sgb[16], s_bg[32], s_bc[16], s_bm[16];
    __shared__ float sb1[64], sb2[64], swo[64];
    __shared__ union {
        struct { float h1s[4][64]; float sred[4][2]; float sev[4]; } head;
        struct { float s_red[16][8]; float s_xm[16]; float s_qk[64]; } tail;
    } u;
    __shared__ int sbase_n[4];

    int tid = threadIdx.x;
    int o0 = off[i], deg = off[i+1] - o0;
    uint sbase = (uint)__cvta_generic_to_shared(sTu);

    // zero agg cp0..7 (incl halo); load X hi-only into cp8..15
    for (int t = tid; t < 324*8; t += 256) {
        int cp = t / 324, pix = t - cp*324;
        sTu[pix*TPITCH_U + cp] = 0u;
    }
    load_tile_hi(sTu, X, 8, b, p16, q16);

    if (tid < 144) sT9[tid] = T9[tid];
    if (tid < 16)  sgb[tid] = gbv[tid];
    if (tid < 32)  s_bg[tid] = bgv[tid];
    if (tid < 16)  s_bc[tid] = bcv[tid];
    if (tid < 16)  s_bm[tid] = bm[tid];
    if (tid < 64)  { sb1[tid] = b1[tid]; sb2[tid] = b2[tid]; swo[tid] = wo[tid]; }
    if (tid < deg) {
        int ej = lj[o0 + tid];
        sbase_n[tid] = ((b*CC)*128 + (ej >> 3)*16)*128 + (ej & 7)*16;
    }
    float bov = bo[0];
    __syncthreads();

    // ---- edge MLP for this node's incident edges (<=4) ----
    int l = tid >> 6, t = tid & 63;
    if (l < deg) {
        int ej = lj[o0 + l];
        float a = AB[(b*NN + i)*128 + t] + AB[(b*NN + ej)*128 + 64 + t] + sb1[t];
        u.head.h1s[l][t] = fmaxf(a, 0.f);
    }
    __syncthreads();
    if (l < deg) {
        float a2 = sb2[t];
        #pragma unroll
        for (int k = 0; k < HIDN; k++) a2 += u.head.h1s[l][k]*__ldg(&W2[k*HIDN + t]);
        a2 = fmaxf(a2, 0.f);
        float part = a2*swo[t];
        #pragma unroll
        for (int o = 16; o; o >>= 1) part += __shfl_down_sync(0xffffffffu, part, o);
        if ((t & 31) == 0) u.head.sred[l][t >> 5] = part;
    }
    __syncthreads();
    if (tid < deg) u.head.sev[tid] = u.head.sred[tid][0] + u.head.sred[tid][1] + bov;
    __syncthreads();

    // ---- gate table ----
    for (int t2 = tid; t2 < deg*144; t2 += 256) {
        int le = t2 / 144, r = t2 - le*144;
        int c = r / 9;
        sg[t2] = sigf(u.head.sev[le]*sT9[r] + sgb[c]);
    }
    __syncthreads();

    // ---- segment-sum of gated messages, hi write into tile ch 0..15 ----
    {
        int cg = tid >> 6, pg = tid & 63;
        int y = pg >> 2, x0 = (pg & 3)*4;
        int cy = (y == 0) ? 0 : ((y == 15) ? 2 : 1);
        int cix[4];
        #pragma unroll
        for (int k = 0; k < 4; k++) {
            int x = x0 + k;
            cix[k] = cy*3 + ((x == 0) ? 0 : ((x == 15) ? 2 : 1));
        }
        int pix = y*128 + x0;
        float av[4][4];
        #pragma unroll
        for (int cc = 0; cc < 4; cc++) {
            int c = cg*4 + cc;
            float a0=0.f,a1=0.f,a2=0.f,a3=0.f;
            for (int le = 0; le < deg; le++) {
                const float* gl = &sg[le*144 + c*9];
                float4 m = *reinterpret_cast<const float4*>(&M[sbase_n[le] + c*PLANE + pix]);
                a0 += gl[cix[0]]*m.x;
                a1 += gl[cix[1]]*m.y;
                a2 += gl[cix[2]]*m.z;
                a3 += gl[cix[3]]*m.w;
            }
            av[cc][0]=a0; av[cc][1]=a1; av[cc][2]=a2; av[cc][3]=a3;
        }
        #pragma unroll
        for (int k = 0; k < 4; k++) {
            int tp = ((y + 1)*18 + (x0 + 1 + k))*TPITCH_U + 2*cg;
            *reinterpret_cast<uint2*>(&sTu[tp]) =
                make_uint2(pkhi(av[0][k], av[1][k]), pkhi(av[2][k], av[3][k]));
        }
    }
    __syncthreads();

    // ---- GRU ----
    int lane = tid & 31, wid = tid >> 5;
    int g = lane >> 2, q = lane & 3, m0 = wid*2;

    float zreg[2][2][4];

    {   // gate conv (2-term)
        float acc[2][4][4];
        mma_convh<32,4>(sbase, pBg, s_bg, acc);
        __syncthreads();
        #pragma unroll
        for (int mm = 0; mm < 2; mm++) {
            int y = m0 + mm;
            #pragma unroll
            for (int nt = 0; nt < 4; nt++) {
                int co = nt*8 + q*2;
                if (nt < 2) {
                    #pragma unroll
                    for (int rr = 0; rr < 4; rr++)
                        zreg[mm][nt][rr] = sigf(acc[mm][nt][rr]);
                } else {
                    // channels co, co+1 (>=16): r gates -> rh in place
                    #pragma unroll
                    for (int half = 0; half < 2; half++) {
                        int x = g + half*8;
                        int ti = ((y + 1)*18 + (x + 1))*TPITCH_U + co/2;
                        float2 h = hirec(sTu[ti]);
                        float r0 = sigf(acc[mm][nt][half*2]);
                        float r1 = sigf(acc[mm][nt][half*2 + 1]);
                        sTu[ti] = pkhi(r0*h.x, r1*h.y);
                    }
                }
            }
        }
    }
    __syncthreads();

    float cs[2][2];     // per-thread channel sums of Xn (nt, parity) for mean
    cs[0][0] = cs[0][1] = cs[1][0] = cs[1][1] = 0.f;

    {   // candidate conv (2-term) + update (+ tile refill for tail)
        float acc[2][2][4];
        mma_convh<32,2>(sbase, pBc, s_bc, acc);
        __syncthreads();   // all warps' tile reads done before tile overwrite
        #pragma unroll
        for (int mm = 0; mm < 2; mm++) {
            int y = m0 + mm;
            #pragma unroll
            for (int nt = 0; nt < 2; nt++) {
                int co = nt*8 + q*2;
                #pragma unroll
                for (int half = 0; half < 2; half++) {
                    int x = g + half*8;
                    int idx = ((b*CC + co)*128 + p16 + y)*128 + q16 + x;
                    float h0 = X[idx];
                    float h1 = X[idx + PLANE];
                    float cand0 = tanhf(acc[mm][nt][half*2]);
                    float cand1 = tanhf(acc[mm][nt][half*2 + 1]);
                    float z0 = zreg[mm][nt][half*2], z1 = zreg[mm][nt][half*2 + 1];
                    float v0 = (1.f - z0)*h0 + z0*cand0;
                    float v1 = (1.f - z1)*h1 + z1*cand1;
                    Xn[idx]         = v0;
                    Xn[idx + PLANE] = v1;
                    cs[nt][0] += v0;
                    cs[nt][1] += v1;
                    if (doTail) {
                        int pix = (y + 1)*18 + (x + 1);
                        sTu[pix*TPITCH_U + co/2] = pkhi(v0, v1);
                    }
                }
            }
        }
    }

    if (!doTail) return;

    // warp-reduce Xn channel sums over g-lanes (lane bits 2..4), exact fp32
    #pragma unroll
    for (int o = 4; o <= 16; o <<= 1) {
        #pragma unroll
        for (int nt = 0; nt < 2; nt++) {
            cs[nt][0] += __shfl_xor_sync(0xffffffffu, cs[nt][0], o);
            cs[nt][1] += __shfl_xor_sync(0xffffffffu, cs[nt][1], o);
        }
    }
    if (lane < 4) {
        #pragma unroll
        for (int nt = 0; nt < 2; nt++) {
            u.tail.s_red[nt*8 + q*2][wid]     = cs[nt][0];
            u.tail.s_red[nt*8 + q*2 + 1][wid] = cs[nt][1];
        }
    }
    __syncthreads();

    {   // M conv for next iteration (2-term)
        float acc[2][2][4];
        mma_convh<16,2>(sbase, pBM, s_bm, acc);
        #pragma unroll
        for (int mm = 0; mm < 2; mm++) {
            int y = m0 + mm;
            #pragma unroll
            for (int nt = 0; nt < 2; nt++) {
                int co = nt*8 + q*2;
                int r0 = ((b*CC + co)*128 + p16 + y)*128 + q16;
                int r1 = r0 + PLANE;
                Mout[r0 + g]     = acc[mm][nt][0];
                Mout[r1 + g]     = acc[mm][nt][1];
                Mout[r0 + g + 8] = acc[mm][nt][2];
                Mout[r1 + g + 8] = acc[mm][nt][3];
            }
        }
    }
    __syncthreads();
    if (tid < 16) {
        float s = 0.f;
        #pragma unroll
        for (int w = 0; w < 8; w++) s += u.tail.s_red[tid][w];
        u.tail.s_xm[tid] = s * (1.f/256.f);
    }
    __syncthreads();
    if (tid < 64) {
        int d = tid & 31;
        const float* wM = (tid < 32) ? wq : wk;
        const float* bM = (tid < 32) ? bq : bk;
        float a = bM[d];
        #pragma unroll
        for (int c = 0; c < CC; c++) a += u.tail.s_xm[c]*wM[c*DQK + d];
        u.tail.s_qk[tid] = a;
    }
    __syncthreads();
    if (tid < 128) {
        int t2 = tid & 63;
        int offp = (tid < 64) ? 0 : 32;
        float a = 0.f;
        #pragma unroll
        for (int d = 0; d < 32; d++) a += u.tail.s_qk[offp + d]*W1[(offp + d)*HIDN + t2];
        ABout[(b*NN + i)*128 + (tid < 64 ? 0 : 64) + t2] = a;
    }
}

// ---------------- launch ------------------------------------------------------
extern "C" void kernel_launch(void* const* d_in, const int* in_sizes, int n_in,
                              void* d_out, int out_size)
{
    const float* seed = (const float*)d_in[0];
    const int*   eidx = (const int*)  d_in[1];
    const float* wq = (const float*)d_in[2];
    const float* bq = (const float*)d_in[3];
    const float* wk = (const float*)d_in[4];
    const float* bk = (const float*)d_in[5];
    const float* wm = (const float*)d_in[6];
    const float* bm = (const float*)d_in[7];
    const float* w1 = (const float*)d_in[8];
    const float* b1 = (const float*)d_in[9];
    const float* w2 = (const float*)d_in[10];
    const float* b2 = (const float*)d_in[11];
    const float* wo = (const float*)d_in[12];
    const float* bo = (const float*)d_in[13];
    const float* gw = (const float*)d_in[14];
    const float* gb = (const float*)d_in[15];
    const float* wg = (const float*)d_in[16];
    const float* bg = (const float*)d_in[17];
    const float* wc = (const float*)d_in[18];
    const float* bc = (const float*)d_in[19];
    float* out = (float*)d_out;

    int B = in_sizes[0] / (CC*128*128);
    int E = in_sizes[1] / 2;

    void *pXa,*pXb,*pM0,*pM1,*pAB0,*pAB1,*pT9,*poff,*plj,*pBM,*pBg,*pBc;
    cudaGetSymbolAddress(&pXa, g_Xa);   cudaGetSymbolAddress(&pXb, g_Xb);
    cudaGetSymbolAddress(&pM0, g_M0);   cudaGetSymbolAddress(&pM1, g_M1);
    cudaGetSymbolAddress(&pAB0,g_AB0);  cudaGetSymbolAddress(&pAB1,g_AB1);
    cudaGetSymbolAddress(&pT9, g_T9);   cudaGetSymbolAddress(&poff,g_off);
    cudaGetSymbolAddress(&plj, g_lj);
    cudaGetSymbolAddress(&pBM, g_pBM);  cudaGetSymbolAddress(&pBg, g_pBg);
    cudaGetSymbolAddress(&pBc, g_pBc);

    cudaFuncSetAttribute(k_iter, cudaFuncAttributeMaxDynamicSharedMemorySize,
                         TILE_BYTES);
    cudaFuncSetAttribute(k_convQ, cudaFuncAttributeMaxDynamicSharedMemorySize,
                         TILE_BYTES);

    // launch order fixed so ncu (-s 5 -c 1) captures a full k_iter (6th launch)
    k_csrT9 <<<1, 256>>>(eidx, E, (int*)poff, (int*)plj, gw, (float*)pT9);
    k_prepAll<<<16, 256>>>(wm, wg, wc, (uint4*)pBM, (uint4*)pBg, (uint4*)pBc);
    k_convQ<<<B*NN, 256, TILE_BYTES>>>(seed, (const uint4*)pBM, bm,
                           wq, bq, wk, bk, w1, (float*)pM0, (float*)pAB0);

    const float* Xc = seed;
    for (int it = 0; it < 4; it++) {
        float* Xn = (it == 3) ? out : ((it & 1) ? (float*)pXb : (float*)pXa);
        float* Mi  = (it & 1) ? (float*)pM1  : (float*)pM0;
        float* Mo  = (it & 1) ? (float*)pM0  : (float*)pM1;
        float* ABi = (it & 1) ? (float*)pAB1 : (float*)pAB0;
        float* ABo = (it & 1) ? (float*)pAB0 : (float*)pAB1;

        k_iter<<<B*NN, 256, TILE_BYTES>>>(Mi, Xc, ABi,
                        (const float*)pT9, gb, b1, w2, b2, wo, bo,
                        (const uint4*)pBg, bg,
                        (const uint4*)pBc, bc,
                        (const uint4*)pBM, bm,
                        wq, bq, wk, bk, w1,
                        (const int*)poff, (const int*)plj,
                        Xn, Mo, ABo, (it < 3) ? 1 : 0);
        Xc = Xn;
    }
}